// round 2
// baseline (speedup 1.0000x reference)
#include <cuda_runtime.h>
#include <math.h>

#define NN 100000
#define F0 128
#define F1 64
#define F2 128
#define F3 256
#define MAXF 256
#define MAXE 1600000

// ---------------- scratch (static device globals; no allocation) ----------------
__device__ float g_deg[NN];
__device__ float g_dinv[NN];
__device__ float g_dinv2[NN];
__device__ float g_norm[MAXE];
__device__ int   g_src[MAXE];
__device__ int   g_dst[MAXE];
__device__ int   g_is32;                    // 1 if edge_index buffer is int32
__device__ float g_h[(size_t)NN * MAXF];    // GEMM output per layer
__device__ float g_acc[(size_t)NN * MAXF];  // aggregation accumulator
__device__ float g_x[(size_t)NN * MAXF];    // layer input/output features
__device__ float g_gmax[F3];                // global max pool result

// ---------------- edge index dtype detect + normalize to int32 ----------------
__global__ void k_flag_init(int* flag) { *flag = 0; }

// If the buffer really holds int64 indices (< 2^31), every int64 read is in
// [0, n). If it holds int32 data, an int64 read combines two adjacent ids:
// val = lo + (hi << 32), out of range whenever hi != 0 (prob 1 - 1e-5 per elem).
__global__ void k_detect(const long long* __restrict__ ei64, int e, int n, int* flag) {
    int i = blockIdx.x * blockDim.x + threadIdx.x;
    if (i < e) {
        long long v = ei64[i];
        if (v < 0 || v >= (long long)n) atomicOr(flag, 1);
    }
}

__global__ void k_convert(const void* __restrict__ ei, int e,
                          const int* __restrict__ flag,
                          int* __restrict__ src, int* __restrict__ dst) {
    int i = blockIdx.x * blockDim.x + threadIdx.x;
    if (i >= e) return;
    if (*flag) {  // int32 layout: [src(e), dst(e)] as int32
        const int* p = (const int*)ei;
        src[i] = p[i];
        dst[i] = p[e + i];
    } else {      // int64 layout
        const long long* p = (const long long*)ei;
        src[i] = (int)p[i];
        dst[i] = (int)p[e + i];
    }
}

// ---------------- degree / norm precompute ----------------
__global__ void k_init_deg(float* deg, int n) {
    int i = blockIdx.x * blockDim.x + threadIdx.x;
    if (i < n) deg[i] = 1.0f;  // self-loop weight
}

__global__ void k_deg_acc(const int* __restrict__ dst,
                          const float* __restrict__ ew,
                          float* deg, int e) {
    int i = blockIdx.x * blockDim.x + threadIdx.x;
    if (i < e) atomicAdd(&deg[dst[i]], ew[i]);
}

__global__ void k_dinv(const float* __restrict__ deg, float* dinv, float* dinv2, int n) {
    int i = blockIdx.x * blockDim.x + threadIdx.x;
    if (i < n) {
        float d = deg[i];
        dinv[i] = rsqrtf(d);
        dinv2[i] = 1.0f / d;
    }
}

__global__ void k_norm(const int* __restrict__ src,
                       const int* __restrict__ dst,
                       const float* __restrict__ ew,
                       const float* __restrict__ dinv,
                       float* norm, int e) {
    int i = blockIdx.x * blockDim.x + threadIdx.x;
    if (i < e) norm[i] = dinv[src[i]] * ew[i] * dinv[dst[i]];
}

// ---------------- SGEMM: H = A @ B, fused self-loop init ACC = H * dinv2[row] ----------------
// A: [M,K] row-major, B: [K,N] row-major. BM=BN=64, BK=16, 256 threads, 4x4 per thread.
// Requires K % 16 == 0, N % 64 == 0 (true for all three layers).
__global__ __launch_bounds__(256) void k_sgemm_fused(
    const float* __restrict__ A, const float* __restrict__ B,
    float* __restrict__ H, float* __restrict__ ACC,
    const float* __restrict__ dinv2, int M, int K, int N) {
    __shared__ float As[16][64];
    __shared__ float Bs[16][64];

    int bm = blockIdx.y * 64;
    int bn = blockIdx.x * 64;
    int tid = threadIdx.x;
    int tm = (tid >> 4) << 2;   // 0..60 step 4
    int tn = (tid & 15) << 2;

    int ar = tid >> 2;          // 0..63
    int ac = (tid & 3) << 2;    // 0,4,8,12
    int br = tid >> 4;          // 0..15
    int bc = (tid & 15) << 2;   // 0..60

    float acc[4][4];
#pragma unroll
    for (int i = 0; i < 4; i++)
#pragma unroll
        for (int j = 0; j < 4; j++) acc[i][j] = 0.0f;

    for (int k0 = 0; k0 < K; k0 += 16) {
        float4 av = make_float4(0.f, 0.f, 0.f, 0.f);
        if (bm + ar < M)
            av = *(const float4*)(A + (size_t)(bm + ar) * K + k0 + ac);
        As[ac + 0][ar] = av.x;
        As[ac + 1][ar] = av.y;
        As[ac + 2][ar] = av.z;
        As[ac + 3][ar] = av.w;

        *(float4*)&Bs[br][bc] = *(const float4*)(B + (size_t)(k0 + br) * N + bn + bc);
        __syncthreads();

#pragma unroll
        for (int k = 0; k < 16; k++) {
            float4 a4 = *(const float4*)&As[k][tm];
            float4 b4 = *(const float4*)&Bs[k][tn];
            float a[4] = {a4.x, a4.y, a4.z, a4.w};
            float b[4] = {b4.x, b4.y, b4.z, b4.w};
#pragma unroll
            for (int i = 0; i < 4; i++)
#pragma unroll
                for (int j = 0; j < 4; j++) acc[i][j] += a[i] * b[j];
        }
        __syncthreads();
    }

#pragma unroll
    for (int i = 0; i < 4; i++) {
        int row = bm + tm + i;
        if (row < M) {
            float d2 = dinv2[row];
            float4 v = make_float4(acc[i][0], acc[i][1], acc[i][2], acc[i][3]);
            *(float4*)(H + (size_t)row * N + bn + tn) = v;
            float4 w = make_float4(v.x * d2, v.y * d2, v.z * d2, v.w * d2);
            *(float4*)(ACC + (size_t)row * N + bn + tn) = w;
        }
    }
}

// ---------------- edge scatter: acc[dst] += h[src] * norm, one warp per edge ----------------
__global__ __launch_bounds__(256) void k_scatter(
    const int* __restrict__ src, const int* __restrict__ dst,
    const float* __restrict__ norm, const float* __restrict__ h,
    float* __restrict__ acc, int e, int f) {
    int warp = (int)((blockIdx.x * blockDim.x + threadIdx.x) >> 5);
    int lane = threadIdx.x & 31;
    if (warp >= e) return;
    int s = src[warp];
    int d = dst[warp];
    float nm = norm[warp];
    const float4* hs = (const float4*)(h + (size_t)s * f);
    float4* ad = (float4*)(acc + (size_t)d * f);
    int nchunk = f >> 2;
    for (int c = lane; c < nchunk; c += 32) {
        float4 v = hs[c];
        v.x *= nm; v.y *= nm; v.z *= nm; v.w *= nm;
        asm volatile("red.global.add.v4.f32 [%0], {%1, %2, %3, %4};"
                     :: "l"(ad + c), "f"(v.x), "f"(v.y), "f"(v.z), "f"(v.w)
                     : "memory");
    }
}

// ---------------- bias + relu ----------------
__global__ void k_bias_relu(const float* __restrict__ acc, const float* __restrict__ b,
                            float* __restrict__ out, int total, int f) {
    int i = blockIdx.x * blockDim.x + threadIdx.x;
    if (i < total) {
        int j = i % f;
        out[i] = fmaxf(acc[i] + b[j], 0.0f);
    }
}

// ---------------- global max pool over rows (values >= 0 after relu) ----------------
__global__ void k_zero_gmax(float* gmax) { gmax[threadIdx.x] = 0.0f; }

__global__ void k_colmax(const float* __restrict__ h, int n, float* gmax) {
    int col = threadIdx.x;  // 256 threads = 256 columns
    int rpb = (n + gridDim.x - 1) / gridDim.x;
    int r0 = blockIdx.x * rpb;
    int r1 = min(n, r0 + rpb);
    float m = 0.0f;
    for (int r = r0; r < r1; r++) m = fmaxf(m, h[(size_t)r * F3 + col]);
    atomicMax((int*)&gmax[col], __float_as_int(m));
}

// ---------------- MLP head + log_softmax ----------------
__global__ void k_head(const float* __restrict__ gmax,
                       const float* __restrict__ Wl1, const float* __restrict__ bl1,
                       const float* __restrict__ Wl2, const float* __restrict__ bl2,
                       float* __restrict__ out) {
    __shared__ float g[256];
    __shared__ float h1[128];
    __shared__ float logits[10];
    int t = threadIdx.x;
    g[t] = gmax[t];
    __syncthreads();
    if (t < 128) {
        float s = bl1[t];
        for (int k = 0; k < 256; k++) s += g[k] * Wl1[k * 128 + t];
        h1[t] = fmaxf(s, 0.0f);
    }
    __syncthreads();
    if (t < 10) {
        float s = bl2[t];
        for (int k = 0; k < 128; k++) s += h1[k] * Wl2[k * 10 + t];
        logits[t] = s;
    }
    __syncthreads();
    if (t == 0) {
        float m = -1e30f;
        for (int c = 0; c < 10; c++) m = fmaxf(m, logits[c]);
        float se = 0.0f;
        for (int c = 0; c < 10; c++) se += expf(logits[c] - m);
        float lse = logf(se);
        for (int c = 0; c < 10; c++) out[c] = logits[c] - m - lse;
    }
}

// ---------------- launch ----------------
extern "C" void kernel_launch(void* const* d_in, const int* in_sizes, int n_in,
                              void* d_out, int out_size) {
    const float* x   = (const float*)d_in[0];
    const void*  ei  = d_in[1];
    const float* ew  = (const float*)d_in[2];
    const float* W1  = (const float*)d_in[3];
    const float* b1  = (const float*)d_in[4];
    const float* W2  = (const float*)d_in[5];
    const float* b2  = (const float*)d_in[6];
    const float* W3  = (const float*)d_in[7];
    const float* b3  = (const float*)d_in[8];
    const float* Wl1 = (const float*)d_in[9];
    const float* bl1 = (const float*)d_in[10];
    const float* Wl2 = (const float*)d_in[11];
    const float* bl2 = (const float*)d_in[12];
    float* out = (float*)d_out;

    int E = in_sizes[2];             // 1,600,000 (edge_attr element count)
    int N = in_sizes[0] / F0;        // 100,000

    float *deg, *dinv, *dinv2, *norm, *h, *accb, *xb, *gmax;
    int *src, *dst, *flag;
    cudaGetSymbolAddress((void**)&deg,   g_deg);
    cudaGetSymbolAddress((void**)&dinv,  g_dinv);
    cudaGetSymbolAddress((void**)&dinv2, g_dinv2);
    cudaGetSymbolAddress((void**)&norm,  g_norm);
    cudaGetSymbolAddress((void**)&src,   g_src);
    cudaGetSymbolAddress((void**)&dst,   g_dst);
    cudaGetSymbolAddress((void**)&flag,  g_is32);
    cudaGetSymbolAddress((void**)&h,     g_h);
    cudaGetSymbolAddress((void**)&accb,  g_acc);
    cudaGetSymbolAddress((void**)&xb,    g_x);
    cudaGetSymbolAddress((void**)&gmax,  g_gmax);

    // ---- normalize edge index dtype to int32 (device-side, capturable) ----
    k_flag_init<<<1, 1>>>(flag);
    k_detect<<<(E + 255) / 256, 256>>>((const long long*)ei, E, N, flag);
    k_convert<<<(E + 255) / 256, 256>>>(ei, E, flag, src, dst);

    // ---- degree / normalization ----
    k_init_deg<<<(N + 255) / 256, 256>>>(deg, N);
    k_deg_acc<<<(E + 255) / 256, 256>>>(dst, ew, deg, E);
    k_dinv<<<(N + 255) / 256, 256>>>(deg, dinv, dinv2, N);
    k_norm<<<(E + 255) / 256, 256>>>(src, dst, ew, dinv, norm, E);

    auto layer = [&](const float* X, const float* W, const float* bias, int K, int Fo) {
        dim3 grid(Fo / 64, (N + 63) / 64);
        k_sgemm_fused<<<grid, 256>>>(X, W, h, accb, dinv2, N, K, Fo);
        k_scatter<<<(E + 7) / 8, 256>>>(src, dst, norm, h, accb, E, Fo);
        int total = N * Fo;
        k_bias_relu<<<(total + 255) / 256, 256>>>(accb, bias, xb, total, Fo);
    };

    layer(x,  W1, b1, F0, F1);   // 128 -> 64
    layer(xb, W2, b2, F1, F2);   // 64  -> 128
    layer(xb, W3, b3, F2, F3);   // 128 -> 256

    k_zero_gmax<<<1, F3>>>(gmax);
    k_colmax<<<400, F3>>>(xb, N, gmax);
    k_head<<<1, 256>>>(gmax, Wl1, bl1, Wl2, bl2, out);
}

// round 3
// speedup vs baseline: 2.3764x; 2.3764x over previous
#include <cuda_runtime.h>
#include <math.h>

#define NN 100000
#define F0 128
#define F1 64
#define F2 128
#define F3 256
#define MAXF 256
#define MAXE 1600000
#define SCAN_BLK 1024   // elements per scan block
#define NBLK ((NN + SCAN_BLK - 1) / SCAN_BLK)   // 98

// ---------------- scratch (static device globals; no allocation) ----------------
__device__ float g_deg[NN];
__device__ float g_dinv[NN];
__device__ float g_dinv2[NN];
__device__ int   g_cnt[NN];
__device__ int   g_part[NN];
__device__ int   g_bsum[NBLK];
__device__ int   g_rowptr[NN + 1];
__device__ int   g_cursor[NN];
__device__ int   g_src[MAXE];
__device__ int   g_dst[MAXE];
__device__ int   g_esrc[MAXE];    // dst-sorted src ids
__device__ float g_enorm[MAXE];   // dst-sorted edge norms
__device__ int   g_is32;
__device__ float g_h[(size_t)NN * MAXF];    // GEMM output per layer
__device__ float g_x[(size_t)NN * MAXF];    // layer output features
__device__ float g_gmax[F3];

// ---------------- edge index dtype detect + normalize to int32 ----------------
__global__ void k_flag_init(int* flag) { *flag = 0; }

__global__ void k_detect(const long long* __restrict__ ei64, int e, int n, int* flag) {
    int i = blockIdx.x * blockDim.x + threadIdx.x;
    if (i < e) {
        long long v = ei64[i];
        if (v < 0 || v >= (long long)n) atomicOr(flag, 1);
    }
}

__global__ void k_convert(const void* __restrict__ ei, int e,
                          const int* __restrict__ flag,
                          int* __restrict__ src, int* __restrict__ dst) {
    int i = blockIdx.x * blockDim.x + threadIdx.x;
    if (i >= e) return;
    if (*flag) {
        const int* p = (const int*)ei;
        src[i] = p[i];
        dst[i] = p[e + i];
    } else {
        const long long* p = (const long long*)ei;
        src[i] = (int)p[i];
        dst[i] = (int)p[e + i];
    }
}

// ---------------- histogram (count + weighted degree, fused) ----------------
__global__ void k_zero_nd(float* deg, int* cnt, int n) {
    int i = blockIdx.x * blockDim.x + threadIdx.x;
    if (i < n) { deg[i] = 1.0f; cnt[i] = 0; }   // deg starts at self-loop weight
}

__global__ void k_hist(const int* __restrict__ dst, const float* __restrict__ ew,
                       float* deg, int* cnt, int e) {
    int i = blockIdx.x * blockDim.x + threadIdx.x;
    if (i < e) {
        int d = dst[i];
        atomicAdd(&cnt[d], 1);
        atomicAdd(&deg[d], ew[i]);
    }
}

__global__ void k_dinv(const float* __restrict__ deg, float* dinv, float* dinv2, int n) {
    int i = blockIdx.x * blockDim.x + threadIdx.x;
    if (i < n) {
        float d = deg[i];
        dinv[i] = rsqrtf(d);
        dinv2[i] = 1.0f / d;
    }
}

// ---------------- exclusive scan of counts (3-stage) ----------------
__global__ __launch_bounds__(256) void k_scan1(const int* __restrict__ in,
                                               int* __restrict__ out,
                                               int* __restrict__ bsum, int n) {
    __shared__ int ts[256];
    int t = threadIdx.x;
    int base = blockIdx.x * SCAN_BLK + t * 4;
    int v0 = 0, v1 = 0, v2 = 0, v3 = 0;
    if (base + 0 < n) v0 = in[base + 0];
    if (base + 1 < n) v1 = in[base + 1];
    if (base + 2 < n) v2 = in[base + 2];
    if (base + 3 < n) v3 = in[base + 3];
    int tsum = v0 + v1 + v2 + v3;
    ts[t] = tsum;
    __syncthreads();
    for (int off = 1; off < 256; off <<= 1) {
        int x = (t >= off) ? ts[t - off] : 0;
        __syncthreads();
        ts[t] += x;
        __syncthreads();
    }
    int excl = ts[t] - tsum;
    if (t == 255) bsum[blockIdx.x] = ts[255];
    if (base + 0 < n) out[base + 0] = excl;
    if (base + 1 < n) out[base + 1] = excl + v0;
    if (base + 2 < n) out[base + 2] = excl + v0 + v1;
    if (base + 3 < n) out[base + 3] = excl + v0 + v1 + v2;
}

__global__ __launch_bounds__(128) void k_scan2(int* bsum, int nb) {
    __shared__ int s[128];
    int t = threadIdx.x;
    int v = (t < nb) ? bsum[t] : 0;
    s[t] = v;
    __syncthreads();
    for (int off = 1; off < 128; off <<= 1) {
        int x = (t >= off) ? s[t - off] : 0;
        __syncthreads();
        s[t] += x;
        __syncthreads();
    }
    if (t < nb) bsum[t] = s[t] - v;  // exclusive
}

__global__ void k_scan3(int* __restrict__ rowptr, int* __restrict__ cursor,
                        const int* __restrict__ part, const int* __restrict__ bsum,
                        int n, int e) {
    int i = blockIdx.x * blockDim.x + threadIdx.x;
    if (i < n) {
        int r = part[i] + bsum[i / SCAN_BLK];
        rowptr[i] = r;
        cursor[i] = r;
    }
    if (i == 0) rowptr[n] = e;
}

// ---------------- sort edges by dst, fusing norm computation ----------------
__global__ void k_sort(const int* __restrict__ src, const int* __restrict__ dst,
                       const float* __restrict__ ew, const float* __restrict__ dinv,
                       int* __restrict__ cursor,
                       int* __restrict__ esrc, float* __restrict__ enorm, int e) {
    int i = blockIdx.x * blockDim.x + threadIdx.x;
    if (i >= e) return;
    int s = src[i];
    int d = dst[i];
    int pos = atomicAdd(&cursor[d], 1);
    esrc[pos] = s;
    enorm[pos] = dinv[s] * ew[i] * dinv[d];
}

// ---------------- SGEMM: H = A @ B ----------------
// A: [M,K] row-major, B: [K,N] row-major. BM=BN=64, BK=16, 256 threads, 4x4/thread.
__global__ __launch_bounds__(256) void k_sgemm(
    const float* __restrict__ A, const float* __restrict__ B,
    float* __restrict__ H, int M, int K, int N) {
    __shared__ float As[16][64];
    __shared__ float Bs[16][64];

    int bm = blockIdx.y * 64;
    int bn = blockIdx.x * 64;
    int tid = threadIdx.x;
    int tm = (tid >> 4) << 2;
    int tn = (tid & 15) << 2;

    int ar = tid >> 2;
    int ac = (tid & 3) << 2;
    int br = tid >> 4;
    int bc = (tid & 15) << 2;

    float acc[4][4];
#pragma unroll
    for (int i = 0; i < 4; i++)
#pragma unroll
        for (int j = 0; j < 4; j++) acc[i][j] = 0.0f;

    for (int k0 = 0; k0 < K; k0 += 16) {
        float4 av = make_float4(0.f, 0.f, 0.f, 0.f);
        if (bm + ar < M)
            av = *(const float4*)(A + (size_t)(bm + ar) * K + k0 + ac);
        As[ac + 0][ar] = av.x;
        As[ac + 1][ar] = av.y;
        As[ac + 2][ar] = av.z;
        As[ac + 3][ar] = av.w;

        *(float4*)&Bs[br][bc] = *(const float4*)(B + (size_t)(k0 + br) * N + bn + bc);
        __syncthreads();

#pragma unroll
        for (int k = 0; k < 16; k++) {
            float4 a4 = *(const float4*)&As[k][tm];
            float4 b4 = *(const float4*)&Bs[k][tn];
            float a[4] = {a4.x, a4.y, a4.z, a4.w};
            float b[4] = {b4.x, b4.y, b4.z, b4.w};
#pragma unroll
            for (int i = 0; i < 4; i++)
#pragma unroll
                for (int j = 0; j < 4; j++) acc[i][j] += a[i] * b[j];
        }
        __syncthreads();
    }

#pragma unroll
    for (int i = 0; i < 4; i++) {
        int row = bm + tm + i;
        if (row < M)
            *(float4*)(H + (size_t)row * N + bn + tn) =
                make_float4(acc[i][0], acc[i][1], acc[i][2], acc[i][3]);
    }
}

// ---------------- CSR aggregation: out = relu(sum_in h[src]*norm + h[v]*dinv2 + b) ----------------
// One warp per destination node; F/32 columns per lane; edge loop unrolled x2.
template <int F>
__global__ __launch_bounds__(256) void k_aggregate(
    const int* __restrict__ rowptr, const int* __restrict__ esrc,
    const float* __restrict__ enorm, const float* __restrict__ H,
    const float* __restrict__ dinv2, const float* __restrict__ bias,
    float* __restrict__ out, int n) {
    int warp = (int)((blockIdx.x * blockDim.x + threadIdx.x) >> 5);
    int lane = threadIdx.x & 31;
    if (warp >= n) return;

    constexpr int C = F / 32;
    float acc[C];
    const float* hv = H + (size_t)warp * F;
    float d2 = dinv2[warp];
#pragma unroll
    for (int c = 0; c < C; c++) acc[c] = hv[lane + 32 * c] * d2;

    int r0 = rowptr[warp], r1 = rowptr[warp + 1];
    int e = r0;
    for (; e + 1 < r1; e += 2) {
        int s0 = esrc[e], s1 = esrc[e + 1];
        float n0 = enorm[e], n1 = enorm[e + 1];
        const float* h0 = H + (size_t)s0 * F;
        const float* h1 = H + (size_t)s1 * F;
#pragma unroll
        for (int c = 0; c < C; c++) {
            float a = h0[lane + 32 * c];
            float b = h1[lane + 32 * c];
            acc[c] += a * n0 + b * n1;
        }
    }
    if (e < r1) {
        int s0 = esrc[e];
        float n0 = enorm[e];
        const float* h0 = H + (size_t)s0 * F;
#pragma unroll
        for (int c = 0; c < C; c++) acc[c] += h0[lane + 32 * c] * n0;
    }

    float* ov = out + (size_t)warp * F;
#pragma unroll
    for (int c = 0; c < C; c++)
        ov[lane + 32 * c] = fmaxf(acc[c] + bias[lane + 32 * c], 0.0f);
}

// ---------------- global max pool ----------------
__global__ void k_zero_gmax(float* gmax) { gmax[threadIdx.x] = 0.0f; }

__global__ void k_colmax(const float* __restrict__ h, int n, float* gmax) {
    int col = threadIdx.x;
    int rpb = (n + gridDim.x - 1) / gridDim.x;
    int r0 = blockIdx.x * rpb;
    int r1 = min(n, r0 + rpb);
    float m = 0.0f;
    for (int r = r0; r < r1; r++) m = fmaxf(m, h[(size_t)r * F3 + col]);
    atomicMax((int*)&gmax[col], __float_as_int(m));
}

// ---------------- MLP head + log_softmax ----------------
__global__ void k_head(const float* __restrict__ gmax,
                       const float* __restrict__ Wl1, const float* __restrict__ bl1,
                       const float* __restrict__ Wl2, const float* __restrict__ bl2,
                       float* __restrict__ out) {
    __shared__ float g[256];
    __shared__ float h1[128];
    __shared__ float logits[10];
    int t = threadIdx.x;
    g[t] = gmax[t];
    __syncthreads();
    if (t < 128) {
        float s = bl1[t];
        for (int k = 0; k < 256; k++) s += g[k] * Wl1[k * 128 + t];
        h1[t] = fmaxf(s, 0.0f);
    }
    __syncthreads();
    if (t < 10) {
        float s = bl2[t];
        for (int k = 0; k < 128; k++) s += h1[k] * Wl2[k * 10 + t];
        logits[t] = s;
    }
    __syncthreads();
    if (t == 0) {
        float m = -1e30f;
        for (int c = 0; c < 10; c++) m = fmaxf(m, logits[c]);
        float se = 0.0f;
        for (int c = 0; c < 10; c++) se += expf(logits[c] - m);
        float lse = logf(se);
        for (int c = 0; c < 10; c++) out[c] = logits[c] - m - lse;
    }
}

// ---------------- launch ----------------
extern "C" void kernel_launch(void* const* d_in, const int* in_sizes, int n_in,
                              void* d_out, int out_size) {
    const float* x   = (const float*)d_in[0];
    const void*  ei  = d_in[1];
    const float* ew  = (const float*)d_in[2];
    const float* W1  = (const float*)d_in[3];
    const float* b1  = (const float*)d_in[4];
    const float* W2  = (const float*)d_in[5];
    const float* b2  = (const float*)d_in[6];
    const float* W3  = (const float*)d_in[7];
    const float* b3  = (const float*)d_in[8];
    const float* Wl1 = (const float*)d_in[9];
    const float* bl1 = (const float*)d_in[10];
    const float* Wl2 = (const float*)d_in[11];
    const float* bl2 = (const float*)d_in[12];
    float* out = (float*)d_out;

    int E = in_sizes[2];
    int N = in_sizes[0] / F0;

    float *deg, *dinv, *dinv2, *enorm, *h, *xb, *gmax;
    int *cnt, *part, *bsum, *rowptr, *cursor, *src, *dst, *esrc, *flag;
    cudaGetSymbolAddress((void**)&deg,    g_deg);
    cudaGetSymbolAddress((void**)&dinv,   g_dinv);
    cudaGetSymbolAddress((void**)&dinv2,  g_dinv2);
    cudaGetSymbolAddress((void**)&cnt,    g_cnt);
    cudaGetSymbolAddress((void**)&part,   g_part);
    cudaGetSymbolAddress((void**)&bsum,   g_bsum);
    cudaGetSymbolAddress((void**)&rowptr, g_rowptr);
    cudaGetSymbolAddress((void**)&cursor, g_cursor);
    cudaGetSymbolAddress((void**)&src,    g_src);
    cudaGetSymbolAddress((void**)&dst,    g_dst);
    cudaGetSymbolAddress((void**)&esrc,   g_esrc);
    cudaGetSymbolAddress((void**)&enorm,  g_enorm);
    cudaGetSymbolAddress((void**)&flag,   g_is32);
    cudaGetSymbolAddress((void**)&h,      g_h);
    cudaGetSymbolAddress((void**)&xb,     g_x);
    cudaGetSymbolAddress((void**)&gmax,   g_gmax);

    // ---- edge index dtype normalize ----
    k_flag_init<<<1, 1>>>(flag);
    k_detect<<<(E + 255) / 256, 256>>>((const long long*)ei, E, N, flag);
    k_convert<<<(E + 255) / 256, 256>>>(ei, E, flag, src, dst);

    // ---- degree + histogram ----
    k_zero_nd<<<(N + 255) / 256, 256>>>(deg, cnt, N);
    k_hist<<<(E + 255) / 256, 256>>>(dst, ew, deg, cnt, E);
    k_dinv<<<(N + 255) / 256, 256>>>(deg, dinv, dinv2, N);

    // ---- CSR build: scan + sort ----
    int nb = (N + SCAN_BLK - 1) / SCAN_BLK;
    k_scan1<<<nb, 256>>>(cnt, part, bsum, N);
    k_scan2<<<1, 128>>>(bsum, nb);
    k_scan3<<<(N + 255) / 256, 256>>>(rowptr, cursor, part, bsum, N, E);
    k_sort<<<(E + 255) / 256, 256>>>(src, dst, ew, dinv, cursor, esrc, enorm, E);

    // ---- layers ----
    int aggGrid = (N + 7) / 8;   // 8 warps per 256-thread block

    {   // layer 1: 128 -> 64
        dim3 grid(F1 / 64, (N + 63) / 64);
        k_sgemm<<<grid, 256>>>(x, W1, h, N, F0, F1);
        k_aggregate<F1><<<aggGrid, 256>>>(rowptr, esrc, enorm, h, dinv2, b1, xb, N);
    }
    {   // layer 2: 64 -> 128
        dim3 grid(F2 / 64, (N + 63) / 64);
        k_sgemm<<<grid, 256>>>(xb, W2, h, N, F1, F2);
        k_aggregate<F2><<<aggGrid, 256>>>(rowptr, esrc, enorm, h, dinv2, b2, xb, N);
    }
    {   // layer 3: 128 -> 256
        dim3 grid(F3 / 64, (N + 63) / 64);
        k_sgemm<<<grid, 256>>>(xb, W3, h, N, F2, F3);
        k_aggregate<F3><<<aggGrid, 256>>>(rowptr, esrc, enorm, h, dinv2, b3, xb, N);
    }

    // ---- pool + head ----
    k_zero_gmax<<<1, F3>>>(gmax);
    k_colmax<<<400, F3>>>(xb, N, gmax);
    k_head<<<1, 256>>>(gmax, Wl1, bl1, Wl2, bl2, out);
}

// round 5
// speedup vs baseline: 3.2549x; 1.3697x over previous
#include <cuda_runtime.h>
#include <math.h>

#define NN 100000
#define F0 128
#define F1 64
#define F2 128
#define F3 256
#define MAXF 256
#define MAXE 1600000
#define SCAN_BLK 1024
#define NBLK ((NN + SCAN_BLK - 1) / SCAN_BLK)

// ---------------- scratch (static device globals; no allocation) ----------------
__device__ float g_deg[NN];
__device__ float g_dinv[NN];
__device__ float g_dinv2[NN];
__device__ int   g_cnt[NN];
__device__ int   g_part[NN];
__device__ int   g_bsum[NBLK];
__device__ int   g_rowptr[NN + 1];
__device__ int   g_cursor[NN];
__device__ int   g_src[MAXE];
__device__ int   g_dst[MAXE];
__device__ int   g_esrc[MAXE];
__device__ float g_enorm[MAXE];
__device__ int   g_is32;
__device__ float g_h[(size_t)NN * MAXF];
__device__ float g_x[(size_t)NN * MAXF];
__device__ float g_gmax[F3];

// ---------------- edge index dtype detect (sampled) + fused convert/hist ----------------
__global__ void k_flag_init(int* flag) { *flag = 0; }

__global__ void k_detect(const long long* __restrict__ ei64, int e, int n, int* flag) {
    int i = blockIdx.x * blockDim.x + threadIdx.x;
    if (i < e) {
        long long v = ei64[i];
        if (v < 0 || v >= (long long)n) atomicOr(flag, 1);
    }
}

__global__ void k_zero_nd(float* deg, int* cnt, int n) {
    int i = blockIdx.x * blockDim.x + threadIdx.x;
    if (i < n) { deg[i] = 1.0f; cnt[i] = 0; }
}

__global__ void k_convert_hist(const void* __restrict__ ei, int e,
                               const int* __restrict__ flag,
                               const float* __restrict__ ew,
                               int* __restrict__ src, int* __restrict__ dst,
                               int* __restrict__ cnt, float* __restrict__ deg) {
    int i = blockIdx.x * blockDim.x + threadIdx.x;
    if (i >= e) return;
    int s, d;
    if (*flag) {
        const int* p = (const int*)ei;
        s = p[i]; d = p[e + i];
    } else {
        const long long* p = (const long long*)ei;
        s = (int)p[i]; d = (int)p[e + i];
    }
    src[i] = s; dst[i] = d;
    atomicAdd(&cnt[d], 1);
    atomicAdd(&deg[d], ew[i]);
}

__global__ void k_dinv(const float* __restrict__ deg, float* dinv, float* dinv2, int n) {
    int i = blockIdx.x * blockDim.x + threadIdx.x;
    if (i < n) {
        float d = deg[i];
        dinv[i] = rsqrtf(d);
        dinv2[i] = 1.0f / d;
    }
}

// ---------------- exclusive scan of counts (3-stage) ----------------
__global__ __launch_bounds__(256) void k_scan1(const int* __restrict__ in,
                                               int* __restrict__ out,
                                               int* __restrict__ bsum, int n) {
    __shared__ int ts[256];
    int t = threadIdx.x;
    int base = blockIdx.x * SCAN_BLK + t * 4;
    int v0 = 0, v1 = 0, v2 = 0, v3 = 0;
    if (base + 0 < n) v0 = in[base + 0];
    if (base + 1 < n) v1 = in[base + 1];
    if (base + 2 < n) v2 = in[base + 2];
    if (base + 3 < n) v3 = in[base + 3];
    int tsum = v0 + v1 + v2 + v3;
    ts[t] = tsum;
    __syncthreads();
    for (int off = 1; off < 256; off <<= 1) {
        int x = (t >= off) ? ts[t - off] : 0;
        __syncthreads();
        ts[t] += x;
        __syncthreads();
    }
    int excl = ts[t] - tsum;
    if (t == 255) bsum[blockIdx.x] = ts[255];
    if (base + 0 < n) out[base + 0] = excl;
    if (base + 1 < n) out[base + 1] = excl + v0;
    if (base + 2 < n) out[base + 2] = excl + v0 + v1;
    if (base + 3 < n) out[base + 3] = excl + v0 + v1 + v2;
}

__global__ __launch_bounds__(128) void k_scan2(int* bsum, int nb) {
    __shared__ int s[128];
    int t = threadIdx.x;
    int v = (t < nb) ? bsum[t] : 0;
    s[t] = v;
    __syncthreads();
    for (int off = 1; off < 128; off <<= 1) {
        int x = (t >= off) ? s[t - off] : 0;
        __syncthreads();
        s[t] += x;
        __syncthreads();
    }
    if (t < nb) bsum[t] = s[t] - v;
}

__global__ void k_scan3(int* __restrict__ rowptr, int* __restrict__ cursor,
                        const int* __restrict__ part, const int* __restrict__ bsum,
                        int n, int e) {
    int i = blockIdx.x * blockDim.x + threadIdx.x;
    if (i < n) {
        int r = part[i] + bsum[i / SCAN_BLK];
        rowptr[i] = r;
        cursor[i] = r;
    }
    if (i == 0) rowptr[n] = e;
}

__global__ void k_sort(const int* __restrict__ src, const int* __restrict__ dst,
                       const float* __restrict__ ew, const float* __restrict__ dinv,
                       int* __restrict__ cursor,
                       int* __restrict__ esrc, float* __restrict__ enorm, int e) {
    int i = blockIdx.x * blockDim.x + threadIdx.x;
    if (i >= e) return;
    int s = src[i];
    int d = dst[i];
    int pos = atomicAdd(&cursor[d], 1);
    esrc[pos] = s;
    enorm[pos] = dinv[s] * ew[i] * dinv[d];
}

// ---------------- SGEMM 64x64x16 (used for layer 1 only: N=64) ----------------
__global__ __launch_bounds__(256) void k_sgemm(
    const float* __restrict__ A, const float* __restrict__ B,
    float* __restrict__ H, int M, int K, int N) {
    __shared__ float As[16][64];
    __shared__ float Bs[16][64];

    int bm = blockIdx.y * 64;
    int bn = blockIdx.x * 64;
    int tid = threadIdx.x;
    int tm = (tid >> 4) << 2;
    int tn = (tid & 15) << 2;
    int ar = tid >> 2;
    int ac = (tid & 3) << 2;
    int br = tid >> 4;
    int bc = (tid & 15) << 2;

    float acc[4][4];
#pragma unroll
    for (int i = 0; i < 4; i++)
#pragma unroll
        for (int j = 0; j < 4; j++) acc[i][j] = 0.0f;

    for (int k0 = 0; k0 < K; k0 += 16) {
        float4 av = make_float4(0.f, 0.f, 0.f, 0.f);
        if (bm + ar < M)
            av = *(const float4*)(A + (size_t)(bm + ar) * K + k0 + ac);
        As[ac + 0][ar] = av.x;
        As[ac + 1][ar] = av.y;
        As[ac + 2][ar] = av.z;
        As[ac + 3][ar] = av.w;
        *(float4*)&Bs[br][bc] = *(const float4*)(B + (size_t)(k0 + br) * N + bn + bc);
        __syncthreads();
#pragma unroll
        for (int k = 0; k < 16; k++) {
            float4 a4 = *(const float4*)&As[k][tm];
            float4 b4 = *(const float4*)&Bs[k][tn];
            float a[4] = {a4.x, a4.y, a4.z, a4.w};
            float b[4] = {b4.x, b4.y, b4.z, b4.w};
#pragma unroll
            for (int i = 0; i < 4; i++)
#pragma unroll
                for (int j = 0; j < 4; j++) acc[i][j] += a[i] * b[j];
        }
        __syncthreads();
    }
#pragma unroll
    for (int i = 0; i < 4; i++) {
        int row = bm + tm + i;
        if (row < M)
            *(float4*)(H + (size_t)row * N + bn + tn) =
                make_float4(acc[i][0], acc[i][1], acc[i][2], acc[i][3]);
    }
}

// ---------------- SGEMM 128x128x16, double-buffered, 8x8/thread ----------------
// EPI: 0 = plain store, 1 = relu(acc+bias) store, 2 = relu(acc+bias) -> gmax (no store)
template <int EPI>
__global__ __launch_bounds__(256) void k_sgemm128(
    const float* __restrict__ A, const float* __restrict__ B,
    const float* __restrict__ bias, float* __restrict__ Out,
    float* __restrict__ gmax, int M, int K, int N) {
    __shared__ float As[2][16][128];
    __shared__ float Bs[2][16][128];

    int tid = threadIdx.x;
    int bm = blockIdx.y * 128;
    int bn = blockIdx.x * 128;

    int ar = tid & 127;            // A row within tile
    int ak = (tid >> 7) << 3;      // 0 or 8
    int brw = tid >> 4;            // B k-row 0..15
    int bc = (tid & 15) << 3;      // B col 0..120 step 8

    int tm0 = (tid >> 4) << 2;     // 0..60
    int tn0 = (tid & 15) << 2;     // 0..60

    const float* Arow = A + (size_t)(bm + ar) * K;
    bool arow_ok = (bm + ar) < M;

    float acc[8][8];
#pragma unroll
    for (int i = 0; i < 8; i++)
#pragma unroll
        for (int j = 0; j < 8; j++) acc[i][j] = 0.0f;

    int T = K / 16;
    float4 a0, a1, b0, b1;

    // prefetch tile 0
    a0 = a1 = make_float4(0.f, 0.f, 0.f, 0.f);
    if (arow_ok) {
        a0 = *(const float4*)(Arow + ak);
        a1 = *(const float4*)(Arow + ak + 4);
    }
    b0 = *(const float4*)(B + (size_t)brw * N + bn + bc);
    b1 = *(const float4*)(B + (size_t)brw * N + bn + bc + 4);

    // store tile 0
    As[0][ak + 0][ar] = a0.x; As[0][ak + 1][ar] = a0.y;
    As[0][ak + 2][ar] = a0.z; As[0][ak + 3][ar] = a0.w;
    As[0][ak + 4][ar] = a1.x; As[0][ak + 5][ar] = a1.y;
    As[0][ak + 6][ar] = a1.z; As[0][ak + 7][ar] = a1.w;
    *(float4*)&Bs[0][brw][bc] = b0;
    *(float4*)&Bs[0][brw][bc + 4] = b1;
    __syncthreads();

    for (int t = 0; t < T; t++) {
        int buf = t & 1;
        if (t + 1 < T) {
            int k0 = (t + 1) * 16;
            a0 = a1 = make_float4(0.f, 0.f, 0.f, 0.f);
            if (arow_ok) {
                a0 = *(const float4*)(Arow + k0 + ak);
                a1 = *(const float4*)(Arow + k0 + ak + 4);
            }
            b0 = *(const float4*)(B + (size_t)(k0 + brw) * N + bn + bc);
            b1 = *(const float4*)(B + (size_t)(k0 + brw) * N + bn + bc + 4);
        }
#pragma unroll
        for (int k = 0; k < 16; k++) {
            float4 af0 = *(const float4*)&As[buf][k][tm0];
            float4 af1 = *(const float4*)&As[buf][k][tm0 + 64];
            float4 bf0 = *(const float4*)&Bs[buf][k][tn0];
            float4 bf1 = *(const float4*)&Bs[buf][k][tn0 + 64];
            float a[8] = {af0.x, af0.y, af0.z, af0.w, af1.x, af1.y, af1.z, af1.w};
            float b[8] = {bf0.x, bf0.y, bf0.z, bf0.w, bf1.x, bf1.y, bf1.z, bf1.w};
#pragma unroll
            for (int i = 0; i < 8; i++)
#pragma unroll
                for (int j = 0; j < 8; j++) acc[i][j] += a[i] * b[j];
        }
        if (t + 1 < T) {
            int nbuf = buf ^ 1;
            As[nbuf][ak + 0][ar] = a0.x; As[nbuf][ak + 1][ar] = a0.y;
            As[nbuf][ak + 2][ar] = a0.z; As[nbuf][ak + 3][ar] = a0.w;
            As[nbuf][ak + 4][ar] = a1.x; As[nbuf][ak + 5][ar] = a1.y;
            As[nbuf][ak + 6][ar] = a1.z; As[nbuf][ak + 7][ar] = a1.w;
            *(float4*)&Bs[nbuf][brw][bc] = b0;
            *(float4*)&Bs[nbuf][brw][bc + 4] = b1;
            __syncthreads();
        }
    }

    // bias (loaded once per thread: 8 columns)
    float bv[8];
    if (EPI >= 1) {
#pragma unroll
        for (int j = 0; j < 4; j++) {
            bv[j]     = bias[bn + tn0 + j];
            bv[j + 4] = bias[bn + tn0 + 64 + j];
        }
    }

    if (EPI == 2) {
        // relu(acc+bias), reduce max over this thread's 8 rows, then block-reduce
        float cmax[8];
#pragma unroll
        for (int j = 0; j < 8; j++) cmax[j] = 0.0f;
#pragma unroll
        for (int i = 0; i < 8; i++) {
            int row = bm + tm0 + (i < 4 ? i : 60 + i);
            if (row < M) {
#pragma unroll
                for (int j = 0; j < 8; j++) {
                    float v = fmaxf(acc[i][j] + bv[j], 0.0f);
                    cmax[j] = fmaxf(cmax[j], v);
                }
            }
        }
        __shared__ float red[16][128];
        __syncthreads();
#pragma unroll
        for (int j = 0; j < 4; j++) {
            red[tid >> 4][tn0 + j]      = cmax[j];
            red[tid >> 4][tn0 + 64 + j] = cmax[j + 4];
        }
        __syncthreads();
        if (tid < 128) {
            float m = 0.0f;
#pragma unroll
            for (int r = 0; r < 16; r++) m = fmaxf(m, red[r][tid]);
            atomicMax((int*)&gmax[bn + tid], __float_as_int(m));
        }
    } else {
#pragma unroll
        for (int i = 0; i < 8; i++) {
            int row = bm + tm0 + (i < 4 ? i : 60 + i);
            if (row < M) {
                float4 v0, v1;
                if (EPI == 1) {
                    v0 = make_float4(fmaxf(acc[i][0] + bv[0], 0.f), fmaxf(acc[i][1] + bv[1], 0.f),
                                     fmaxf(acc[i][2] + bv[2], 0.f), fmaxf(acc[i][3] + bv[3], 0.f));
                    v1 = make_float4(fmaxf(acc[i][4] + bv[4], 0.f), fmaxf(acc[i][5] + bv[5], 0.f),
                                     fmaxf(acc[i][6] + bv[6], 0.f), fmaxf(acc[i][7] + bv[7], 0.f));
                } else {
                    v0 = make_float4(acc[i][0], acc[i][1], acc[i][2], acc[i][3]);
                    v1 = make_float4(acc[i][4], acc[i][5], acc[i][6], acc[i][7]);
                }
                *(float4*)(Out + (size_t)row * N + bn + tn0) = v0;
                *(float4*)(Out + (size_t)row * N + bn + tn0 + 64) = v1;
            }
        }
    }
}

// ---------------- CSR aggregation ----------------
// REL=true:  out = relu(sum h[src]*norm + h[v]*dinv2 + bias)
// REL=false: out =      sum h[src]*norm + h[v]*dinv2
template <int F, bool REL>
__global__ __launch_bounds__(256) void k_aggregate(
    const int* __restrict__ rowptr, const int* __restrict__ esrc,
    const float* __restrict__ enorm, const float* __restrict__ H,
    const float* __restrict__ dinv2, const float* __restrict__ bias,
    float* __restrict__ out, int n) {
    int warp = (int)((blockIdx.x * blockDim.x + threadIdx.x) >> 5);
    int lane = threadIdx.x & 31;
    if (warp >= n) return;

    constexpr int C = F / 32;
    float acc[C];
    const float* hv = H + (size_t)warp * F;
    float d2 = dinv2[warp];
#pragma unroll
    for (int c = 0; c < C; c++) acc[c] = hv[lane + 32 * c] * d2;

    int r0 = rowptr[warp], r1 = rowptr[warp + 1];
    int e = r0;
    for (; e + 1 < r1; e += 2) {
        int s0 = esrc[e], s1 = esrc[e + 1];
        float n0 = enorm[e], n1 = enorm[e + 1];
        const float* h0 = H + (size_t)s0 * F;
        const float* h1 = H + (size_t)s1 * F;
#pragma unroll
        for (int c = 0; c < C; c++) {
            float a = h0[lane + 32 * c];
            float b = h1[lane + 32 * c];
            acc[c] += a * n0 + b * n1;
        }
    }
    if (e < r1) {
        int s0 = esrc[e];
        float n0 = enorm[e];
        const float* h0 = H + (size_t)s0 * F;
#pragma unroll
        for (int c = 0; c < C; c++) acc[c] += h0[lane + 32 * c] * n0;
    }

    float* ov = out + (size_t)warp * F;
#pragma unroll
    for (int c = 0; c < C; c++) {
        float v = acc[c];
        if (REL) v = fmaxf(v + bias[lane + 32 * c], 0.0f);
        ov[lane + 32 * c] = v;
    }
}

// ---------------- pool init + MLP head ----------------
__global__ void k_zero_gmax(float* gmax) { gmax[threadIdx.x] = 0.0f; }

__global__ void k_head(const float* __restrict__ gmax,
                       const float* __restrict__ Wl1, const float* __restrict__ bl1,
                       const float* __restrict__ Wl2, const float* __restrict__ bl2,
                       float* __restrict__ out) {
    __shared__ float g[256];
    __shared__ float h1[128];
    __shared__ float logits[10];
    int t = threadIdx.x;
    g[t] = gmax[t];
    __syncthreads();
    if (t < 128) {
        float s = bl1[t];
        for (int k = 0; k < 256; k++) s += g[k] * Wl1[k * 128 + t];
        h1[t] = fmaxf(s, 0.0f);
    }
    __syncthreads();
    if (t < 10) {
        float s = bl2[t];
        for (int k = 0; k < 128; k++) s += h1[k] * Wl2[k * 10 + t];
        logits[t] = s;
    }
    __syncthreads();
    if (t == 0) {
        float m = -1e30f;
        for (int c = 0; c < 10; c++) m = fmaxf(m, logits[c]);
        float se = 0.0f;
        for (int c = 0; c < 10; c++) se += expf(logits[c] - m);
        float lse = logf(se);
        for (int c = 0; c < 10; c++) out[c] = logits[c] - m - lse;
    }
}

// ---------------- launch ----------------
extern "C" void kernel_launch(void* const* d_in, const int* in_sizes, int n_in,
                              void* d_out, int out_size) {
    const float* x   = (const float*)d_in[0];
    const void*  ei  = d_in[1];
    const float* ew  = (const float*)d_in[2];
    const float* W1  = (const float*)d_in[3];
    const float* b1  = (const float*)d_in[4];
    const float* W2  = (const float*)d_in[5];
    const float* b2  = (const float*)d_in[6];
    const float* W3  = (const float*)d_in[7];
    const float* b3  = (const float*)d_in[8];
    const float* Wl1 = (const float*)d_in[9];
    const float* bl1 = (const float*)d_in[10];
    const float* Wl2 = (const float*)d_in[11];
    const float* bl2 = (const float*)d_in[12];
    float* out = (float*)d_out;

    int E = in_sizes[2];
    int N = in_sizes[0] / F0;

    float *deg, *dinv, *dinv2, *enorm, *h, *xb, *gmax;
    int *cnt, *part, *bsum, *rowptr, *cursor, *src, *dst, *esrc, *flag;
    cudaGetSymbolAddress((void**)&deg,    g_deg);
    cudaGetSymbolAddress((void**)&dinv,   g_dinv);
    cudaGetSymbolAddress((void**)&dinv2,  g_dinv2);
    cudaGetSymbolAddress((void**)&cnt,    g_cnt);
    cudaGetSymbolAddress((void**)&part,   g_part);
    cudaGetSymbolAddress((void**)&bsum,   g_bsum);
    cudaGetSymbolAddress((void**)&rowptr, g_rowptr);
    cudaGetSymbolAddress((void**)&cursor, g_cursor);
    cudaGetSymbolAddress((void**)&src,    g_src);
    cudaGetSymbolAddress((void**)&dst,    g_dst);
    cudaGetSymbolAddress((void**)&esrc,   g_esrc);
    cudaGetSymbolAddress((void**)&enorm,  g_enorm);
    cudaGetSymbolAddress((void**)&flag,   g_is32);
    cudaGetSymbolAddress((void**)&h,      g_h);
    cudaGetSymbolAddress((void**)&xb,     g_x);
    cudaGetSymbolAddress((void**)&gmax,   g_gmax);

    // ---- dtype detect (sampled) + fused convert/histogram ----
    k_flag_init<<<1, 1>>>(flag);
    int det = E < 65536 ? E : 65536;
    k_detect<<<(det + 255) / 256, 256>>>((const long long*)ei, det, N, flag);
    k_zero_nd<<<(N + 255) / 256, 256>>>(deg, cnt, N);
    k_convert_hist<<<(E + 255) / 256, 256>>>(ei, E, flag, ew, src, dst, cnt, deg);
    k_dinv<<<(N + 255) / 256, 256>>>(deg, dinv, dinv2, N);

    // ---- CSR build ----
    int nb = (N + SCAN_BLK - 1) / SCAN_BLK;
    k_scan1<<<nb, 256>>>(cnt, part, bsum, N);
    k_scan2<<<1, 128>>>(bsum, nb);
    k_scan3<<<(N + 255) / 256, 256>>>(rowptr, cursor, part, bsum, N, E);
    k_sort<<<(E + 255) / 256, 256>>>(src, dst, ew, dinv, cursor, esrc, enorm, E);

    int aggGrid = (N + 7) / 8;

    // ---- layer 1: H = X W1 (128->64); X1 = relu(A_hat H + b1) ----
    {
        dim3 grid(F1 / 64, (N + 63) / 64);
        k_sgemm<<<grid, 256>>>(x, W1, h, N, F0, F1);
        k_aggregate<F1, true><<<aggGrid, 256>>>(rowptr, esrc, enorm, h, dinv2, b1, xb, N);
    }
    // ---- layer 2: Y = A_hat X1 (64-wide); X2 = relu(Y W2 + b2) ----
    {
        k_aggregate<F1, false><<<aggGrid, 256>>>(rowptr, esrc, enorm, xb, dinv2, nullptr, h, N);
        dim3 grid(F2 / 128, (N + 127) / 128);
        k_sgemm128<1><<<grid, 256>>>(h, W2, b2, xb, nullptr, N, F1, F2);
    }
    // ---- layer 3: Y = A_hat X2 (128-wide); gmax = colmax(relu(Y W3 + b3)) ----
    {
        k_aggregate<F2, false><<<aggGrid, 256>>>(rowptr, esrc, enorm, xb, dinv2, nullptr, h, N);
        k_zero_gmax<<<1, F3>>>(gmax);
        dim3 grid(F3 / 128, (N + 127) / 128);
        k_sgemm128<2><<<grid, 256>>>(h, W3, b3, nullptr, gmax, N, F2, F3);
    }

    k_head<<<1, 256>>>(gmax, Wl1, bl1, Wl2, bl2, out);
}

// round 8
// speedup vs baseline: 4.7167x; 1.4491x over previous
#include <cuda_runtime.h>
#include <stdint.h>
#include <math.h>

#define NN 100000
#define F0 128
#define F1 64
#define F2 128
#define F3 256
#define MAXF 256
#define MAXE 1600000
#define SCAN_BLK 1024
#define NBLK ((NN + SCAN_BLK - 1) / SCAN_BLK)

// ---------------- scratch (static device globals; no allocation) ----------------
__device__ float g_deg[NN];
__device__ float g_dinv[NN];
__device__ float g_dinv2[NN];
__device__ int   g_cnt[NN];
__device__ int   g_part[NN];
__device__ int   g_bsum[NBLK];
__device__ int   g_rowptr[NN + 1];
__device__ int   g_cursor[NN];
__device__ int   g_esrc[MAXE];
__device__ float g_enorm[MAXE];
__device__ int   g_is32;
__device__ float g_h[(size_t)NN * MAXF];
__device__ float g_x[(size_t)NN * MAXF];
__device__ float g_gmax[F3];

// ---------------- dtype detect + degree/histogram ----------------
__global__ void k_zero_nd(float* deg, int* cnt, int n, int* flag) {
    int i = blockIdx.x * blockDim.x + threadIdx.x;
    if (i < n) { deg[i] = 1.0f; cnt[i] = 0; }
    if (i == 0) *flag = 0;
}

__global__ void k_detect(const long long* __restrict__ ei64, int e, int n, int* flag) {
    int i = blockIdx.x * blockDim.x + threadIdx.x;
    if (i < e) {
        long long v = ei64[i];
        if (v < 0 || v >= (long long)n) atomicOr(flag, 1);
    }
}

__global__ void k_hist(const void* __restrict__ ei, int e,
                       const int* __restrict__ flag, const float* __restrict__ ew,
                       int* __restrict__ cnt, float* __restrict__ deg) {
    int i = blockIdx.x * blockDim.x + threadIdx.x;
    if (i >= e) return;
    int d;
    if (*flag) d = ((const int*)ei)[e + i];
    else       d = (int)((const long long*)ei)[e + i];
    atomicAdd(&cnt[d], 1);
    atomicAdd(&deg[d], ew[i]);
}

__global__ void k_dinv(const float* __restrict__ deg, float* dinv, float* dinv2, int n) {
    int i = blockIdx.x * blockDim.x + threadIdx.x;
    if (i < n) {
        float d = deg[i];
        dinv[i] = rsqrtf(d);
        dinv2[i] = 1.0f / d;
    }
}

// ---------------- exclusive scan of counts (3-stage) ----------------
__global__ __launch_bounds__(256) void k_scan1(const int* __restrict__ in,
                                               int* __restrict__ out,
                                               int* __restrict__ bsum, int n) {
    __shared__ int ts[256];
    int t = threadIdx.x;
    int base = blockIdx.x * SCAN_BLK + t * 4;
    int v0 = 0, v1 = 0, v2 = 0, v3 = 0;
    if (base + 0 < n) v0 = in[base + 0];
    if (base + 1 < n) v1 = in[base + 1];
    if (base + 2 < n) v2 = in[base + 2];
    if (base + 3 < n) v3 = in[base + 3];
    int tsum = v0 + v1 + v2 + v3;
    ts[t] = tsum;
    __syncthreads();
    for (int off = 1; off < 256; off <<= 1) {
        int x = (t >= off) ? ts[t - off] : 0;
        __syncthreads();
        ts[t] += x;
        __syncthreads();
    }
    int excl = ts[t] - tsum;
    if (t == 255) bsum[blockIdx.x] = ts[255];
    if (base + 0 < n) out[base + 0] = excl;
    if (base + 1 < n) out[base + 1] = excl + v0;
    if (base + 2 < n) out[base + 2] = excl + v0 + v1;
    if (base + 3 < n) out[base + 3] = excl + v0 + v1 + v2;
}

__global__ __launch_bounds__(128) void k_scan2(int* bsum, int nb) {
    __shared__ int s[128];
    int t = threadIdx.x;
    int v = (t < nb) ? bsum[t] : 0;
    s[t] = v;
    __syncthreads();
    for (int off = 1; off < 128; off <<= 1) {
        int x = (t >= off) ? s[t - off] : 0;
        __syncthreads();
        s[t] += x;
        __syncthreads();
    }
    if (t < nb) bsum[t] = s[t] - v;
}

__global__ void k_scan3(int* __restrict__ rowptr, int* __restrict__ cursor,
                        const int* __restrict__ part, const int* __restrict__ bsum,
                        int n, int e) {
    int i = blockIdx.x * blockDim.x + threadIdx.x;
    if (i < n) {
        int r = part[i] + bsum[i / SCAN_BLK];
        rowptr[i] = r;
        cursor[i] = r;
    }
    if (i == 0) rowptr[n] = e;
}

__global__ void k_sort(const void* __restrict__ ei, int e,
                       const int* __restrict__ flag,
                       const float* __restrict__ ew, const float* __restrict__ dinv,
                       int* __restrict__ cursor,
                       int* __restrict__ esrc, float* __restrict__ enorm) {
    int i = blockIdx.x * blockDim.x + threadIdx.x;
    if (i >= e) return;
    int s, d;
    if (*flag) {
        const int* p = (const int*)ei;
        s = p[i]; d = p[e + i];
    } else {
        const long long* p = (const long long*)ei;
        s = (int)p[i]; d = (int)p[e + i];
    }
    int pos = atomicAdd(&cursor[d], 1);
    esrc[pos] = s;
    enorm[pos] = dinv[s] * ew[i] * dinv[d];
}

// ---------------- tf32 tensor-core GEMM: 128x64 tile, BK=16, 8 warps ----------------
// EPI: 0 = plain store, 1 = relu(acc+bias) store, 2 = relu(acc+bias) -> gmax (no store)
__device__ __forceinline__ uint32_t f2tf(float f) {
    uint32_t u;
    asm("cvt.rna.tf32.f32 %0, %1;" : "=r"(u) : "f"(f));
    return u;
}

template <int EPI>
__global__ __launch_bounds__(256) void k_tfgemm(
    const float* __restrict__ A, const float* __restrict__ B,
    const float* __restrict__ bias, float* __restrict__ Out,
    float* __restrict__ gmax, int M, int K, int N) {
    __shared__ uint32_t As[2][128][20];   // stride 20: conflict-free frag loads
    __shared__ uint32_t Bs[2][16][72];    // stride 72: conflict-free frag loads

    int tid = threadIdx.x;
    int lane = tid & 31, wid = tid >> 5;
    int warpM = wid & 3, warpN = wid >> 2;
    int bm = blockIdx.y * 128, bn = blockIdx.x * 64;

    // global load mapping
    int lr = tid >> 1;            // A row 0..127
    int lc = (tid & 1) << 3;      // A col 0 or 8
    int brr = tid >> 4;           // B k-row 0..15
    int bcc = (tid & 15) << 2;    // B col 0..60

    const float* Ap = A + (size_t)(bm + lr) * K + lc;
    bool aok = (bm + lr) < M;
    const float* Bp = B + (size_t)brr * N + bn + bcc;

    float d[2][4][4];
#pragma unroll
    for (int mt = 0; mt < 2; mt++)
#pragma unroll
        for (int nt = 0; nt < 4; nt++)
#pragma unroll
            for (int j = 0; j < 4; j++) d[mt][nt][j] = 0.0f;

    int T = K >> 4;
    float4 ax0 = make_float4(0.f, 0.f, 0.f, 0.f), ax1 = ax0, bx;

    // tile 0 load
    if (aok) { ax0 = *(const float4*)Ap; ax1 = *(const float4*)(Ap + 4); }
    bx = *(const float4*)Bp;
    As[0][lr][lc + 0] = f2tf(ax0.x); As[0][lr][lc + 1] = f2tf(ax0.y);
    As[0][lr][lc + 2] = f2tf(ax0.z); As[0][lr][lc + 3] = f2tf(ax0.w);
    As[0][lr][lc + 4] = f2tf(ax1.x); As[0][lr][lc + 5] = f2tf(ax1.y);
    As[0][lr][lc + 6] = f2tf(ax1.z); As[0][lr][lc + 7] = f2tf(ax1.w);
    Bs[0][brr][bcc + 0] = f2tf(bx.x); Bs[0][brr][bcc + 1] = f2tf(bx.y);
    Bs[0][brr][bcc + 2] = f2tf(bx.z); Bs[0][brr][bcc + 3] = f2tf(bx.w);
    __syncthreads();

    for (int t = 0; t < T; t++) {
        int buf = t & 1;
        if (t + 1 < T) {
            const float* Ap2 = Ap + (t + 1) * 16;
            ax0 = ax1 = make_float4(0.f, 0.f, 0.f, 0.f);
            if (aok) { ax0 = *(const float4*)Ap2; ax1 = *(const float4*)(Ap2 + 4); }
            bx = *(const float4*)(Bp + (size_t)(t + 1) * 16 * N);
        }
#pragma unroll
        for (int kk = 0; kk < 2; kk++) {
            int k0 = kk * 8 + (lane & 3);
            uint32_t a[2][4], b[4][2];
#pragma unroll
            for (int mt = 0; mt < 2; mt++) {
                int r = warpM * 32 + mt * 16 + (lane >> 2);
                a[mt][0] = As[buf][r][k0];
                a[mt][1] = As[buf][r + 8][k0];
                a[mt][2] = As[buf][r][k0 + 4];
                a[mt][3] = As[buf][r + 8][k0 + 4];
            }
#pragma unroll
            for (int nt = 0; nt < 4; nt++) {
                int c = warpN * 32 + nt * 8 + (lane >> 2);
                b[nt][0] = Bs[buf][k0][c];
                b[nt][1] = Bs[buf][k0 + 4][c];
            }
#pragma unroll
            for (int mt = 0; mt < 2; mt++)
#pragma unroll
                for (int nt = 0; nt < 4; nt++) {
                    asm volatile(
                        "mma.sync.aligned.m16n8k8.row.col.f32.tf32.tf32.f32 "
                        "{%0,%1,%2,%3}, {%4,%5,%6,%7}, {%8,%9}, {%0,%1,%2,%3};"
                        : "+f"(d[mt][nt][0]), "+f"(d[mt][nt][1]),
                          "+f"(d[mt][nt][2]), "+f"(d[mt][nt][3])
                        : "r"(a[mt][0]), "r"(a[mt][1]), "r"(a[mt][2]), "r"(a[mt][3]),
                          "r"(b[nt][0]), "r"(b[nt][1]));
                }
        }
        if (t + 1 < T) {
            int nb = buf ^ 1;
            As[nb][lr][lc + 0] = f2tf(ax0.x); As[nb][lr][lc + 1] = f2tf(ax0.y);
            As[nb][lr][lc + 2] = f2tf(ax0.z); As[nb][lr][lc + 3] = f2tf(ax0.w);
            As[nb][lr][lc + 4] = f2tf(ax1.x); As[nb][lr][lc + 5] = f2tf(ax1.y);
            As[nb][lr][lc + 6] = f2tf(ax1.z); As[nb][lr][lc + 7] = f2tf(ax1.w);
            Bs[nb][brr][bcc + 0] = f2tf(bx.x); Bs[nb][brr][bcc + 1] = f2tf(bx.y);
            Bs[nb][brr][bcc + 2] = f2tf(bx.z); Bs[nb][brr][bcc + 3] = f2tf(bx.w);
        }
        __syncthreads();
    }

    if (EPI == 2) {
        __shared__ float sgm[64];
        if (tid < 64) sgm[tid] = 0.0f;
        __syncthreads();
#pragma unroll
        for (int mt = 0; mt < 2; mt++)
#pragma unroll
            for (int nt = 0; nt < 4; nt++) {
                int c = warpN * 32 + nt * 8 + 2 * (lane & 3);
                int r = bm + warpM * 32 + mt * 16 + (lane >> 2);
                float bv0 = bias[bn + c], bv1 = bias[bn + c + 1];
                float m0 = 0.0f, m1 = 0.0f;
                if (r < M) {
                    m0 = fmaxf(d[mt][nt][0] + bv0, 0.0f);
                    m1 = fmaxf(d[mt][nt][1] + bv1, 0.0f);
                }
                if (r + 8 < M) {
                    m0 = fmaxf(m0, fmaxf(d[mt][nt][2] + bv0, 0.0f));
                    m1 = fmaxf(m1, fmaxf(d[mt][nt][3] + bv1, 0.0f));
                }
                atomicMax((int*)&sgm[c], __float_as_int(m0));
                atomicMax((int*)&sgm[c + 1], __float_as_int(m1));
            }
        __syncthreads();
        if (tid < 64) atomicMax((int*)&gmax[bn + tid], __float_as_int(sgm[tid]));
    } else {
#pragma unroll
        for (int mt = 0; mt < 2; mt++)
#pragma unroll
            for (int nt = 0; nt < 4; nt++) {
                int c = warpN * 32 + nt * 8 + 2 * (lane & 3);
                int r = bm + warpM * 32 + mt * 16 + (lane >> 2);
                float bv0 = 0.0f, bv1 = 0.0f;
                if (EPI == 1) { bv0 = bias[bn + c]; bv1 = bias[bn + c + 1]; }
                if (r < M) {
                    float v0 = d[mt][nt][0], v1 = d[mt][nt][1];
                    if (EPI == 1) { v0 = fmaxf(v0 + bv0, 0.0f); v1 = fmaxf(v1 + bv1, 0.0f); }
                    *(float2*)(Out + (size_t)r * N + bn + c) = make_float2(v0, v1);
                }
                if (r + 8 < M) {
                    float v2 = d[mt][nt][2], v3 = d[mt][nt][3];
                    if (EPI == 1) { v2 = fmaxf(v2 + bv0, 0.0f); v3 = fmaxf(v3 + bv1, 0.0f); }
                    *(float2*)(Out + (size_t)(r + 8) * N + bn + c) = make_float2(v2, v3);
                }
            }
    }
}

// ---------------- CSR aggregation, F=64 (float2/lane), edge loop unrolled x4 ----------------
template <bool REL>
__global__ __launch_bounds__(256) void k_agg64(
    const int* __restrict__ rowptr, const int* __restrict__ esrc,
    const float* __restrict__ enorm, const float* __restrict__ H,
    const float* __restrict__ dinv2, const float* __restrict__ bias,
    float* __restrict__ out, int n) {
    int warp = (int)((blockIdx.x * blockDim.x + threadIdx.x) >> 5);
    int lane = threadIdx.x & 31;
    if (warp >= n) return;

    const float2* Hv = (const float2*)H;
    float2 acc;
    {
        float2 hv = Hv[(size_t)warp * 32 + lane];
        float d2 = dinv2[warp];
        acc.x = hv.x * d2; acc.y = hv.y * d2;
    }
    int e = rowptr[warp], r1 = rowptr[warp + 1];
    for (; e + 3 < r1; e += 4) {
        int s0 = esrc[e], s1 = esrc[e + 1], s2 = esrc[e + 2], s3 = esrc[e + 3];
        float n0 = enorm[e], n1 = enorm[e + 1], n2 = enorm[e + 2], n3 = enorm[e + 3];
        float2 v0 = Hv[(size_t)s0 * 32 + lane];
        float2 v1 = Hv[(size_t)s1 * 32 + lane];
        float2 v2 = Hv[(size_t)s2 * 32 + lane];
        float2 v3 = Hv[(size_t)s3 * 32 + lane];
        acc.x += v0.x * n0 + v1.x * n1 + v2.x * n2 + v3.x * n3;
        acc.y += v0.y * n0 + v1.y * n1 + v2.y * n2 + v3.y * n3;
    }
    for (; e < r1; e++) {
        int s0 = esrc[e];
        float n0 = enorm[e];
        float2 v0 = Hv[(size_t)s0 * 32 + lane];
        acc.x += v0.x * n0;
        acc.y += v0.y * n0;
    }
    if (REL) {
        float2 bv = ((const float2*)bias)[lane];
        acc.x = fmaxf(acc.x + bv.x, 0.0f);
        acc.y = fmaxf(acc.y + bv.y, 0.0f);
    }
    ((float2*)out)[(size_t)warp * 32 + lane] = acc;
}

// ---------------- CSR aggregation, F=128 (float4/lane), edge loop unrolled x4 ----------------
__global__ __launch_bounds__(256) void k_agg128(
    const int* __restrict__ rowptr, const int* __restrict__ esrc,
    const float* __restrict__ enorm, const float* __restrict__ H,
    const float* __restrict__ dinv2, float* __restrict__ out, int n) {
    int warp = (int)((blockIdx.x * blockDim.x + threadIdx.x) >> 5);
    int lane = threadIdx.x & 31;
    if (warp >= n) return;

    const float4* Hv = (const float4*)H;
    float4 acc;
    {
        float4 hv = Hv[(size_t)warp * 32 + lane];
        float d2 = dinv2[warp];
        acc.x = hv.x * d2; acc.y = hv.y * d2; acc.z = hv.z * d2; acc.w = hv.w * d2;
    }
    int e = rowptr[warp], r1 = rowptr[warp + 1];
    for (; e + 3 < r1; e += 4) {
        int s0 = esrc[e], s1 = esrc[e + 1], s2 = esrc[e + 2], s3 = esrc[e + 3];
        float n0 = enorm[e], n1 = enorm[e + 1], n2 = enorm[e + 2], n3 = enorm[e + 3];
        float4 v0 = Hv[(size_t)s0 * 32 + lane];
        float4 v1 = Hv[(size_t)s1 * 32 + lane];
        float4 v2 = Hv[(size_t)s2 * 32 + lane];
        float4 v3 = Hv[(size_t)s3 * 32 + lane];
        acc.x += v0.x * n0 + v1.x * n1 + v2.x * n2 + v3.x * n3;
        acc.y += v0.y * n0 + v1.y * n1 + v2.y * n2 + v3.y * n3;
        acc.z += v0.z * n0 + v1.z * n1 + v2.z * n2 + v3.z * n3;
        acc.w += v0.w * n0 + v1.w * n1 + v2.w * n2 + v3.w * n3;
    }
    for (; e < r1; e++) {
        int s0 = esrc[e];
        float n0 = enorm[e];
        float4 v0 = Hv[(size_t)s0 * 32 + lane];
        acc.x += v0.x * n0; acc.y += v0.y * n0; acc.z += v0.z * n0; acc.w += v0.w * n0;
    }
    ((float4*)out)[(size_t)warp * 32 + lane] = acc;
}

// ---------------- pool init + MLP head ----------------
__global__ void k_zero_gmax(float* gmax) { gmax[threadIdx.x] = 0.0f; }

__global__ void k_head(const float* __restrict__ gmax,
                       const float* __restrict__ Wl1, const float* __restrict__ bl1,
                       const float* __restrict__ Wl2, const float* __restrict__ bl2,
                       float* __restrict__ out) {
    __shared__ float g[256];
    __shared__ float h1[128];
    __shared__ float logits[10];
    int t = threadIdx.x;
    g[t] = gmax[t];
    __syncthreads();
    if (t < 128) {
        float s = bl1[t];
        for (int k = 0; k < 256; k++) s += g[k] * Wl1[k * 128 + t];
        h1[t] = fmaxf(s, 0.0f);
    }
    __syncthreads();
    if (t < 10) {
        float s = bl2[t];
        for (int k = 0; k < 128; k++) s += h1[k] * Wl2[k * 10 + t];
        logits[t] = s;
    }
    __syncthreads();
    if (t == 0) {
        float m = -1e30f;
        for (int c = 0; c < 10; c++) m = fmaxf(m, logits[c]);
        float se = 0.0f;
        for (int c = 0; c < 10; c++) se += expf(logits[c] - m);
        float lse = logf(se);
        for (int c = 0; c < 10; c++) out[c] = logits[c] - m - lse;
    }
}

// ---------------- launch ----------------
extern "C" void kernel_launch(void* const* d_in, const int* in_sizes, int n_in,
                              void* d_out, int out_size) {
    const float* x   = (const float*)d_in[0];
    const void*  ei  = d_in[1];
    const float* ew  = (const float*)d_in[2];
    const float* W1  = (const float*)d_in[3];
    const float* b1  = (const float*)d_in[4];
    const float* W2  = (const float*)d_in[5];
    const float* b2  = (const float*)d_in[6];
    const float* W3  = (const float*)d_in[7];
    const float* b3  = (const float*)d_in[8];
    const float* Wl1 = (const float*)d_in[9];
    const float* bl1 = (const float*)d_in[10];
    const float* Wl2 = (const float*)d_in[11];
    const float* bl2 = (const float*)d_in[12];
    float* out = (float*)d_out;

    int E = in_sizes[2];
    int N = in_sizes[0] / F0;

    float *deg, *dinv, *dinv2, *enorm, *h, *xb, *gmax;
    int *cnt, *part, *bsum, *rowptr, *cursor, *esrc, *flag;
    cudaGetSymbolAddress((void**)&deg,    g_deg);
    cudaGetSymbolAddress((void**)&dinv,   g_dinv);
    cudaGetSymbolAddress((void**)&dinv2,  g_dinv2);
    cudaGetSymbolAddress((void**)&cnt,    g_cnt);
    cudaGetSymbolAddress((void**)&part,   g_part);
    cudaGetSymbolAddress((void**)&bsum,   g_bsum);
    cudaGetSymbolAddress((void**)&rowptr, g_rowptr);
    cudaGetSymbolAddress((void**)&cursor, g_cursor);
    cudaGetSymbolAddress((void**)&esrc,   g_esrc);
    cudaGetSymbolAddress((void**)&enorm,  g_enorm);
    cudaGetSymbolAddress((void**)&flag,   g_is32);
    cudaGetSymbolAddress((void**)&h,      g_h);
    cudaGetSymbolAddress((void**)&xb,     g_x);
    cudaGetSymbolAddress((void**)&gmax,   g_gmax);

    // ---- dtype detect (sampled) + degree/histogram ----
    k_zero_nd<<<(N + 255) / 256, 256>>>(deg, cnt, N, flag);
    int det = E < 65536 ? E : 65536;
    k_detect<<<(det + 255) / 256, 256>>>((const long long*)ei, det, N, flag);
    k_hist<<<(E + 255) / 256, 256>>>(ei, E, flag, ew, cnt, deg);
    k_dinv<<<(N + 255) / 256, 256>>>(deg, dinv, dinv2, N);

    // ---- CSR build ----
    int nb = (N + SCAN_BLK - 1) / SCAN_BLK;
    k_scan1<<<nb, 256>>>(cnt, part, bsum, N);
    k_scan2<<<1, 128>>>(bsum, nb);
    k_scan3<<<(N + 255) / 256, 256>>>(rowptr, cursor, part, bsum, N, E);
    k_sort<<<(E + 255) / 256, 256>>>(ei, E, flag, ew, dinv, cursor, esrc, enorm);

    int aggGrid = (N + 7) / 8;
    int gy = (N + 127) / 128;

    // ---- layer 1: h = x W1 (128->64); xb = relu(A_hat h + b1) ----
    k_tfgemm<0><<<dim3(F1 / 64, gy), 256>>>(x, W1, nullptr, h, nullptr, N, F0, F1);
    k_agg64<true><<<aggGrid, 256>>>(rowptr, esrc, enorm, h, dinv2, b1, xb, N);

    // ---- layer 2: h = A_hat xb (64-wide); xb = relu(h W2 + b2) ----
    k_agg64<false><<<aggGrid, 256>>>(rowptr, esrc, enorm, xb, dinv2, nullptr, h, N);
    k_tfgemm<1><<<dim3(F2 / 64, gy), 256>>>(h, W2, b2, xb, nullptr, N, F1, F2);

    // ---- layer 3: h = A_hat xb (128-wide); gmax = colmax(relu(h W3 + b3)) ----
    k_agg128<<<aggGrid, 256>>>(rowptr, esrc, enorm, xb, dinv2, h, N);
    k_zero_gmax<<<1, F3>>>(gmax);
    k_tfgemm<2><<<dim3(F3 / 64, gy), 256>>>(h, W3, b3, nullptr, gmax, N, F2, F3);

    k_head<<<1, 256>>>(gmax, Wl1, bl1, Wl2, bl2, out);
}

// round 9
// speedup vs baseline: 5.3067x; 1.1251x over previous
#include <cuda_runtime.h>
#include <cuda_fp16.h>
#include <stdint.h>
#include <math.h>

#define NN 100000
#define F0 128
#define F1 64
#define F2 128
#define F3 256
#define MAXF 256
#define MAXE 1600000
#define SCAN_BLK 1024
#define NBLK ((NN + SCAN_BLK - 1) / SCAN_BLK)

// ---------------- scratch (static device globals; no allocation) ----------------
__device__ float  g_deg[NN];
__device__ float  g_dinv[NN];
__device__ float  g_dinv2[NN];
__device__ int    g_cnt[NN];
__device__ int    g_part[NN];
__device__ int    g_bsum[NBLK];
__device__ int    g_rowptr[NN + 1];
__device__ int    g_cursor[NN];
__device__ int2   g_epack[MAXE];            // {src, float_bits(norm)} dst-sorted
__device__ int    g_is32;
__device__ __half g_hh[(size_t)NN * MAXF];  // half feature buffer A
__device__ __half g_xh[(size_t)NN * MAXF];  // half feature buffer B
__device__ float  g_gmax[F3];

// ---------------- init + dtype detect + degree/histogram ----------------
__global__ void k_zero_nd(float* deg, int* cnt, int n, int* flag, float* gmax) {
    int i = blockIdx.x * blockDim.x + threadIdx.x;
    if (i < n) { deg[i] = 1.0f; cnt[i] = 0; }
    if (i < F3) gmax[i] = 0.0f;
    if (i == 0) *flag = 0;
}

__global__ void k_detect(const long long* __restrict__ ei64, int e, int n, int* flag) {
    int i = blockIdx.x * blockDim.x + threadIdx.x;
    if (i < e) {
        long long v = ei64[i];
        if (v < 0 || v >= (long long)n) atomicOr(flag, 1);
    }
}

__global__ void k_hist(const void* __restrict__ ei, int e,
                       const int* __restrict__ flag, const float* __restrict__ ew,
                       int* __restrict__ cnt, float* __restrict__ deg) {
    int i = blockIdx.x * blockDim.x + threadIdx.x;
    if (i >= e) return;
    int d;
    if (*flag) d = ((const int*)ei)[e + i];
    else       d = (int)((const long long*)ei)[e + i];
    atomicAdd(&cnt[d], 1);
    atomicAdd(&deg[d], ew[i]);
}

// ---------------- exclusive scan of counts (3-stage; stage 3 fuses dinv) ----------------
__global__ __launch_bounds__(256) void k_scan1(const int* __restrict__ in,
                                               int* __restrict__ out,
                                               int* __restrict__ bsum, int n) {
    __shared__ int ts[256];
    int t = threadIdx.x;
    int base = blockIdx.x * SCAN_BLK + t * 4;
    int v0 = 0, v1 = 0, v2 = 0, v3 = 0;
    if (base + 0 < n) v0 = in[base + 0];
    if (base + 1 < n) v1 = in[base + 1];
    if (base + 2 < n) v2 = in[base + 2];
    if (base + 3 < n) v3 = in[base + 3];
    int tsum = v0 + v1 + v2 + v3;
    ts[t] = tsum;
    __syncthreads();
    for (int off = 1; off < 256; off <<= 1) {
        int x = (t >= off) ? ts[t - off] : 0;
        __syncthreads();
        ts[t] += x;
        __syncthreads();
    }
    int excl = ts[t] - tsum;
    if (t == 255) bsum[blockIdx.x] = ts[255];
    if (base + 0 < n) out[base + 0] = excl;
    if (base + 1 < n) out[base + 1] = excl + v0;
    if (base + 2 < n) out[base + 2] = excl + v0 + v1;
    if (base + 3 < n) out[base + 3] = excl + v0 + v1 + v2;
}

__global__ __launch_bounds__(128) void k_scan2(int* bsum, int nb) {
    __shared__ int s[128];
    int t = threadIdx.x;
    int v = (t < nb) ? bsum[t] : 0;
    s[t] = v;
    __syncthreads();
    for (int off = 1; off < 128; off <<= 1) {
        int x = (t >= off) ? s[t - off] : 0;
        __syncthreads();
        s[t] += x;
        __syncthreads();
    }
    if (t < nb) bsum[t] = s[t] - v;
}

__global__ void k_scan3(int* __restrict__ rowptr, int* __restrict__ cursor,
                        const int* __restrict__ part, const int* __restrict__ bsum,
                        const float* __restrict__ deg,
                        float* __restrict__ dinv, float* __restrict__ dinv2,
                        int n, int e) {
    int i = blockIdx.x * blockDim.x + threadIdx.x;
    if (i < n) {
        int r = part[i] + bsum[i / SCAN_BLK];
        rowptr[i] = r;
        cursor[i] = r;
        float d = deg[i];
        dinv[i] = rsqrtf(d);
        dinv2[i] = 1.0f / d;
    }
    if (i == 0) rowptr[n] = e;
}

__global__ void k_sort(const void* __restrict__ ei, int e,
                       const int* __restrict__ flag,
                       const float* __restrict__ ew, const float* __restrict__ dinv,
                       int* __restrict__ cursor, int2* __restrict__ epack) {
    int i = blockIdx.x * blockDim.x + threadIdx.x;
    if (i >= e) return;
    int s, d;
    if (*flag) {
        const int* p = (const int*)ei;
        s = p[i]; d = p[e + i];
    } else {
        const long long* p = (const long long*)ei;
        s = (int)p[i]; d = (int)p[e + i];
    }
    int pos = atomicAdd(&cursor[d], 1);
    epack[pos] = make_int2(s, __float_as_int(dinv[s] * ew[i] * dinv[d]));
}

// ---------------- tf32 tensor-core GEMM: 128x64 tile, BK=16, 8 warps ----------------
// A input: float (layer 1) or half (layers 2/3). Output half (EPI 0/1) or gmax (EPI 2).
__device__ __forceinline__ uint32_t f2tf(float f) {
    uint32_t u;
    asm("cvt.rna.tf32.f32 %0, %1;" : "=r"(u) : "f"(f));
    return u;
}

__device__ __forceinline__ void load_a8(const float* Ap, bool aok, uint32_t* t8) {
    float4 a0 = make_float4(0.f, 0.f, 0.f, 0.f), a1 = a0;
    if (aok) { a0 = *(const float4*)Ap; a1 = *(const float4*)(Ap + 4); }
    t8[0] = f2tf(a0.x); t8[1] = f2tf(a0.y); t8[2] = f2tf(a0.z); t8[3] = f2tf(a0.w);
    t8[4] = f2tf(a1.x); t8[5] = f2tf(a1.y); t8[6] = f2tf(a1.z); t8[7] = f2tf(a1.w);
}

__device__ __forceinline__ void load_a8(const __half* Ap, bool aok, uint32_t* t8) {
    uint4 raw = make_uint4(0u, 0u, 0u, 0u);
    if (aok) raw = *(const uint4*)Ap;
    const __half2* h = (const __half2*)&raw;
#pragma unroll
    for (int j = 0; j < 4; j++) {
        float2 f = __half22float2(h[j]);
        t8[2 * j + 0] = f2tf(f.x);
        t8[2 * j + 1] = f2tf(f.y);
    }
}

template <int EPI, typename TA>
__global__ __launch_bounds__(256) void k_tfgemm(
    const TA* __restrict__ A, const float* __restrict__ B,
    const float* __restrict__ bias, __half* __restrict__ Out,
    float* __restrict__ gmax, int M, int K, int N) {
    __shared__ uint32_t As[2][128][20];   // stride 20: conflict-free frag loads
    __shared__ uint32_t Bs[2][16][72];    // stride 72: conflict-free frag loads

    int tid = threadIdx.x;
    int lane = tid & 31, wid = tid >> 5;
    int warpM = wid & 3, warpN = wid >> 2;
    int bm = blockIdx.y * 128, bn = blockIdx.x * 64;

    int lr = tid >> 1;            // A row 0..127
    int lc = (tid & 1) << 3;      // A col 0 or 8
    int brr = tid >> 4;           // B k-row 0..15
    int bcc = (tid & 15) << 2;    // B col 0..60

    const TA* Ap = A + (size_t)(bm + lr) * K + lc;
    bool aok = (bm + lr) < M;
    const float* Bp = B + (size_t)brr * N + bn + bcc;

    float d[2][4][4];
#pragma unroll
    for (int mt = 0; mt < 2; mt++)
#pragma unroll
        for (int nt = 0; nt < 4; nt++)
#pragma unroll
            for (int j = 0; j < 4; j++) d[mt][nt][j] = 0.0f;

    int T = K >> 4;
    uint32_t a8[8];
    float4 bx;

    load_a8(Ap, aok, a8);
    bx = *(const float4*)Bp;
#pragma unroll
    for (int j = 0; j < 8; j++) As[0][lr][lc + j] = a8[j];
    Bs[0][brr][bcc + 0] = f2tf(bx.x); Bs[0][brr][bcc + 1] = f2tf(bx.y);
    Bs[0][brr][bcc + 2] = f2tf(bx.z); Bs[0][brr][bcc + 3] = f2tf(bx.w);
    __syncthreads();

    for (int t = 0; t < T; t++) {
        int buf = t & 1;
        if (t + 1 < T) {
            load_a8(Ap + (t + 1) * 16, aok, a8);
            bx = *(const float4*)(Bp + (size_t)(t + 1) * 16 * N);
        }
#pragma unroll
        for (int kk = 0; kk < 2; kk++) {
            int k0 = kk * 8 + (lane & 3);
            uint32_t a[2][4], b[4][2];
#pragma unroll
            for (int mt = 0; mt < 2; mt++) {
                int r = warpM * 32 + mt * 16 + (lane >> 2);
                a[mt][0] = As[buf][r][k0];
                a[mt][1] = As[buf][r + 8][k0];
                a[mt][2] = As[buf][r][k0 + 4];
                a[mt][3] = As[buf][r + 8][k0 + 4];
            }
#pragma unroll
            for (int nt = 0; nt < 4; nt++) {
                int c = warpN * 32 + nt * 8 + (lane >> 2);
                b[nt][0] = Bs[buf][k0][c];
                b[nt][1] = Bs[buf][k0 + 4][c];
            }
#pragma unroll
            for (int mt = 0; mt < 2; mt++)
#pragma unroll
                for (int nt = 0; nt < 4; nt++) {
                    asm volatile(
                        "mma.sync.aligned.m16n8k8.row.col.f32.tf32.tf32.f32 "
                        "{%0,%1,%2,%3}, {%4,%5,%6,%7}, {%8,%9}, {%0,%1,%2,%3};"
                        : "+f"(d[mt][nt][0]), "+f"(d[mt][nt][1]),
                          "+f"(d[mt][nt][2]), "+f"(d[mt][nt][3])
                        : "r"(a[mt][0]), "r"(a[mt][1]), "r"(a[mt][2]), "r"(a[mt][3]),
                          "r"(b[nt][0]), "r"(b[nt][1]));
                }
        }
        if (t + 1 < T) {
            int nb = buf ^ 1;
#pragma unroll
            for (int j = 0; j < 8; j++) As[nb][lr][lc + j] = a8[j];
            Bs[nb][brr][bcc + 0] = f2tf(bx.x); Bs[nb][brr][bcc + 1] = f2tf(bx.y);
            Bs[nb][brr][bcc + 2] = f2tf(bx.z); Bs[nb][brr][bcc + 3] = f2tf(bx.w);
        }
        __syncthreads();
    }

    if (EPI == 2) {
        __shared__ float sgm[64];
        if (tid < 64) sgm[tid] = 0.0f;
        __syncthreads();
#pragma unroll
        for (int mt = 0; mt < 2; mt++)
#pragma unroll
            for (int nt = 0; nt < 4; nt++) {
                int c = warpN * 32 + nt * 8 + 2 * (lane & 3);
                int r = bm + warpM * 32 + mt * 16 + (lane >> 2);
                float bv0 = bias[bn + c], bv1 = bias[bn + c + 1];
                float m0 = 0.0f, m1 = 0.0f;
                if (r < M) {
                    m0 = fmaxf(d[mt][nt][0] + bv0, 0.0f);
                    m1 = fmaxf(d[mt][nt][1] + bv1, 0.0f);
                }
                if (r + 8 < M) {
                    m0 = fmaxf(m0, fmaxf(d[mt][nt][2] + bv0, 0.0f));
                    m1 = fmaxf(m1, fmaxf(d[mt][nt][3] + bv1, 0.0f));
                }
                atomicMax((int*)&sgm[c], __float_as_int(m0));
                atomicMax((int*)&sgm[c + 1], __float_as_int(m1));
            }
        __syncthreads();
        if (tid < 64) atomicMax((int*)&gmax[bn + tid], __float_as_int(sgm[tid]));
    } else {
#pragma unroll
        for (int mt = 0; mt < 2; mt++)
#pragma unroll
            for (int nt = 0; nt < 4; nt++) {
                int c = warpN * 32 + nt * 8 + 2 * (lane & 3);
                int r = bm + warpM * 32 + mt * 16 + (lane >> 2);
                float bv0 = 0.0f, bv1 = 0.0f;
                if (EPI == 1) { bv0 = bias[bn + c]; bv1 = bias[bn + c + 1]; }
                if (r < M) {
                    float v0 = d[mt][nt][0], v1 = d[mt][nt][1];
                    if (EPI == 1) { v0 = fmaxf(v0 + bv0, 0.0f); v1 = fmaxf(v1 + bv1, 0.0f); }
                    *(__half2*)(Out + (size_t)r * N + bn + c) = __floats2half2_rn(v0, v1);
                }
                if (r + 8 < M) {
                    float v2 = d[mt][nt][2], v3 = d[mt][nt][3];
                    if (EPI == 1) { v2 = fmaxf(v2 + bv0, 0.0f); v3 = fmaxf(v3 + bv1, 0.0f); }
                    *(__half2*)(Out + (size_t)(r + 8) * N + bn + c) = __floats2half2_rn(v2, v3);
                }
            }
    }
}

// ---------------- CSR aggregation, F=64, half features (half2/lane), unroll x4 ----------------
template <bool REL>
__global__ __launch_bounds__(256) void k_agg64(
    const int* __restrict__ rowptr, const int2* __restrict__ ep,
    const __half* __restrict__ H, const float* __restrict__ dinv2,
    const float* __restrict__ bias, __half* __restrict__ out, int n) {
    int warp = (int)((blockIdx.x * blockDim.x + threadIdx.x) >> 5);
    int lane = threadIdx.x & 31;
    if (warp >= n) return;

    const __half2* Hv = (const __half2*)H;
    float2 acc;
    {
        float2 hv = __half22float2(Hv[(size_t)warp * 32 + lane]);
        float d2 = dinv2[warp];
        acc.x = hv.x * d2; acc.y = hv.y * d2;
    }
    int e = rowptr[warp], r1 = rowptr[warp + 1];
    for (; e + 3 < r1; e += 4) {
        int2 e0 = ep[e], e1 = ep[e + 1], e2 = ep[e + 2], e3 = ep[e + 3];
        float n0 = __int_as_float(e0.y), n1 = __int_as_float(e1.y);
        float n2 = __int_as_float(e2.y), n3 = __int_as_float(e3.y);
        float2 v0 = __half22float2(Hv[(size_t)e0.x * 32 + lane]);
        float2 v1 = __half22float2(Hv[(size_t)e1.x * 32 + lane]);
        float2 v2 = __half22float2(Hv[(size_t)e2.x * 32 + lane]);
        float2 v3 = __half22float2(Hv[(size_t)e3.x * 32 + lane]);
        acc.x += v0.x * n0 + v1.x * n1 + v2.x * n2 + v3.x * n3;
        acc.y += v0.y * n0 + v1.y * n1 + v2.y * n2 + v3.y * n3;
    }
    for (; e < r1; e++) {
        int2 e0 = ep[e];
        float n0 = __int_as_float(e0.y);
        float2 v0 = __half22float2(Hv[(size_t)e0.x * 32 + lane]);
        acc.x += v0.x * n0;
        acc.y += v0.y * n0;
    }
    if (REL) {
        float2 bv = ((const float2*)bias)[lane];
        acc.x = fmaxf(acc.x + bv.x, 0.0f);
        acc.y = fmaxf(acc.y + bv.y, 0.0f);
    }
    ((__half2*)out)[(size_t)warp * 32 + lane] = __floats2half2_rn(acc.x, acc.y);
}

// ---------------- CSR aggregation, F=128, half features (uint2 = 4 halves/lane) ----------------
__global__ __launch_bounds__(256) void k_agg128(
    const int* __restrict__ rowptr, const int2* __restrict__ ep,
    const __half* __restrict__ H, const float* __restrict__ dinv2,
    __half* __restrict__ out, int n) {
    int warp = (int)((blockIdx.x * blockDim.x + threadIdx.x) >> 5);
    int lane = threadIdx.x & 31;
    if (warp >= n) return;

    const uint2* Hv = (const uint2*)H;
    float4 acc;
    {
        uint2 r = Hv[(size_t)warp * 32 + lane];
        float2 lo = __half22float2(*(__half2*)&r.x);
        float2 hi = __half22float2(*(__half2*)&r.y);
        float d2 = dinv2[warp];
        acc.x = lo.x * d2; acc.y = lo.y * d2; acc.z = hi.x * d2; acc.w = hi.y * d2;
    }
    int e = rowptr[warp], r1 = rowptr[warp + 1];
    for (; e + 3 < r1; e += 4) {
        int2 e0 = ep[e], e1 = ep[e + 1], e2 = ep[e + 2], e3 = ep[e + 3];
        float n0 = __int_as_float(e0.y), n1 = __int_as_float(e1.y);
        float n2 = __int_as_float(e2.y), n3 = __int_as_float(e3.y);
        uint2 r0 = Hv[(size_t)e0.x * 32 + lane];
        uint2 r1v = Hv[(size_t)e1.x * 32 + lane];
        uint2 r2 = Hv[(size_t)e2.x * 32 + lane];
        uint2 r3 = Hv[(size_t)e3.x * 32 + lane];
        float2 l0 = __half22float2(*(__half2*)&r0.x), h0 = __half22float2(*(__half2*)&r0.y);
        float2 l1 = __half22float2(*(__half2*)&r1v.x), h1 = __half22float2(*(__half2*)&r1v.y);
        float2 l2 = __half22float2(*(__half2*)&r2.x), h2 = __half22float2(*(__half2*)&r2.y);
        float2 l3 = __half22float2(*(__half2*)&r3.x), h3 = __half22float2(*(__half2*)&r3.y);
        acc.x += l0.x * n0 + l1.x * n1 + l2.x * n2 + l3.x * n3;
        acc.y += l0.y * n0 + l1.y * n1 + l2.y * n2 + l3.y * n3;
        acc.z += h0.x * n0 + h1.x * n1 + h2.x * n2 + h3.x * n3;
        acc.w += h0.y * n0 + h1.y * n1 + h2.y * n2 + h3.y * n3;
    }
    for (; e < r1; e++) {
        int2 e0 = ep[e];
        float n0 = __int_as_float(e0.y);
        uint2 r0 = Hv[(size_t)e0.x * 32 + lane];
        float2 l0 = __half22float2(*(__half2*)&r0.x), h0 = __half22float2(*(__half2*)&r0.y);
        acc.x += l0.x * n0; acc.y += l0.y * n0; acc.z += h0.x * n0; acc.w += h0.y * n0;
    }
    uint2 o;
    *(__half2*)&o.x = __floats2half2_rn(acc.x, acc.y);
    *(__half2*)&o.y = __floats2half2_rn(acc.z, acc.w);
    ((uint2*)out)[(size_t)warp * 32 + lane] = o;
}

// ---------------- MLP head + log_softmax ----------------
__global__ void k_head(const float* __restrict__ gmax,
                       const float* __restrict__ Wl1, const float* __restrict__ bl1,
                       const float* __restrict__ Wl2, const float* __restrict__ bl2,
                       float* __restrict__ out) {
    __shared__ float g[256];
    __shared__ float h1[128];
    __shared__ float logits[10];
    int t = threadIdx.x;
    g[t] = gmax[t];
    __syncthreads();
    if (t < 128) {
        float s = bl1[t];
        for (int k = 0; k < 256; k++) s += g[k] * Wl1[k * 128 + t];
        h1[t] = fmaxf(s, 0.0f);
    }
    __syncthreads();
    if (t < 10) {
        float s = bl2[t];
        for (int k = 0; k < 128; k++) s += h1[k] * Wl2[k * 10 + t];
        logits[t] = s;
    }
    __syncthreads();
    if (t == 0) {
        float m = -1e30f;
        for (int c = 0; c < 10; c++) m = fmaxf(m, logits[c]);
        float se = 0.0f;
        for (int c = 0; c < 10; c++) se += expf(logits[c] - m);
        float lse = logf(se);
        for (int c = 0; c < 10; c++) out[c] = logits[c] - m - lse;
    }
}

// ---------------- launch ----------------
extern "C" void kernel_launch(void* const* d_in, const int* in_sizes, int n_in,
                              void* d_out, int out_size) {
    const float* x   = (const float*)d_in[0];
    const void*  ei  = d_in[1];
    const float* ew  = (const float*)d_in[2];
    const float* W1  = (const float*)d_in[3];
    const float* b1  = (const float*)d_in[4];
    const float* W2  = (const float*)d_in[5];
    const float* b2  = (const float*)d_in[6];
    const float* W3  = (const float*)d_in[7];
    const float* b3  = (const float*)d_in[8];
    const float* Wl1 = (const float*)d_in[9];
    const float* bl1 = (const float*)d_in[10];
    const float* Wl2 = (const float*)d_in[11];
    const float* bl2 = (const float*)d_in[12];
    float* out = (float*)d_out;

    int E = in_sizes[2];
    int N = in_sizes[0] / F0;

    float *deg, *dinv, *dinv2, *gmax;
    int *cnt, *part, *bsum, *rowptr, *cursor, *flag;
    int2* epack;
    __half *hh, *xh;
    cudaGetSymbolAddress((void**)&deg,    g_deg);
    cudaGetSymbolAddress((void**)&dinv,   g_dinv);
    cudaGetSymbolAddress((void**)&dinv2,  g_dinv2);
    cudaGetSymbolAddress((void**)&cnt,    g_cnt);
    cudaGetSymbolAddress((void**)&part,   g_part);
    cudaGetSymbolAddress((void**)&bsum,   g_bsum);
    cudaGetSymbolAddress((void**)&rowptr, g_rowptr);
    cudaGetSymbolAddress((void**)&cursor, g_cursor);
    cudaGetSymbolAddress((void**)&epack,  g_epack);
    cudaGetSymbolAddress((void**)&flag,   g_is32);
    cudaGetSymbolAddress((void**)&hh,     g_hh);
    cudaGetSymbolAddress((void**)&xh,     g_xh);
    cudaGetSymbolAddress((void**)&gmax,   g_gmax);

    // ---- init + dtype detect (sampled) + degree/histogram ----
    k_zero_nd<<<(N + 255) / 256, 256>>>(deg, cnt, N, flag, gmax);
    int det = E < 65536 ? E : 65536;
    k_detect<<<(det + 255) / 256, 256>>>((const long long*)ei, det, N, flag);
    k_hist<<<(E + 255) / 256, 256>>>(ei, E, flag, ew, cnt, deg);

    // ---- CSR build (scan3 fuses dinv) ----
    int nb = (N + SCAN_BLK - 1) / SCAN_BLK;
    k_scan1<<<nb, 256>>>(cnt, part, bsum, N);
    k_scan2<<<1, 128>>>(bsum, nb);
    k_scan3<<<(N + 255) / 256, 256>>>(rowptr, cursor, part, bsum, deg, dinv, dinv2, N, E);
    k_sort<<<(E + 255) / 256, 256>>>(ei, E, flag, ew, dinv, cursor, epack);

    int aggGrid = (N + 7) / 8;
    int gy = (N + 127) / 128;

    // ---- layer 1: hh = x W1 (128->64); xh = relu(A_hat hh + b1) ----
    k_tfgemm<0, float><<<dim3(F1 / 64, gy), 256>>>(x, W1, nullptr, hh, nullptr, N, F0, F1);
    k_agg64<true><<<aggGrid, 256>>>(rowptr, epack, hh, dinv2, b1, xh, N);

    // ---- layer 2: hh = A_hat xh (64-wide); xh = relu(hh W2 + b2) ----
    k_agg64<false><<<aggGrid, 256>>>(rowptr, epack, xh, dinv2, nullptr, hh, N);
    k_tfgemm<1, __half><<<dim3(F2 / 64, gy), 256>>>(hh, W2, b2, xh, nullptr, N, F1, F2);

    // ---- layer 3: hh = A_hat xh (128-wide); gmax = colmax(relu(hh W3 + b3)) ----
    k_agg128<<<aggGrid, 256>>>(rowptr, epack, xh, dinv2, hh, N);
    k_tfgemm<2, __half><<<dim3(F3 / 64, gy), 256>>>(hh, W3, b3, nullptr, gmax, N, F2, F3);

    k_head<<<1, 256>>>(gmax, Wl1, bl1, Wl2, bl2, out);
}

// round 10
// speedup vs baseline: 5.6536x; 1.0654x over previous
#include <cuda_runtime.h>
#include <cuda_fp16.h>
#include <stdint.h>
#include <math.h>

#define NN 100000
#define F0 128
#define F1 64
#define F2 128
#define F3 256
#define MAXF 256
#define MAXE 1600000
#define SCAN_BLK 1024
#define NBLK ((NN + SCAN_BLK - 1) / SCAN_BLK)

// ---------------- scratch (static device globals; no allocation) ----------------
__device__ float  g_deg[NN];
__device__ float  g_dinv[NN];
__device__ float  g_dinv2[NN];
__device__ int    g_cnt[NN];
__device__ int    g_part[NN];
__device__ int    g_bsum[NBLK];
__device__ int    g_rowptr[NN + 1];
__device__ int    g_cursor[NN];
__device__ int2   g_epack[MAXE];            // {src, float_bits(norm)} dst-sorted
__device__ int    g_is32;
__device__ __half g_hh[(size_t)NN * MAXF];  // half feature buffer A
__device__ __half g_xh[(size_t)NN * MAXF];  // half feature buffer B
__device__ float  g_gmax[F3];

// ---------------- init + dtype detect + degree/histogram ----------------
__global__ void k_zero_nd(float* deg, int* cnt, int n, int* flag, float* gmax) {
    int i = blockIdx.x * blockDim.x + threadIdx.x;
    if (i < n) { deg[i] = 1.0f; cnt[i] = 0; }
    if (i < F3) gmax[i] = 0.0f;
    if (i == 0) *flag = 0;
}

__global__ void k_detect(const long long* __restrict__ ei64, int e, int n, int* flag) {
    int i = blockIdx.x * blockDim.x + threadIdx.x;
    if (i < e) {
        long long v = ei64[i];
        if (v < 0 || v >= (long long)n) atomicOr(flag, 1);
    }
}

__global__ void k_hist(const void* __restrict__ ei, int e,
                       const int* __restrict__ flag, const float* __restrict__ ew,
                       int* __restrict__ cnt, float* __restrict__ deg) {
    int i = blockIdx.x * blockDim.x + threadIdx.x;
    if (i >= e) return;
    int d;
    if (*flag) d = ((const int*)ei)[e + i];
    else       d = (int)((const long long*)ei)[e + i];
    atomicAdd(&cnt[d], 1);
    atomicAdd(&deg[d], ew[i]);
}

// ---------------- exclusive scan of counts (3-stage; stage 3 fuses dinv) ----------------
__global__ __launch_bounds__(256) void k_scan1(const int* __restrict__ in,
                                               int* __restrict__ out,
                                               int* __restrict__ bsum, int n) {
    __shared__ int ts[256];
    int t = threadIdx.x;
    int base = blockIdx.x * SCAN_BLK + t * 4;
    int v0 = 0, v1 = 0, v2 = 0, v3 = 0;
    if (base + 0 < n) v0 = in[base + 0];
    if (base + 1 < n) v1 = in[base + 1];
    if (base + 2 < n) v2 = in[base + 2];
    if (base + 3 < n) v3 = in[base + 3];
    int tsum = v0 + v1 + v2 + v3;
    ts[t] = tsum;
    __syncthreads();
    for (int off = 1; off < 256; off <<= 1) {
        int x = (t >= off) ? ts[t - off] : 0;
        __syncthreads();
        ts[t] += x;
        __syncthreads();
    }
    int excl = ts[t] - tsum;
    if (t == 255) bsum[blockIdx.x] = ts[255];
    if (base + 0 < n) out[base + 0] = excl;
    if (base + 1 < n) out[base + 1] = excl + v0;
    if (base + 2 < n) out[base + 2] = excl + v0 + v1;
    if (base + 3 < n) out[base + 3] = excl + v0 + v1 + v2;
}

__global__ __launch_bounds__(128) void k_scan2(int* bsum, int nb) {
    __shared__ int s[128];
    int t = threadIdx.x;
    int v = (t < nb) ? bsum[t] : 0;
    s[t] = v;
    __syncthreads();
    for (int off = 1; off < 128; off <<= 1) {
        int x = (t >= off) ? s[t - off] : 0;
        __syncthreads();
        s[t] += x;
        __syncthreads();
    }
    if (t < nb) bsum[t] = s[t] - v;
}

__global__ void k_scan3(int* __restrict__ rowptr, int* __restrict__ cursor,
                        const int* __restrict__ part, const int* __restrict__ bsum,
                        const float* __restrict__ deg,
                        float* __restrict__ dinv, float* __restrict__ dinv2,
                        int n, int e) {
    int i = blockIdx.x * blockDim.x + threadIdx.x;
    if (i < n) {
        int r = part[i] + bsum[i / SCAN_BLK];
        rowptr[i] = r;
        cursor[i] = r;
        float d = deg[i];
        dinv[i] = rsqrtf(d);
        dinv2[i] = 1.0f / d;
    }
    if (i == 0) rowptr[n] = e;
}

__global__ void k_sort(const void* __restrict__ ei, int e,
                       const int* __restrict__ flag,
                       const float* __restrict__ ew, const float* __restrict__ dinv,
                       int* __restrict__ cursor, int2* __restrict__ epack) {
    int i = blockIdx.x * blockDim.x + threadIdx.x;
    if (i >= e) return;
    int s, d;
    if (*flag) {
        const int* p = (const int*)ei;
        s = p[i]; d = p[e + i];
    } else {
        const long long* p = (const long long*)ei;
        s = (int)p[i]; d = (int)p[e + i];
    }
    int pos = atomicAdd(&cursor[d], 1);
    epack[pos] = make_int2(s, __float_as_int(dinv[s] * ew[i] * dinv[d]));
}

// ---------------- tf32 tensor-core GEMM: 128x64 tile, BK=16, 8 warps ----------------
__device__ __forceinline__ uint32_t f2tf(float f) {
    uint32_t u;
    asm("cvt.rna.tf32.f32 %0, %1;" : "=r"(u) : "f"(f));
    return u;
}

__device__ __forceinline__ void load_a8(const float* Ap, bool aok, uint32_t* t8) {
    float4 a0 = make_float4(0.f, 0.f, 0.f, 0.f), a1 = a0;
    if (aok) { a0 = *(const float4*)Ap; a1 = *(const float4*)(Ap + 4); }
    t8[0] = f2tf(a0.x); t8[1] = f2tf(a0.y); t8[2] = f2tf(a0.z); t8[3] = f2tf(a0.w);
    t8[4] = f2tf(a1.x); t8[5] = f2tf(a1.y); t8[6] = f2tf(a1.z); t8[7] = f2tf(a1.w);
}

__device__ __forceinline__ void load_a8(const __half* Ap, bool aok, uint32_t* t8) {
    uint4 raw = make_uint4(0u, 0u, 0u, 0u);
    if (aok) raw = *(const uint4*)Ap;
    const __half2* h = (const __half2*)&raw;
#pragma unroll
    for (int j = 0; j < 4; j++) {
        float2 f = __half22float2(h[j]);
        t8[2 * j + 0] = f2tf(f.x);
        t8[2 * j + 1] = f2tf(f.y);
    }
}

template <int EPI, typename TA>
__global__ __launch_bounds__(256) void k_tfgemm(
    const TA* __restrict__ A, const float* __restrict__ B,
    const float* __restrict__ bias, __half* __restrict__ Out,
    float* __restrict__ gmax, int M, int K, int N) {
    __shared__ uint32_t As[2][128][20];
    __shared__ uint32_t Bs[2][16][72];

    int tid = threadIdx.x;
    int lane = tid & 31, wid = tid >> 5;
    int warpM = wid & 3, warpN = wid >> 2;
    int bm = blockIdx.y * 128, bn = blockIdx.x * 64;

    int lr = tid >> 1;
    int lc = (tid & 1) << 3;
    int brr = tid >> 4;
    int bcc = (tid & 15) << 2;

    const TA* Ap = A + (size_t)(bm + lr) * K + lc;
    bool aok = (bm + lr) < M;
    const float* Bp = B + (size_t)brr * N + bn + bcc;

    float d[2][4][4];
#pragma unroll
    for (int mt = 0; mt < 2; mt++)
#pragma unroll
        for (int nt = 0; nt < 4; nt++)
#pragma unroll
            for (int j = 0; j < 4; j++) d[mt][nt][j] = 0.0f;

    int T = K >> 4;
    uint32_t a8[8];
    float4 bx;

    load_a8(Ap, aok, a8);
    bx = *(const float4*)Bp;
#pragma unroll
    for (int j = 0; j < 8; j++) As[0][lr][lc + j] = a8[j];
    Bs[0][brr][bcc + 0] = f2tf(bx.x); Bs[0][brr][bcc + 1] = f2tf(bx.y);
    Bs[0][brr][bcc + 2] = f2tf(bx.z); Bs[0][brr][bcc + 3] = f2tf(bx.w);
    __syncthreads();

    for (int t = 0; t < T; t++) {
        int buf = t & 1;
        if (t + 1 < T) {
            load_a8(Ap + (t + 1) * 16, aok, a8);
            bx = *(const float4*)(Bp + (size_t)(t + 1) * 16 * N);
        }
#pragma unroll
        for (int kk = 0; kk < 2; kk++) {
            int k0 = kk * 8 + (lane & 3);
            uint32_t a[2][4], b[4][2];
#pragma unroll
            for (int mt = 0; mt < 2; mt++) {
                int r = warpM * 32 + mt * 16 + (lane >> 2);
                a[mt][0] = As[buf][r][k0];
                a[mt][1] = As[buf][r + 8][k0];
                a[mt][2] = As[buf][r][k0 + 4];
                a[mt][3] = As[buf][r + 8][k0 + 4];
            }
#pragma unroll
            for (int nt = 0; nt < 4; nt++) {
                int c = warpN * 32 + nt * 8 + (lane >> 2);
                b[nt][0] = Bs[buf][k0][c];
                b[nt][1] = Bs[buf][k0 + 4][c];
            }
#pragma unroll
            for (int mt = 0; mt < 2; mt++)
#pragma unroll
                for (int nt = 0; nt < 4; nt++) {
                    asm volatile(
                        "mma.sync.aligned.m16n8k8.row.col.f32.tf32.tf32.f32 "
                        "{%0,%1,%2,%3}, {%4,%5,%6,%7}, {%8,%9}, {%0,%1,%2,%3};"
                        : "+f"(d[mt][nt][0]), "+f"(d[mt][nt][1]),
                          "+f"(d[mt][nt][2]), "+f"(d[mt][nt][3])
                        : "r"(a[mt][0]), "r"(a[mt][1]), "r"(a[mt][2]), "r"(a[mt][3]),
                          "r"(b[nt][0]), "r"(b[nt][1]));
                }
        }
        if (t + 1 < T) {
            int nb = buf ^ 1;
#pragma unroll
            for (int j = 0; j < 8; j++) As[nb][lr][lc + j] = a8[j];
            Bs[nb][brr][bcc + 0] = f2tf(bx.x); Bs[nb][brr][bcc + 1] = f2tf(bx.y);
            Bs[nb][brr][bcc + 2] = f2tf(bx.z); Bs[nb][brr][bcc + 3] = f2tf(bx.w);
        }
        __syncthreads();
    }

    if (EPI == 2) {
        __shared__ float sgm[64];
        if (tid < 64) sgm[tid] = 0.0f;
        __syncthreads();
#pragma unroll
        for (int mt = 0; mt < 2; mt++)
#pragma unroll
            for (int nt = 0; nt < 4; nt++) {
                int c = warpN * 32 + nt * 8 + 2 * (lane & 3);
                int r = bm + warpM * 32 + mt * 16 + (lane >> 2);
                float bv0 = bias[bn + c], bv1 = bias[bn + c + 1];
                float m0 = 0.0f, m1 = 0.0f;
                if (r < M) {
                    m0 = fmaxf(d[mt][nt][0] + bv0, 0.0f);
                    m1 = fmaxf(d[mt][nt][1] + bv1, 0.0f);
                }
                if (r + 8 < M) {
                    m0 = fmaxf(m0, fmaxf(d[mt][nt][2] + bv0, 0.0f));
                    m1 = fmaxf(m1, fmaxf(d[mt][nt][3] + bv1, 0.0f));
                }
                atomicMax((int*)&sgm[c], __float_as_int(m0));
                atomicMax((int*)&sgm[c + 1], __float_as_int(m1));
            }
        __syncthreads();
        if (tid < 64) atomicMax((int*)&gmax[bn + tid], __float_as_int(sgm[tid]));
    } else {
#pragma unroll
        for (int mt = 0; mt < 2; mt++)
#pragma unroll
            for (int nt = 0; nt < 4; nt++) {
                int c = warpN * 32 + nt * 8 + 2 * (lane & 3);
                int r = bm + warpM * 32 + mt * 16 + (lane >> 2);
                float bv0 = 0.0f, bv1 = 0.0f;
                if (EPI == 1) { bv0 = bias[bn + c]; bv1 = bias[bn + c + 1]; }
                if (r < M) {
                    float v0 = d[mt][nt][0], v1 = d[mt][nt][1];
                    if (EPI == 1) { v0 = fmaxf(v0 + bv0, 0.0f); v1 = fmaxf(v1 + bv1, 0.0f); }
                    *(__half2*)(Out + (size_t)r * N + bn + c) = __floats2half2_rn(v0, v1);
                }
                if (r + 8 < M) {
                    float v2 = d[mt][nt][2], v3 = d[mt][nt][3];
                    if (EPI == 1) { v2 = fmaxf(v2 + bv0, 0.0f); v3 = fmaxf(v3 + bv1, 0.0f); }
                    *(__half2*)(Out + (size_t)(r + 8) * N + bn + c) = __floats2half2_rn(v2, v3);
                }
            }
    }
}

// ---------------- CSR aggregation, F=64: HALF-WARP per node, uint2 (4 halves)/lane ----------------
template <bool REL>
__global__ __launch_bounds__(256) void k_agg64(
    const int* __restrict__ rowptr, const int2* __restrict__ ep,
    const __half* __restrict__ H, const float* __restrict__ dinv2,
    const float* __restrict__ bias, __half* __restrict__ out, int n) {
    int hw = (int)((blockIdx.x * blockDim.x + threadIdx.x) >> 4);  // half-warp id = node
    int li = threadIdx.x & 15;
    if (hw >= n) return;

    const uint2* Hv = (const uint2*)H;   // 16 uint2 per 64-half row
    float4 acc;
    {
        uint2 r = Hv[(size_t)hw * 16 + li];
        float2 lo = __half22float2(*(__half2*)&r.x);
        float2 hi = __half22float2(*(__half2*)&r.y);
        float d2 = dinv2[hw];
        acc.x = lo.x * d2; acc.y = lo.y * d2; acc.z = hi.x * d2; acc.w = hi.y * d2;
    }
    int e = rowptr[hw], r1 = rowptr[hw + 1];
    for (; e + 3 < r1; e += 4) {
        int2 e0 = ep[e], e1 = ep[e + 1], e2 = ep[e + 2], e3 = ep[e + 3];
        float n0 = __int_as_float(e0.y), n1 = __int_as_float(e1.y);
        float n2 = __int_as_float(e2.y), n3 = __int_as_float(e3.y);
        uint2 r0 = Hv[(size_t)e0.x * 16 + li];
        uint2 r1v = Hv[(size_t)e1.x * 16 + li];
        uint2 r2 = Hv[(size_t)e2.x * 16 + li];
        uint2 r3 = Hv[(size_t)e3.x * 16 + li];
        float2 l0 = __half22float2(*(__half2*)&r0.x), h0 = __half22float2(*(__half2*)&r0.y);
        float2 l1 = __half22float2(*(__half2*)&r1v.x), h1 = __half22float2(*(__half2*)&r1v.y);
        float2 l2 = __half22float2(*(__half2*)&r2.x), h2 = __half22float2(*(__half2*)&r2.y);
        float2 l3 = __half22float2(*(__half2*)&r3.x), h3 = __half22float2(*(__half2*)&r3.y);
        acc.x += l0.x * n0 + l1.x * n1 + l2.x * n2 + l3.x * n3;
        acc.y += l0.y * n0 + l1.y * n1 + l2.y * n2 + l3.y * n3;
        acc.z += h0.x * n0 + h1.x * n1 + h2.x * n2 + h3.x * n3;
        acc.w += h0.y * n0 + h1.y * n1 + h2.y * n2 + h3.y * n3;
    }
    for (; e < r1; e++) {
        int2 e0 = ep[e];
        float n0 = __int_as_float(e0.y);
        uint2 r0 = Hv[(size_t)e0.x * 16 + li];
        float2 l0 = __half22float2(*(__half2*)&r0.x), h0 = __half22float2(*(__half2*)&r0.y);
        acc.x += l0.x * n0; acc.y += l0.y * n0; acc.z += h0.x * n0; acc.w += h0.y * n0;
    }
    if (REL) {
        float4 bv = ((const float4*)bias)[li];
        acc.x = fmaxf(acc.x + bv.x, 0.0f);
        acc.y = fmaxf(acc.y + bv.y, 0.0f);
        acc.z = fmaxf(acc.z + bv.z, 0.0f);
        acc.w = fmaxf(acc.w + bv.w, 0.0f);
    }
    uint2 o;
    *(__half2*)&o.x = __floats2half2_rn(acc.x, acc.y);
    *(__half2*)&o.y = __floats2half2_rn(acc.z, acc.w);
    ((uint2*)out)[(size_t)hw * 16 + li] = o;
}

// ---------------- CSR aggregation, F=128: HALF-WARP per node, uint4 (8 halves)/lane ----------------
__global__ __launch_bounds__(256) void k_agg128(
    const int* __restrict__ rowptr, const int2* __restrict__ ep,
    const __half* __restrict__ H, const float* __restrict__ dinv2,
    __half* __restrict__ out, int n) {
    int hw = (int)((blockIdx.x * blockDim.x + threadIdx.x) >> 4);
    int li = threadIdx.x & 15;
    if (hw >= n) return;

    const uint4* Hv = (const uint4*)H;   // 16 uint4 per 128-half row
    float a0, a1, a2, a3, a4, a5, a6, a7;
    {
        uint4 r = Hv[(size_t)hw * 16 + li];
        float2 f0 = __half22float2(*(__half2*)&r.x);
        float2 f1 = __half22float2(*(__half2*)&r.y);
        float2 f2 = __half22float2(*(__half2*)&r.z);
        float2 f3 = __half22float2(*(__half2*)&r.w);
        float d2 = dinv2[hw];
        a0 = f0.x * d2; a1 = f0.y * d2; a2 = f1.x * d2; a3 = f1.y * d2;
        a4 = f2.x * d2; a5 = f2.y * d2; a6 = f3.x * d2; a7 = f3.y * d2;
    }
    int e = rowptr[hw], r1 = rowptr[hw + 1];
    for (; e + 1 < r1; e += 2) {
        int2 e0 = ep[e], e1 = ep[e + 1];
        float n0 = __int_as_float(e0.y), n1 = __int_as_float(e1.y);
        uint4 r0 = Hv[(size_t)e0.x * 16 + li];
        uint4 r1v = Hv[(size_t)e1.x * 16 + li];
        float2 p0 = __half22float2(*(__half2*)&r0.x), p1 = __half22float2(*(__half2*)&r0.y);
        float2 p2 = __half22float2(*(__half2*)&r0.z), p3 = __half22float2(*(__half2*)&r0.w);
        float2 q0 = __half22float2(*(__half2*)&r1v.x), q1 = __half22float2(*(__half2*)&r1v.y);
        float2 q2 = __half22float2(*(__half2*)&r1v.z), q3 = __half22float2(*(__half2*)&r1v.w);
        a0 += p0.x * n0 + q0.x * n1; a1 += p0.y * n0 + q0.y * n1;
        a2 += p1.x * n0 + q1.x * n1; a3 += p1.y * n0 + q1.y * n1;
        a4 += p2.x * n0 + q2.x * n1; a5 += p2.y * n0 + q2.y * n1;
        a6 += p3.x * n0 + q3.x * n1; a7 += p3.y * n0 + q3.y * n1;
    }
    if (e < r1) {
        int2 e0 = ep[e];
        float n0 = __int_as_float(e0.y);
        uint4 r0 = Hv[(size_t)e0.x * 16 + li];
        float2 p0 = __half22float2(*(__half2*)&r0.x), p1 = __half22float2(*(__half2*)&r0.y);
        float2 p2 = __half22float2(*(__half2*)&r0.z), p3 = __half22float2(*(__half2*)&r0.w);
        a0 += p0.x * n0; a1 += p0.y * n0; a2 += p1.x * n0; a3 += p1.y * n0;
        a4 += p2.x * n0; a5 += p2.y * n0; a6 += p3.x * n0; a7 += p3.y * n0;
    }
    uint4 o;
    *(__half2*)&o.x = __floats2half2_rn(a0, a1);
    *(__half2*)&o.y = __floats2half2_rn(a2, a3);
    *(__half2*)&o.z = __floats2half2_rn(a4, a5);
    *(__half2*)&o.w = __floats2half2_rn(a6, a7);
    ((uint4*)out)[(size_t)hw * 16 + li] = o;
}

// ---------------- MLP head + log_softmax ----------------
__global__ void k_head(const float* __restrict__ gmax,
                       const float* __restrict__ Wl1, const float* __restrict__ bl1,
                       const float* __restrict__ Wl2, const float* __restrict__ bl2,
                       float* __restrict__ out) {
    __shared__ float g[256];
    __shared__ float h1[128];
    __shared__ float logits[10];
    int t = threadIdx.x;
    g[t] = gmax[t];
    __syncthreads();
    if (t < 128) {
        float s = bl1[t];
        for (int k = 0; k < 256; k++) s += g[k] * Wl1[k * 128 + t];
        h1[t] = fmaxf(s, 0.0f);
    }
    __syncthreads();
    if (t < 10) {
        float s = bl2[t];
        for (int k = 0; k < 128; k++) s += h1[k] * Wl2[k * 10 + t];
        logits[t] = s;
    }
    __syncthreads();
    if (t == 0) {
        float m = -1e30f;
        for (int c = 0; c < 10; c++) m = fmaxf(m, logits[c]);
        float se = 0.0f;
        for (int c = 0; c < 10; c++) se += expf(logits[c] - m);
        float lse = logf(se);
        for (int c = 0; c < 10; c++) out[c] = logits[c] - m - lse;
    }
}

// ---------------- launch ----------------
extern "C" void kernel_launch(void* const* d_in, const int* in_sizes, int n_in,
                              void* d_out, int out_size) {
    const float* x   = (const float*)d_in[0];
    const void*  ei  = d_in[1];
    const float* ew  = (const float*)d_in[2];
    const float* W1  = (const float*)d_in[3];
    const float* b1  = (const float*)d_in[4];
    const float* W2  = (const float*)d_in[5];
    const float* b2  = (const float*)d_in[6];
    const float* W3  = (const float*)d_in[7];
    const float* b3  = (const float*)d_in[8];
    const float* Wl1 = (const float*)d_in[9];
    const float* bl1 = (const float*)d_in[10];
    const float* Wl2 = (const float*)d_in[11];
    const float* bl2 = (const float*)d_in[12];
    float* out = (float*)d_out;

    int E = in_sizes[2];
    int N = in_sizes[0] / F0;

    float *deg, *dinv, *dinv2, *gmax;
    int *cnt, *part, *bsum, *rowptr, *cursor, *flag;
    int2* epack;
    __half *hh, *xh;
    cudaGetSymbolAddress((void**)&deg,    g_deg);
    cudaGetSymbolAddress((void**)&dinv,   g_dinv);
    cudaGetSymbolAddress((void**)&dinv2,  g_dinv2);
    cudaGetSymbolAddress((void**)&cnt,    g_cnt);
    cudaGetSymbolAddress((void**)&part,   g_part);
    cudaGetSymbolAddress((void**)&bsum,   g_bsum);
    cudaGetSymbolAddress((void**)&rowptr, g_rowptr);
    cudaGetSymbolAddress((void**)&cursor, g_cursor);
    cudaGetSymbolAddress((void**)&epack,  g_epack);
    cudaGetSymbolAddress((void**)&flag,   g_is32);
    cudaGetSymbolAddress((void**)&hh,     g_hh);
    cudaGetSymbolAddress((void**)&xh,     g_xh);
    cudaGetSymbolAddress((void**)&gmax,   g_gmax);

    // ---- init + dtype detect (sampled) + degree/histogram ----
    k_zero_nd<<<(N + 255) / 256, 256>>>(deg, cnt, N, flag, gmax);
    int det = E < 65536 ? E : 65536;
    k_detect<<<(det + 255) / 256, 256>>>((const long long*)ei, det, N, flag);
    k_hist<<<(E + 255) / 256, 256>>>(ei, E, flag, ew, cnt, deg);

    // ---- CSR build (scan3 fuses dinv) ----
    int nb = (N + SCAN_BLK - 1) / SCAN_BLK;
    k_scan1<<<nb, 256>>>(cnt, part, bsum, N);
    k_scan2<<<1, 128>>>(bsum, nb);
    k_scan3<<<(N + 255) / 256, 256>>>(rowptr, cursor, part, bsum, deg, dinv, dinv2, N, E);
    k_sort<<<(E + 255) / 256, 256>>>(ei, E, flag, ew, dinv, cursor, epack);

    int aggGrid = (N + 15) / 16;   // 16 half-warps (nodes) per 256-thread block
    int gy = (N + 127) / 128;

    // ---- layer 1: hh = x W1 (128->64); xh = relu(A_hat hh + b1) ----
    k_tfgemm<0, float><<<dim3(F1 / 64, gy), 256>>>(x, W1, nullptr, hh, nullptr, N, F0, F1);
    k_agg64<true><<<aggGrid, 256>>>(rowptr, epack, hh, dinv2, b1, xh, N);

    // ---- layer 2: hh = A_hat xh (64-wide); xh = relu(hh W2 + b2) ----
    k_agg64<false><<<aggGrid, 256>>>(rowptr, epack, xh, dinv2, nullptr, hh, N);
    k_tfgemm<1, __half><<<dim3(F2 / 64, gy), 256>>>(hh, W2, b2, xh, nullptr, N, F1, F2);

    // ---- layer 3: hh = A_hat xh (128-wide); gmax = colmax(relu(hh W3 + b3)) ----
    k_agg128<<<aggGrid, 256>>>(rowptr, epack, xh, dinv2, hh, N);
    k_tfgemm<2, __half><<<dim3(F3 / 64, gy), 256>>>(hh, W3, b3, nullptr, gmax, N, F2, F3);

    k_head<<<1, 256>>>(gmax, Wl1, bl1, Wl2, bl2, out);
}

// round 11
// speedup vs baseline: 5.7811x; 1.0226x over previous
#include <cuda_runtime.h>
#include <cuda_fp16.h>
#include <stdint.h>
#include <math.h>

#define NN 100000
#define F0 128
#define F1 64
#define F2 128
#define F3 256
#define MAXF 256
#define MAXE 1600000
#define SCAN_BLK 1024
#define NBLK ((NN + SCAN_BLK - 1) / SCAN_BLK)

// ---------------- scratch (static device globals; no allocation) ----------------
__device__ float  g_deg[NN];
__device__ float  g_dinv[NN];
__device__ float  g_dinv2[NN];
__device__ int    g_cnt[NN];
__device__ int    g_part[NN];
__device__ int    g_bsum[NBLK];
__device__ int    g_rowptr[NN + 1];
__device__ int    g_cursor[NN];
__device__ int2   g_epack[MAXE];            // {src, float_bits(norm)} dst-sorted
__device__ int    g_is32;
__device__ __half g_hh[(size_t)NN * MAXF];  // half feature buffer A
__device__ __half g_xh[(size_t)NN * MAXF];  // half feature buffer B
__device__ float  g_gmax[F3];

// ---------------- init + dtype detect (fused) ----------------
__global__ void k_init_detect(float* deg, int* cnt, int n, int* flag, float* gmax,
                              const long long* __restrict__ ei64, int ndet) {
    int i = blockIdx.x * blockDim.x + threadIdx.x;
    if (i == 0) *flag = 0;
    if (i < n) { deg[i] = 1.0f; cnt[i] = 0; }
    if (i < F3) gmax[i] = 0.0f;
    if (i < ndet) {
        long long v = ei64[i];
        if (v < 0 || v >= (long long)n) atomicOr(flag, 1);
    }
}

__global__ void k_hist(const void* __restrict__ ei, int e,
                       const int* __restrict__ flag, const float* __restrict__ ew,
                       int* __restrict__ cnt, float* __restrict__ deg) {
    int i = blockIdx.x * blockDim.x + threadIdx.x;
    if (i >= e) return;
    int d;
    if (*flag) d = ((const int*)ei)[e + i];
    else       d = (int)((const long long*)ei)[e + i];
    atomicAdd(&cnt[d], 1);
    atomicAdd(&deg[d], ew[i]);
}

// ---------------- exclusive scan of counts (3-stage; stage 3 fuses dinv) ----------------
__global__ __launch_bounds__(256) void k_scan1(const int* __restrict__ in,
                                               int* __restrict__ out,
                                               int* __restrict__ bsum, int n) {
    __shared__ int ts[256];
    int t = threadIdx.x;
    int base = blockIdx.x * SCAN_BLK + t * 4;
    int v0 = 0, v1 = 0, v2 = 0, v3 = 0;
    if (base + 0 < n) v0 = in[base + 0];
    if (base + 1 < n) v1 = in[base + 1];
    if (base + 2 < n) v2 = in[base + 2];
    if (base + 3 < n) v3 = in[base + 3];
    int tsum = v0 + v1 + v2 + v3;
    ts[t] = tsum;
    __syncthreads();
    for (int off = 1; off < 256; off <<= 1) {
        int x = (t >= off) ? ts[t - off] : 0;
        __syncthreads();
        ts[t] += x;
        __syncthreads();
    }
    int excl = ts[t] - tsum;
    if (t == 255) bsum[blockIdx.x] = ts[255];
    if (base + 0 < n) out[base + 0] = excl;
    if (base + 1 < n) out[base + 1] = excl + v0;
    if (base + 2 < n) out[base + 2] = excl + v0 + v1;
    if (base + 3 < n) out[base + 3] = excl + v0 + v1 + v2;
}

__global__ __launch_bounds__(128) void k_scan2(int* bsum, int nb) {
    __shared__ int s[128];
    int t = threadIdx.x;
    int v = (t < nb) ? bsum[t] : 0;
    s[t] = v;
    __syncthreads();
    for (int off = 1; off < 128; off <<= 1) {
        int x = (t >= off) ? s[t - off] : 0;
        __syncthreads();
        s[t] += x;
        __syncthreads();
    }
    if (t < nb) bsum[t] = s[t] - v;
}

__global__ void k_scan3(int* __restrict__ rowptr, int* __restrict__ cursor,
                        const int* __restrict__ part, const int* __restrict__ bsum,
                        const float* __restrict__ deg,
                        float* __restrict__ dinv, float* __restrict__ dinv2,
                        int n, int e) {
    int i = blockIdx.x * blockDim.x + threadIdx.x;
    if (i < n) {
        int r = part[i] + bsum[i / SCAN_BLK];
        rowptr[i] = r;
        cursor[i] = r;
        float d = deg[i];
        dinv[i] = rsqrtf(d);
        dinv2[i] = 1.0f / d;
    }
    if (i == 0) rowptr[n] = e;
}

__global__ void k_sort(const void* __restrict__ ei, int e,
                       const int* __restrict__ flag,
                       const float* __restrict__ ew, const float* __restrict__ dinv,
                       int* __restrict__ cursor, int2* __restrict__ epack) {
    int i = blockIdx.x * blockDim.x + threadIdx.x;
    if (i >= e) return;
    int s, d;
    if (*flag) {
        const int* p = (const int*)ei;
        s = p[i]; d = p[e + i];
    } else {
        const long long* p = (const long long*)ei;
        s = (int)p[i]; d = (int)p[e + i];
    }
    int pos = atomicAdd(&cursor[d], 1);
    epack[pos] = make_int2(s, __float_as_int(dinv[s] * ew[i] * dinv[d]));
}

// ---------------- tf32 tensor-core GEMM: 128x64 tile, BK=16, 8 warps ----------------
__device__ __forceinline__ uint32_t f2tf(float f) {
    uint32_t u;
    asm("cvt.rna.tf32.f32 %0, %1;" : "=r"(u) : "f"(f));
    return u;
}

__device__ __forceinline__ void load_a8(const float* Ap, bool aok, uint32_t* t8) {
    float4 a0 = make_float4(0.f, 0.f, 0.f, 0.f), a1 = a0;
    if (aok) { a0 = *(const float4*)Ap; a1 = *(const float4*)(Ap + 4); }
    t8[0] = f2tf(a0.x); t8[1] = f2tf(a0.y); t8[2] = f2tf(a0.z); t8[3] = f2tf(a0.w);
    t8[4] = f2tf(a1.x); t8[5] = f2tf(a1.y); t8[6] = f2tf(a1.z); t8[7] = f2tf(a1.w);
}

__device__ __forceinline__ void load_a8(const __half* Ap, bool aok, uint32_t* t8) {
    uint4 raw = make_uint4(0u, 0u, 0u, 0u);
    if (aok) raw = *(const uint4*)Ap;
    const __half2* h = (const __half2*)&raw;
#pragma unroll
    for (int j = 0; j < 4; j++) {
        float2 f = __half22float2(h[j]);
        t8[2 * j + 0] = f2tf(f.x);
        t8[2 * j + 1] = f2tf(f.y);
    }
}

template <int EPI, typename TA>
__global__ __launch_bounds__(256) void k_tfgemm(
    const TA* __restrict__ A, const float* __restrict__ B,
    const float* __restrict__ bias, __half* __restrict__ Out,
    float* __restrict__ gmax, int M, int K, int N) {
    __shared__ uint32_t As[2][128][20];
    __shared__ uint32_t Bs[2][16][72];

    int tid = threadIdx.x;
    int lane = tid & 31, wid = tid >> 5;
    int warpM = wid & 3, warpN = wid >> 2;
    int bm = blockIdx.y * 128, bn = blockIdx.x * 64;

    int lr = tid >> 1;
    int lc = (tid & 1) << 3;
    int brr = tid >> 4;
    int bcc = (tid & 15) << 2;

    const TA* Ap = A + (size_t)(bm + lr) * K + lc;
    bool aok = (bm + lr) < M;
    const float* Bp = B + (size_t)brr * N + bn + bcc;

    float d[2][4][4];
#pragma unroll
    for (int mt = 0; mt < 2; mt++)
#pragma unroll
        for (int nt = 0; nt < 4; nt++)
#pragma unroll
            for (int j = 0; j < 4; j++) d[mt][nt][j] = 0.0f;

    int T = K >> 4;
    uint32_t a8[8];
    float4 bx;

    load_a8(Ap, aok, a8);
    bx = *(const float4*)Bp;
#pragma unroll
    for (int j = 0; j < 8; j++) As[0][lr][lc + j] = a8[j];
    Bs[0][brr][bcc + 0] = f2tf(bx.x); Bs[0][brr][bcc + 1] = f2tf(bx.y);
    Bs[0][brr][bcc + 2] = f2tf(bx.z); Bs[0][brr][bcc + 3] = f2tf(bx.w);
    __syncthreads();

    for (int t = 0; t < T; t++) {
        int buf = t & 1;
        if (t + 1 < T) {
            load_a8(Ap + (t + 1) * 16, aok, a8);
            bx = *(const float4*)(Bp + (size_t)(t + 1) * 16 * N);
        }
#pragma unroll
        for (int kk = 0; kk < 2; kk++) {
            int k0 = kk * 8 + (lane & 3);
            uint32_t a[2][4], b[4][2];
#pragma unroll
            for (int mt = 0; mt < 2; mt++) {
                int r = warpM * 32 + mt * 16 + (lane >> 2);
                a[mt][0] = As[buf][r][k0];
                a[mt][1] = As[buf][r + 8][k0];
                a[mt][2] = As[buf][r][k0 + 4];
                a[mt][3] = As[buf][r + 8][k0 + 4];
            }
#pragma unroll
            for (int nt = 0; nt < 4; nt++) {
                int c = warpN * 32 + nt * 8 + (lane >> 2);
                b[nt][0] = Bs[buf][k0][c];
                b[nt][1] = Bs[buf][k0 + 4][c];
            }
#pragma unroll
            for (int mt = 0; mt < 2; mt++)
#pragma unroll
                for (int nt = 0; nt < 4; nt++) {
                    asm volatile(
                        "mma.sync.aligned.m16n8k8.row.col.f32.tf32.tf32.f32 "
                        "{%0,%1,%2,%3}, {%4,%5,%6,%7}, {%8,%9}, {%0,%1,%2,%3};"
                        : "+f"(d[mt][nt][0]), "+f"(d[mt][nt][1]),
                          "+f"(d[mt][nt][2]), "+f"(d[mt][nt][3])
                        : "r"(a[mt][0]), "r"(a[mt][1]), "r"(a[mt][2]), "r"(a[mt][3]),
                          "r"(b[nt][0]), "r"(b[nt][1]));
                }
        }
        if (t + 1 < T) {
            int nb = buf ^ 1;
#pragma unroll
            for (int j = 0; j < 8; j++) As[nb][lr][lc + j] = a8[j];
            Bs[nb][brr][bcc + 0] = f2tf(bx.x); Bs[nb][brr][bcc + 1] = f2tf(bx.y);
            Bs[nb][brr][bcc + 2] = f2tf(bx.z); Bs[nb][brr][bcc + 3] = f2tf(bx.w);
        }
        __syncthreads();
    }

    if (EPI == 2) {
        __shared__ float sgm[64];
        if (tid < 64) sgm[tid] = 0.0f;
        __syncthreads();
#pragma unroll
        for (int mt = 0; mt < 2; mt++)
#pragma unroll
            for (int nt = 0; nt < 4; nt++) {
                int c = warpN * 32 + nt * 8 + 2 * (lane & 3);
                int r = bm + warpM * 32 + mt * 16 + (lane >> 2);
                float bv0 = bias[bn + c], bv1 = bias[bn + c + 1];
                float m0 = 0.0f, m1 = 0.0f;
                if (r < M) {
                    m0 = fmaxf(d[mt][nt][0] + bv0, 0.0f);
                    m1 = fmaxf(d[mt][nt][1] + bv1, 0.0f);
                }
                if (r + 8 < M) {
                    m0 = fmaxf(m0, fmaxf(d[mt][nt][2] + bv0, 0.0f));
                    m1 = fmaxf(m1, fmaxf(d[mt][nt][3] + bv1, 0.0f));
                }
                atomicMax((int*)&sgm[c], __float_as_int(m0));
                atomicMax((int*)&sgm[c + 1], __float_as_int(m1));
            }
        __syncthreads();
        if (tid < 64) atomicMax((int*)&gmax[bn + tid], __float_as_int(sgm[tid]));
    } else {
#pragma unroll
        for (int mt = 0; mt < 2; mt++)
#pragma unroll
            for (int nt = 0; nt < 4; nt++) {
                int c = warpN * 32 + nt * 8 + 2 * (lane & 3);
                int r = bm + warpM * 32 + mt * 16 + (lane >> 2);
                float bv0 = 0.0f, bv1 = 0.0f;
                if (EPI == 1) { bv0 = bias[bn + c]; bv1 = bias[bn + c + 1]; }
                if (r < M) {
                    float v0 = d[mt][nt][0], v1 = d[mt][nt][1];
                    if (EPI == 1) { v0 = fmaxf(v0 + bv0, 0.0f); v1 = fmaxf(v1 + bv1, 0.0f); }
                    *(__half2*)(Out + (size_t)r * N + bn + c) = __floats2half2_rn(v0, v1);
                }
                if (r + 8 < M) {
                    float v2 = d[mt][nt][2], v3 = d[mt][nt][3];
                    if (EPI == 1) { v2 = fmaxf(v2 + bv0, 0.0f); v3 = fmaxf(v3 + bv1, 0.0f); }
                    *(__half2*)(Out + (size_t)(r + 8) * N + bn + c) = __floats2half2_rn(v2, v3);
                }
            }
    }
}

// ---------------- CSR aggregation, F=64: QUARTER-WARP per node, uint4 (8 halves)/lane ----------------
template <bool REL>
__global__ __launch_bounds__(256) void k_agg64(
    const int* __restrict__ rowptr, const int2* __restrict__ ep,
    const __half* __restrict__ H, const float* __restrict__ dinv2,
    const float* __restrict__ bias, __half* __restrict__ out, int n) {
    int qw = (int)((blockIdx.x * blockDim.x + threadIdx.x) >> 3);  // quarter-warp id = node
    int li = threadIdx.x & 7;
    if (qw >= n) return;

    const uint4* Hv = (const uint4*)H;   // 8 uint4 per 64-half row
    float a0, a1, a2, a3, a4, a5, a6, a7;
    {
        uint4 r = Hv[(size_t)qw * 8 + li];
        float2 f0 = __half22float2(*(__half2*)&r.x);
        float2 f1 = __half22float2(*(__half2*)&r.y);
        float2 f2 = __half22float2(*(__half2*)&r.z);
        float2 f3 = __half22float2(*(__half2*)&r.w);
        float d2 = dinv2[qw];
        a0 = f0.x * d2; a1 = f0.y * d2; a2 = f1.x * d2; a3 = f1.y * d2;
        a4 = f2.x * d2; a5 = f2.y * d2; a6 = f3.x * d2; a7 = f3.y * d2;
    }
    int e = rowptr[qw], r1 = rowptr[qw + 1];
    for (; e + 3 < r1; e += 4) {
        int2 e0 = ep[e], e1 = ep[e + 1], e2 = ep[e + 2], e3 = ep[e + 3];
        float n0 = __int_as_float(e0.y), n1 = __int_as_float(e1.y);
        float n2 = __int_as_float(e2.y), n3 = __int_as_float(e3.y);
        uint4 r0 = Hv[(size_t)e0.x * 8 + li];
        uint4 r1v = Hv[(size_t)e1.x * 8 + li];
        uint4 r2 = Hv[(size_t)e2.x * 8 + li];
        uint4 r3 = Hv[(size_t)e3.x * 8 + li];
        float2 p0 = __half22float2(*(__half2*)&r0.x), p1 = __half22float2(*(__half2*)&r0.y);
        float2 p2 = __half22float2(*(__half2*)&r0.z), p3 = __half22float2(*(__half2*)&r0.w);
        float2 q0 = __half22float2(*(__half2*)&r1v.x), q1 = __half22float2(*(__half2*)&r1v.y);
        float2 q2 = __half22float2(*(__half2*)&r1v.z), q3 = __half22float2(*(__half2*)&r1v.w);
        float2 s0 = __half22float2(*(__half2*)&r2.x), s1 = __half22float2(*(__half2*)&r2.y);
        float2 s2 = __half22float2(*(__half2*)&r2.z), s3 = __half22float2(*(__half2*)&r2.w);
        float2 t0 = __half22float2(*(__half2*)&r3.x), t1 = __half22float2(*(__half2*)&r3.y);
        float2 t2 = __half22float2(*(__half2*)&r3.z), t3 = __half22float2(*(__half2*)&r3.w);
        a0 += p0.x * n0 + q0.x * n1 + s0.x * n2 + t0.x * n3;
        a1 += p0.y * n0 + q0.y * n1 + s0.y * n2 + t0.y * n3;
        a2 += p1.x * n0 + q1.x * n1 + s1.x * n2 + t1.x * n3;
        a3 += p1.y * n0 + q1.y * n1 + s1.y * n2 + t1.y * n3;
        a4 += p2.x * n0 + q2.x * n1 + s2.x * n2 + t2.x * n3;
        a5 += p2.y * n0 + q2.y * n1 + s2.y * n2 + t2.y * n3;
        a6 += p3.x * n0 + q3.x * n1 + s3.x * n2 + t3.x * n3;
        a7 += p3.y * n0 + q3.y * n1 + s3.y * n2 + t3.y * n3;
    }
    for (; e < r1; e++) {
        int2 e0 = ep[e];
        float n0 = __int_as_float(e0.y);
        uint4 r0 = Hv[(size_t)e0.x * 8 + li];
        float2 p0 = __half22float2(*(__half2*)&r0.x), p1 = __half22float2(*(__half2*)&r0.y);
        float2 p2 = __half22float2(*(__half2*)&r0.z), p3 = __half22float2(*(__half2*)&r0.w);
        a0 += p0.x * n0; a1 += p0.y * n0; a2 += p1.x * n0; a3 += p1.y * n0;
        a4 += p2.x * n0; a5 += p2.y * n0; a6 += p3.x * n0; a7 += p3.y * n0;
    }
    if (REL) {
        float4 bv0 = ((const float4*)bias)[2 * li];
        float4 bv1 = ((const float4*)bias)[2 * li + 1];
        a0 = fmaxf(a0 + bv0.x, 0.0f); a1 = fmaxf(a1 + bv0.y, 0.0f);
        a2 = fmaxf(a2 + bv0.z, 0.0f); a3 = fmaxf(a3 + bv0.w, 0.0f);
        a4 = fmaxf(a4 + bv1.x, 0.0f); a5 = fmaxf(a5 + bv1.y, 0.0f);
        a6 = fmaxf(a6 + bv1.z, 0.0f); a7 = fmaxf(a7 + bv1.w, 0.0f);
    }
    uint4 o;
    *(__half2*)&o.x = __floats2half2_rn(a0, a1);
    *(__half2*)&o.y = __floats2half2_rn(a2, a3);
    *(__half2*)&o.z = __floats2half2_rn(a4, a5);
    *(__half2*)&o.w = __floats2half2_rn(a6, a7);
    ((uint4*)out)[(size_t)qw * 8 + li] = o;
}

// ---------------- CSR aggregation, F=128: HALF-WARP per node, uint4/lane, unroll x4 ----------------
__global__ __launch_bounds__(256) void k_agg128(
    const int* __restrict__ rowptr, const int2* __restrict__ ep,
    const __half* __restrict__ H, const float* __restrict__ dinv2,
    __half* __restrict__ out, int n) {
    int hw = (int)((blockIdx.x * blockDim.x + threadIdx.x) >> 4);
    int li = threadIdx.x & 15;
    if (hw >= n) return;

    const uint4* Hv = (const uint4*)H;   // 16 uint4 per 128-half row
    float a0, a1, a2, a3, a4, a5, a6, a7;
    {
        uint4 r = Hv[(size_t)hw * 16 + li];
        float2 f0 = __half22float2(*(__half2*)&r.x);
        float2 f1 = __half22float2(*(__half2*)&r.y);
        float2 f2 = __half22float2(*(__half2*)&r.z);
        float2 f3 = __half22float2(*(__half2*)&r.w);
        float d2 = dinv2[hw];
        a0 = f0.x * d2; a1 = f0.y * d2; a2 = f1.x * d2; a3 = f1.y * d2;
        a4 = f2.x * d2; a5 = f2.y * d2; a6 = f3.x * d2; a7 = f3.y * d2;
    }
    int e = rowptr[hw], r1 = rowptr[hw + 1];
    for (; e + 3 < r1; e += 4) {
        int2 e0 = ep[e], e1 = ep[e + 1], e2 = ep[e + 2], e3 = ep[e + 3];
        float n0 = __int_as_float(e0.y), n1 = __int_as_float(e1.y);
        float n2 = __int_as_float(e2.y), n3 = __int_as_float(e3.y);
        uint4 r0 = Hv[(size_t)e0.x * 16 + li];
        uint4 r1v = Hv[(size_t)e1.x * 16 + li];
        uint4 r2 = Hv[(size_t)e2.x * 16 + li];
        uint4 r3 = Hv[(size_t)e3.x * 16 + li];
        float2 p0 = __half22float2(*(__half2*)&r0.x), p1 = __half22float2(*(__half2*)&r0.y);
        float2 p2 = __half22float2(*(__half2*)&r0.z), p3 = __half22float2(*(__half2*)&r0.w);
        float2 q0 = __half22float2(*(__half2*)&r1v.x), q1 = __half22float2(*(__half2*)&r1v.y);
        float2 q2 = __half22float2(*(__half2*)&r1v.z), q3 = __half22float2(*(__half2*)&r1v.w);
        float2 s0 = __half22float2(*(__half2*)&r2.x), s1 = __half22float2(*(__half2*)&r2.y);
        float2 s2 = __half22float2(*(__half2*)&r2.z), s3 = __half22float2(*(__half2*)&r2.w);
        float2 t0 = __half22float2(*(__half2*)&r3.x), t1 = __half22float2(*(__half2*)&r3.y);
        float2 t2 = __half22float2(*(__half2*)&r3.z), t3 = __half22float2(*(__half2*)&r3.w);
        a0 += p0.x * n0 + q0.x * n1 + s0.x * n2 + t0.x * n3;
        a1 += p0.y * n0 + q0.y * n1 + s0.y * n2 + t0.y * n3;
        a2 += p1.x * n0 + q1.x * n1 + s1.x * n2 + t1.x * n3;
        a3 += p1.y * n0 + q1.y * n1 + s1.y * n2 + t1.y * n3;
        a4 += p2.x * n0 + q2.x * n1 + s2.x * n2 + t2.x * n3;
        a5 += p2.y * n0 + q2.y * n1 + s2.y * n2 + t2.y * n3;
        a6 += p3.x * n0 + q3.x * n1 + s3.x * n2 + t3.x * n3;
        a7 += p3.y * n0 + q3.y * n1 + s3.y * n2 + t3.y * n3;
    }
    for (; e < r1; e++) {
        int2 e0 = ep[e];
        float n0 = __int_as_float(e0.y);
        uint4 r0 = Hv[(size_t)e0.x * 16 + li];
        float2 p0 = __half22float2(*(__half2*)&r0.x), p1 = __half22float2(*(__half2*)&r0.y);
        float2 p2 = __half22float2(*(__half2*)&r0.z), p3 = __half22float2(*(__half2*)&r0.w);
        a0 += p0.x * n0; a1 += p0.y * n0; a2 += p1.x * n0; a3 += p1.y * n0;
        a4 += p2.x * n0; a5 += p2.y * n0; a6 += p3.x * n0; a7 += p3.y * n0;
    }
    uint4 o;
    *(__half2*)&o.x = __floats2half2_rn(a0, a1);
    *(__half2*)&o.y = __floats2half2_rn(a2, a3);
    *(__half2*)&o.z = __floats2half2_rn(a4, a5);
    *(__half2*)&o.w = __floats2half2_rn(a6, a7);
    ((uint4*)out)[(size_t)hw * 16 + li] = o;
}

// ---------------- MLP head + log_softmax ----------------
__global__ void k_head(const float* __restrict__ gmax,
                       const float* __restrict__ Wl1, const float* __restrict__ bl1,
                       const float* __restrict__ Wl2, const float* __restrict__ bl2,
                       float* __restrict__ out) {
    __shared__ float g[256];
    __shared__ float h1[128];
    __shared__ float logits[10];
    int t = threadIdx.x;
    g[t] = gmax[t];
    __syncthreads();
    if (t < 128) {
        float s = bl1[t];
        for (int k = 0; k < 256; k++) s += g[k] * Wl1[k * 128 + t];
        h1[t] = fmaxf(s, 0.0f);
    }
    __syncthreads();
    if (t < 10) {
        float s = bl2[t];
        for (int k = 0; k < 128; k++) s += h1[k] * Wl2[k * 10 + t];
        logits[t] = s;
    }
    __syncthreads();
    if (t == 0) {
        float m = -1e30f;
        for (int c = 0; c < 10; c++) m = fmaxf(m, logits[c]);
        float se = 0.0f;
        for (int c = 0; c < 10; c++) se += expf(logits[c] - m);
        float lse = logf(se);
        for (int c = 0; c < 10; c++) out[c] = logits[c] - m - lse;
    }
}

// ---------------- launch ----------------
extern "C" void kernel_launch(void* const* d_in, const int* in_sizes, int n_in,
                              void* d_out, int out_size) {
    const float* x   = (const float*)d_in[0];
    const void*  ei  = d_in[1];
    const float* ew  = (const float*)d_in[2];
    const float* W1  = (const float*)d_in[3];
    const float* b1  = (const float*)d_in[4];
    const float* W2  = (const float*)d_in[5];
    const float* b2  = (const float*)d_in[6];
    const float* W3  = (const float*)d_in[7];
    const float* b3  = (const float*)d_in[8];
    const float* Wl1 = (const float*)d_in[9];
    const float* bl1 = (const float*)d_in[10];
    const float* Wl2 = (const float*)d_in[11];
    const float* bl2 = (const float*)d_in[12];
    float* out = (float*)d_out;

    int E = in_sizes[2];
    int N = in_sizes[0] / F0;

    float *deg, *dinv, *dinv2, *gmax;
    int *cnt, *part, *bsum, *rowptr, *cursor, *flag;
    int2* epack;
    __half *hh, *xh;
    cudaGetSymbolAddress((void**)&deg,    g_deg);
    cudaGetSymbolAddress((void**)&dinv,   g_dinv);
    cudaGetSymbolAddress((void**)&dinv2,  g_dinv2);
    cudaGetSymbolAddress((void**)&cnt,    g_cnt);
    cudaGetSymbolAddress((void**)&part,   g_part);
    cudaGetSymbolAddress((void**)&bsum,   g_bsum);
    cudaGetSymbolAddress((void**)&rowptr, g_rowptr);
    cudaGetSymbolAddress((void**)&cursor, g_cursor);
    cudaGetSymbolAddress((void**)&epack,  g_epack);
    cudaGetSymbolAddress((void**)&flag,   g_is32);
    cudaGetSymbolAddress((void**)&hh,     g_hh);
    cudaGetSymbolAddress((void**)&xh,     g_xh);
    cudaGetSymbolAddress((void**)&gmax,   g_gmax);

    // ---- init + dtype detect (sampled, fused) + degree/histogram ----
    int det = E < 65536 ? E : 65536;
    k_init_detect<<<(N + 255) / 256, 256>>>(deg, cnt, N, flag, gmax,
                                            (const long long*)ei, det);
    k_hist<<<(E + 255) / 256, 256>>>(ei, E, flag, ew, cnt, deg);

    // ---- CSR build (scan3 fuses dinv) ----
    int nb = (N + SCAN_BLK - 1) / SCAN_BLK;
    k_scan1<<<nb, 256>>>(cnt, part, bsum, N);
    k_scan2<<<1, 128>>>(bsum, nb);
    k_scan3<<<(N + 255) / 256, 256>>>(rowptr, cursor, part, bsum, deg, dinv, dinv2, N, E);
    k_sort<<<(E + 255) / 256, 256>>>(ei, E, flag, ew, dinv, cursor, epack);

    int agg64Grid = (N + 31) / 32;   // 32 quarter-warps (nodes) per 256-thread block
    int agg128Grid = (N + 15) / 16;  // 16 half-warps per block
    int gy = (N + 127) / 128;

    // ---- layer 1: hh = x W1 (128->64); xh = relu(A_hat hh + b1) ----
    k_tfgemm<0, float><<<dim3(F1 / 64, gy), 256>>>(x, W1, nullptr, hh, nullptr, N, F0, F1);
    k_agg64<true><<<agg64Grid, 256>>>(rowptr, epack, hh, dinv2, b1, xh, N);

    // ---- layer 2: hh = A_hat xh (64-wide); xh = relu(hh W2 + b2) ----
    k_agg64<false><<<agg64Grid, 256>>>(rowptr, epack, xh, dinv2, nullptr, hh, N);
    k_tfgemm<1, __half><<<dim3(F2 / 64, gy), 256>>>(hh, W2, b2, xh, nullptr, N, F1, F2);

    // ---- layer 3: hh = A_hat xh (128-wide); gmax = colmax(relu(hh W3 + b3)) ----
    k_agg128<<<agg128Grid, 256>>>(rowptr, epack, xh, dinv2, hh, N);
    k_tfgemm<2, __half><<<dim3(F3 / 64, gy), 256>>>(hh, W3, b3, nullptr, gmax, N, F2, F3);

    k_head<<<1, 256>>>(gmax, Wl1, bl1, Wl2, bl2, out);
}

// round 12
// speedup vs baseline: 5.8048x; 1.0041x over previous
#include <cuda_runtime.h>
#include <cuda_fp16.h>
#include <stdint.h>
#include <math.h>

#define NN 100000
#define F0 128
#define F1 64
#define F2 128
#define F3 256
#define MAXF 256
#define MAXE 1600000
#define SCAN_BLK 1024
#define NBLK ((NN + SCAN_BLK - 1) / SCAN_BLK)

// ---------------- scratch (static device globals; no allocation) ----------------
__device__ float  g_deg[NN];
__device__ float  g_dinv[NN];
__device__ float  g_dinv2[NN];
__device__ int    g_cnt[NN];
__device__ int    g_part[NN];
__device__ int    g_bsum[NBLK];
__device__ int    g_rowptr[NN + 1];
__device__ int    g_cursor[NN];
__device__ int2   g_epack[MAXE];            // {src, float_bits(norm)} dst-sorted
__device__ int    g_is32;
__device__ __half g_hh[(size_t)NN * MAXF];  // half feature buffer A
__device__ __half g_xh[(size_t)NN * MAXF];  // half feature buffer B
__device__ float  g_gmax[F3];

// ---------------- init + dtype detect (fused) ----------------
__global__ void k_init_detect(float* deg, int* cnt, int n, int* flag, float* gmax,
                              const long long* __restrict__ ei64, int ndet) {
    int i = blockIdx.x * blockDim.x + threadIdx.x;
    if (i == 0) *flag = 0;
    if (i < n) { deg[i] = 1.0f; cnt[i] = 0; }
    if (i < F3) gmax[i] = 0.0f;
    if (i < ndet) {
        long long v = ei64[i];
        if (v < 0 || v >= (long long)n) atomicOr(flag, 1);
    }
}

__global__ void k_hist(const void* __restrict__ ei, int e,
                       const int* __restrict__ flag, const float* __restrict__ ew,
                       int* __restrict__ cnt, float* __restrict__ deg) {
    int i = blockIdx.x * blockDim.x + threadIdx.x;
    if (i >= e) return;
    int d;
    if (*flag) d = ((const int*)ei)[e + i];
    else       d = (int)((const long long*)ei)[e + i];
    atomicAdd(&cnt[d], 1);
    atomicAdd(&deg[d], ew[i]);
}

// ---------------- scan stage 1: per-1024-block partial scan ----------------
__global__ __launch_bounds__(256) void k_scan1(const int* __restrict__ in,
                                               int* __restrict__ out,
                                               int* __restrict__ bsum, int n) {
    __shared__ int ts[256];
    int t = threadIdx.x;
    int base = blockIdx.x * SCAN_BLK + t * 4;
    int v0 = 0, v1 = 0, v2 = 0, v3 = 0;
    if (base + 0 < n) v0 = in[base + 0];
    if (base + 1 < n) v1 = in[base + 1];
    if (base + 2 < n) v2 = in[base + 2];
    if (base + 3 < n) v3 = in[base + 3];
    int tsum = v0 + v1 + v2 + v3;
    ts[t] = tsum;
    __syncthreads();
    for (int off = 1; off < 256; off <<= 1) {
        int x = (t >= off) ? ts[t - off] : 0;
        __syncthreads();
        ts[t] += x;
        __syncthreads();
    }
    int excl = ts[t] - tsum;
    if (t == 255) bsum[blockIdx.x] = ts[255];
    if (base + 0 < n) out[base + 0] = excl;
    if (base + 1 < n) out[base + 1] = excl + v0;
    if (base + 2 < n) out[base + 2] = excl + v0 + v1;
    if (base + 3 < n) out[base + 3] = excl + v0 + v1 + v2;
}

// ---------------- scan stage 2+3 fused: each block scans the <=128 block sums
// redundantly in smem, then emits rowptr/cursor and dinv/dinv2 ----------------
__global__ __launch_bounds__(256) void k_scan3f(
    int* __restrict__ rowptr, int* __restrict__ cursor,
    const int* __restrict__ part, const int* __restrict__ bsum, int nb,
    const float* __restrict__ deg,
    float* __restrict__ dinv, float* __restrict__ dinv2,
    int n, int e) {
    __shared__ int s[128];
    __shared__ int ex[128];
    int t = threadIdx.x;
    int v = 0;
    if (t < 128) {
        v = (t < nb) ? bsum[t] : 0;
        s[t] = v;
    }
    __syncthreads();
    for (int off = 1; off < 128; off <<= 1) {
        int x = 0;
        if (t < 128 && t >= off) x = s[t - off];
        __syncthreads();
        if (t < 128) s[t] += x;
        __syncthreads();
    }
    if (t < 128) ex[t] = s[t] - v;   // exclusive prefix of block sums
    __syncthreads();

    int i = blockIdx.x * blockDim.x + t;
    if (i < n) {
        int r = part[i] + ex[i / SCAN_BLK];
        rowptr[i] = r;
        cursor[i] = r;
        float d = deg[i];
        dinv[i] = rsqrtf(d);
        dinv2[i] = 1.0f / d;
    }
    if (i == 0) rowptr[n] = e;
}

__global__ void k_sort(const void* __restrict__ ei, int e,
                       const int* __restrict__ flag,
                       const float* __restrict__ ew, const float* __restrict__ dinv,
                       int* __restrict__ cursor, int2* __restrict__ epack) {
    int i = blockIdx.x * blockDim.x + threadIdx.x;
    if (i >= e) return;
    int s, d;
    if (*flag) {
        const int* p = (const int*)ei;
        s = p[i]; d = p[e + i];
    } else {
        const long long* p = (const long long*)ei;
        s = (int)p[i]; d = (int)p[e + i];
    }
    int pos = atomicAdd(&cursor[d], 1);
    epack[pos] = make_int2(s, __float_as_int(dinv[s] * ew[i] * dinv[d]));
}

// ---------------- tf32 tensor-core GEMM: 128x64 tile, BK=16, 8 warps ----------------
__device__ __forceinline__ uint32_t f2tf(float f) {
    uint32_t u;
    asm("cvt.rna.tf32.f32 %0, %1;" : "=r"(u) : "f"(f));
    return u;
}

__device__ __forceinline__ void load_a8(const float* Ap, bool aok, uint32_t* t8) {
    float4 a0 = make_float4(0.f, 0.f, 0.f, 0.f), a1 = a0;
    if (aok) { a0 = *(const float4*)Ap; a1 = *(const float4*)(Ap + 4); }
    t8[0] = f2tf(a0.x); t8[1] = f2tf(a0.y); t8[2] = f2tf(a0.z); t8[3] = f2tf(a0.w);
    t8[4] = f2tf(a1.x); t8[5] = f2tf(a1.y); t8[6] = f2tf(a1.z); t8[7] = f2tf(a1.w);
}

__device__ __forceinline__ void load_a8(const __half* Ap, bool aok, uint32_t* t8) {
    uint4 raw = make_uint4(0u, 0u, 0u, 0u);
    if (aok) raw = *(const uint4*)Ap;
    const __half2* h = (const __half2*)&raw;
#pragma unroll
    for (int j = 0; j < 4; j++) {
        float2 f = __half22float2(h[j]);
        t8[2 * j + 0] = f2tf(f.x);
        t8[2 * j + 1] = f2tf(f.y);
    }
}

template <int EPI, typename TA>
__global__ __launch_bounds__(256) void k_tfgemm(
    const TA* __restrict__ A, const float* __restrict__ B,
    const float* __restrict__ bias, __half* __restrict__ Out,
    float* __restrict__ gmax, int M, int K, int N) {
    __shared__ uint32_t As[2][128][20];
    __shared__ uint32_t Bs[2][16][72];

    int tid = threadIdx.x;
    int lane = tid & 31, wid = tid >> 5;
    int warpM = wid & 3, warpN = wid >> 2;
    int bm = blockIdx.y * 128, bn = blockIdx.x * 64;

    int lr = tid >> 1;
    int lc = (tid & 1) << 3;
    int brr = tid >> 4;
    int bcc = (tid & 15) << 2;

    const TA* Ap = A + (size_t)(bm + lr) * K + lc;
    bool aok = (bm + lr) < M;
    const float* Bp = B + (size_t)brr * N + bn + bcc;

    float d[2][4][4];
#pragma unroll
    for (int mt = 0; mt < 2; mt++)
#pragma unroll
        for (int nt = 0; nt < 4; nt++)
#pragma unroll
            for (int j = 0; j < 4; j++) d[mt][nt][j] = 0.0f;

    int T = K >> 4;
    uint32_t a8[8];
    float4 bx;

    load_a8(Ap, aok, a8);
    bx = *(const float4*)Bp;
#pragma unroll
    for (int j = 0; j < 8; j++) As[0][lr][lc + j] = a8[j];
    Bs[0][brr][bcc + 0] = f2tf(bx.x); Bs[0][brr][bcc + 1] = f2tf(bx.y);
    Bs[0][brr][bcc + 2] = f2tf(bx.z); Bs[0][brr][bcc + 3] = f2tf(bx.w);
    __syncthreads();

    for (int t = 0; t < T; t++) {
        int buf = t & 1;
        if (t + 1 < T) {
            load_a8(Ap + (t + 1) * 16, aok, a8);
            bx = *(const float4*)(Bp + (size_t)(t + 1) * 16 * N);
        }
#pragma unroll
        for (int kk = 0; kk < 2; kk++) {
            int k0 = kk * 8 + (lane & 3);
            uint32_t a[2][4], b[4][2];
#pragma unroll
            for (int mt = 0; mt < 2; mt++) {
                int r = warpM * 32 + mt * 16 + (lane >> 2);
                a[mt][0] = As[buf][r][k0];
                a[mt][1] = As[buf][r + 8][k0];
                a[mt][2] = As[buf][r][k0 + 4];
                a[mt][3] = As[buf][r + 8][k0 + 4];
            }
#pragma unroll
            for (int nt = 0; nt < 4; nt++) {
                int c = warpN * 32 + nt * 8 + (lane >> 2);
                b[nt][0] = Bs[buf][k0][c];
                b[nt][1] = Bs[buf][k0 + 4][c];
            }
#pragma unroll
            for (int mt = 0; mt < 2; mt++)
#pragma unroll
                for (int nt = 0; nt < 4; nt++) {
                    asm volatile(
                        "mma.sync.aligned.m16n8k8.row.col.f32.tf32.tf32.f32 "
                        "{%0,%1,%2,%3}, {%4,%5,%6,%7}, {%8,%9}, {%0,%1,%2,%3};"
                        : "+f"(d[mt][nt][0]), "+f"(d[mt][nt][1]),
                          "+f"(d[mt][nt][2]), "+f"(d[mt][nt][3])
                        : "r"(a[mt][0]), "r"(a[mt][1]), "r"(a[mt][2]), "r"(a[mt][3]),
                          "r"(b[nt][0]), "r"(b[nt][1]));
                }
        }
        if (t + 1 < T) {
            int nb2 = buf ^ 1;
#pragma unroll
            for (int j = 0; j < 8; j++) As[nb2][lr][lc + j] = a8[j];
            Bs[nb2][brr][bcc + 0] = f2tf(bx.x); Bs[nb2][brr][bcc + 1] = f2tf(bx.y);
            Bs[nb2][brr][bcc + 2] = f2tf(bx.z); Bs[nb2][brr][bcc + 3] = f2tf(bx.w);
        }
        __syncthreads();
    }

    if (EPI == 2) {
        __shared__ float sgm[64];
        if (tid < 64) sgm[tid] = 0.0f;
        __syncthreads();
#pragma unroll
        for (int mt = 0; mt < 2; mt++)
#pragma unroll
            for (int nt = 0; nt < 4; nt++) {
                int c = warpN * 32 + nt * 8 + 2 * (lane & 3);
                int r = bm + warpM * 32 + mt * 16 + (lane >> 2);
                float bv0 = bias[bn + c], bv1 = bias[bn + c + 1];
                float m0 = 0.0f, m1 = 0.0f;
                if (r < M) {
                    m0 = fmaxf(d[mt][nt][0] + bv0, 0.0f);
                    m1 = fmaxf(d[mt][nt][1] + bv1, 0.0f);
                }
                if (r + 8 < M) {
                    m0 = fmaxf(m0, fmaxf(d[mt][nt][2] + bv0, 0.0f));
                    m1 = fmaxf(m1, fmaxf(d[mt][nt][3] + bv1, 0.0f));
                }
                atomicMax((int*)&sgm[c], __float_as_int(m0));
                atomicMax((int*)&sgm[c + 1], __float_as_int(m1));
            }
        __syncthreads();
        if (tid < 64) atomicMax((int*)&gmax[bn + tid], __float_as_int(sgm[tid]));
    } else {
#pragma unroll
        for (int mt = 0; mt < 2; mt++)
#pragma unroll
            for (int nt = 0; nt < 4; nt++) {
                int c = warpN * 32 + nt * 8 + 2 * (lane & 3);
                int r = bm + warpM * 32 + mt * 16 + (lane >> 2);
                float bv0 = 0.0f, bv1 = 0.0f;
                if (EPI == 1) { bv0 = bias[bn + c]; bv1 = bias[bn + c + 1]; }
                if (r < M) {
                    float v0 = d[mt][nt][0], v1 = d[mt][nt][1];
                    if (EPI == 1) { v0 = fmaxf(v0 + bv0, 0.0f); v1 = fmaxf(v1 + bv1, 0.0f); }
                    *(__half2*)(Out + (size_t)r * N + bn + c) = __floats2half2_rn(v0, v1);
                }
                if (r + 8 < M) {
                    float v2 = d[mt][nt][2], v3 = d[mt][nt][3];
                    if (EPI == 1) { v2 = fmaxf(v2 + bv0, 0.0f); v3 = fmaxf(v3 + bv1, 0.0f); }
                    *(__half2*)(Out + (size_t)(r + 8) * N + bn + c) = __floats2half2_rn(v2, v3);
                }
            }
    }
}

// ---------------- CSR aggregation, F=64: QUARTER-WARP per node, uint4 (8 halves)/lane ----------------
template <bool REL>
__global__ __launch_bounds__(256) void k_agg64(
    const int* __restrict__ rowptr, const int2* __restrict__ ep,
    const __half* __restrict__ H, const float* __restrict__ dinv2,
    const float* __restrict__ bias, __half* __restrict__ out, int n) {
    int qw = (int)((blockIdx.x * blockDim.x + threadIdx.x) >> 3);  // quarter-warp id = node
    int li = threadIdx.x & 7;
    if (qw >= n) return;

    const uint4* Hv = (const uint4*)H;   // 8 uint4 per 64-half row
    float a0, a1, a2, a3, a4, a5, a6, a7;
    {
        uint4 r = Hv[(size_t)qw * 8 + li];
        float2 f0 = __half22float2(*(__half2*)&r.x);
        float2 f1 = __half22float2(*(__half2*)&r.y);
        float2 f2 = __half22float2(*(__half2*)&r.z);
        float2 f3 = __half22float2(*(__half2*)&r.w);
        float d2 = dinv2[qw];
        a0 = f0.x * d2; a1 = f0.y * d2; a2 = f1.x * d2; a3 = f1.y * d2;
        a4 = f2.x * d2; a5 = f2.y * d2; a6 = f3.x * d2; a7 = f3.y * d2;
    }
    int e = rowptr[qw], r1 = rowptr[qw + 1];
    for (; e + 3 < r1; e += 4) {
        int2 e0 = ep[e], e1 = ep[e + 1], e2 = ep[e + 2], e3 = ep[e + 3];
        float n0 = __int_as_float(e0.y), n1 = __int_as_float(e1.y);
        float n2 = __int_as_float(e2.y), n3 = __int_as_float(e3.y);
        uint4 r0 = Hv[(size_t)e0.x * 8 + li];
        uint4 r1v = Hv[(size_t)e1.x * 8 + li];
        uint4 r2 = Hv[(size_t)e2.x * 8 + li];
        uint4 r3 = Hv[(size_t)e3.x * 8 + li];
        float2 p0 = __half22float2(*(__half2*)&r0.x), p1 = __half22float2(*(__half2*)&r0.y);
        float2 p2 = __half22float2(*(__half2*)&r0.z), p3 = __half22float2(*(__half2*)&r0.w);
        float2 q0 = __half22float2(*(__half2*)&r1v.x), q1 = __half22float2(*(__half2*)&r1v.y);
        float2 q2 = __half22float2(*(__half2*)&r1v.z), q3 = __half22float2(*(__half2*)&r1v.w);
        float2 s0 = __half22float2(*(__half2*)&r2.x), s1 = __half22float2(*(__half2*)&r2.y);
        float2 s2 = __half22float2(*(__half2*)&r2.z), s3 = __half22float2(*(__half2*)&r2.w);
        float2 t0 = __half22float2(*(__half2*)&r3.x), t1 = __half22float2(*(__half2*)&r3.y);
        float2 t2 = __half22float2(*(__half2*)&r3.z), t3 = __half22float2(*(__half2*)&r3.w);
        a0 += p0.x * n0 + q0.x * n1 + s0.x * n2 + t0.x * n3;
        a1 += p0.y * n0 + q0.y * n1 + s0.y * n2 + t0.y * n3;
        a2 += p1.x * n0 + q1.x * n1 + s1.x * n2 + t1.x * n3;
        a3 += p1.y * n0 + q1.y * n1 + s1.y * n2 + t1.y * n3;
        a4 += p2.x * n0 + q2.x * n1 + s2.x * n2 + t2.x * n3;
        a5 += p2.y * n0 + q2.y * n1 + s2.y * n2 + t2.y * n3;
        a6 += p3.x * n0 + q3.x * n1 + s3.x * n2 + t3.x * n3;
        a7 += p3.y * n0 + q3.y * n1 + s3.y * n2 + t3.y * n3;
    }
    for (; e < r1; e++) {
        int2 e0 = ep[e];
        float n0 = __int_as_float(e0.y);
        uint4 r0 = Hv[(size_t)e0.x * 8 + li];
        float2 p0 = __half22float2(*(__half2*)&r0.x), p1 = __half22float2(*(__half2*)&r0.y);
        float2 p2 = __half22float2(*(__half2*)&r0.z), p3 = __half22float2(*(__half2*)&r0.w);
        a0 += p0.x * n0; a1 += p0.y * n0; a2 += p1.x * n0; a3 += p1.y * n0;
        a4 += p2.x * n0; a5 += p2.y * n0; a6 += p3.x * n0; a7 += p3.y * n0;
    }
    if (REL) {
        float4 bv0 = ((const float4*)bias)[2 * li];
        float4 bv1 = ((const float4*)bias)[2 * li + 1];
        a0 = fmaxf(a0 + bv0.x, 0.0f); a1 = fmaxf(a1 + bv0.y, 0.0f);
        a2 = fmaxf(a2 + bv0.z, 0.0f); a3 = fmaxf(a3 + bv0.w, 0.0f);
        a4 = fmaxf(a4 + bv1.x, 0.0f); a5 = fmaxf(a5 + bv1.y, 0.0f);
        a6 = fmaxf(a6 + bv1.z, 0.0f); a7 = fmaxf(a7 + bv1.w, 0.0f);
    }
    uint4 o;
    *(__half2*)&o.x = __floats2half2_rn(a0, a1);
    *(__half2*)&o.y = __floats2half2_rn(a2, a3);
    *(__half2*)&o.z = __floats2half2_rn(a4, a5);
    *(__half2*)&o.w = __floats2half2_rn(a6, a7);
    ((uint4*)out)[(size_t)qw * 8 + li] = o;
}

// ---------------- CSR aggregation, F=128: HALF-WARP per node, uint4/lane, unroll x4 ----------------
__global__ __launch_bounds__(256) void k_agg128(
    const int* __restrict__ rowptr, const int2* __restrict__ ep,
    const __half* __restrict__ H, const float* __restrict__ dinv2,
    __half* __restrict__ out, int n) {
    int hw = (int)((blockIdx.x * blockDim.x + threadIdx.x) >> 4);
    int li = threadIdx.x & 15;
    if (hw >= n) return;

    const uint4* Hv = (const uint4*)H;   // 16 uint4 per 128-half row
    float a0, a1, a2, a3, a4, a5, a6, a7;
    {
        uint4 r = Hv[(size_t)hw * 16 + li];
        float2 f0 = __half22float2(*(__half2*)&r.x);
        float2 f1 = __half22float2(*(__half2*)&r.y);
        float2 f2 = __half22float2(*(__half2*)&r.z);
        float2 f3 = __half22float2(*(__half2*)&r.w);
        float d2 = dinv2[hw];
        a0 = f0.x * d2; a1 = f0.y * d2; a2 = f1.x * d2; a3 = f1.y * d2;
        a4 = f2.x * d2; a5 = f2.y * d2; a6 = f3.x * d2; a7 = f3.y * d2;
    }
    int e = rowptr[hw], r1 = rowptr[hw + 1];
    for (; e + 3 < r1; e += 4) {
        int2 e0 = ep[e], e1 = ep[e + 1], e2 = ep[e + 2], e3 = ep[e + 3];
        float n0 = __int_as_float(e0.y), n1 = __int_as_float(e1.y);
        float n2 = __int_as_float(e2.y), n3 = __int_as_float(e3.y);
        uint4 r0 = Hv[(size_t)e0.x * 16 + li];
        uint4 r1v = Hv[(size_t)e1.x * 16 + li];
        uint4 r2 = Hv[(size_t)e2.x * 16 + li];
        uint4 r3 = Hv[(size_t)e3.x * 16 + li];
        float2 p0 = __half22float2(*(__half2*)&r0.x), p1 = __half22float2(*(__half2*)&r0.y);
        float2 p2 = __half22float2(*(__half2*)&r0.z), p3 = __half22float2(*(__half2*)&r0.w);
        float2 q0 = __half22float2(*(__half2*)&r1v.x), q1 = __half22float2(*(__half2*)&r1v.y);
        float2 q2 = __half22float2(*(__half2*)&r1v.z), q3 = __half22float2(*(__half2*)&r1v.w);
        float2 s0 = __half22float2(*(__half2*)&r2.x), s1 = __half22float2(*(__half2*)&r2.y);
        float2 s2 = __half22float2(*(__half2*)&r2.z), s3 = __half22float2(*(__half2*)&r2.w);
        float2 t0 = __half22float2(*(__half2*)&r3.x), t1 = __half22float2(*(__half2*)&r3.y);
        float2 t2 = __half22float2(*(__half2*)&r3.z), t3 = __half22float2(*(__half2*)&r3.w);
        a0 += p0.x * n0 + q0.x * n1 + s0.x * n2 + t0.x * n3;
        a1 += p0.y * n0 + q0.y * n1 + s0.y * n2 + t0.y * n3;
        a2 += p1.x * n0 + q1.x * n1 + s1.x * n2 + t1.x * n3;
        a3 += p1.y * n0 + q1.y * n1 + s1.y * n2 + t1.y * n3;
        a4 += p2.x * n0 + q2.x * n1 + s2.x * n2 + t2.x * n3;
        a5 += p2.y * n0 + q2.y * n1 + s2.y * n2 + t2.y * n3;
        a6 += p3.x * n0 + q3.x * n1 + s3.x * n2 + t3.x * n3;
        a7 += p3.y * n0 + q3.y * n1 + s3.y * n2 + t3.y * n3;
    }
    for (; e < r1; e++) {
        int2 e0 = ep[e];
        float n0 = __int_as_float(e0.y);
        uint4 r0 = Hv[(size_t)e0.x * 16 + li];
        float2 p0 = __half22float2(*(__half2*)&r0.x), p1 = __half22float2(*(__half2*)&r0.y);
        float2 p2 = __half22float2(*(__half2*)&r0.z), p3 = __half22float2(*(__half2*)&r0.w);
        a0 += p0.x * n0; a1 += p0.y * n0; a2 += p1.x * n0; a3 += p1.y * n0;
        a4 += p2.x * n0; a5 += p2.y * n0; a6 += p3.x * n0; a7 += p3.y * n0;
    }
    uint4 o;
    *(__half2*)&o.x = __floats2half2_rn(a0, a1);
    *(__half2*)&o.y = __floats2half2_rn(a2, a3);
    *(__half2*)&o.z = __floats2half2_rn(a4, a5);
    *(__half2*)&o.w = __floats2half2_rn(a6, a7);
    ((uint4*)out)[(size_t)hw * 16 + li] = o;
}

// ---------------- MLP head + log_softmax ----------------
__global__ void k_head(const float* __restrict__ gmax,
                       const float* __restrict__ Wl1, const float* __restrict__ bl1,
                       const float* __restrict__ Wl2, const float* __restrict__ bl2,
                       float* __restrict__ out) {
    __shared__ float g[256];
    __shared__ float h1[128];
    __shared__ float logits[10];
    int t = threadIdx.x;
    g[t] = gmax[t];
    __syncthreads();
    if (t < 128) {
        float s = bl1[t];
        for (int k = 0; k < 256; k++) s += g[k] * Wl1[k * 128 + t];
        h1[t] = fmaxf(s, 0.0f);
    }
    __syncthreads();
    if (t < 10) {
        float s = bl2[t];
        for (int k = 0; k < 128; k++) s += h1[k] * Wl2[k * 10 + t];
        logits[t] = s;
    }
    __syncthreads();
    if (t == 0) {
        float m = -1e30f;
        for (int c = 0; c < 10; c++) m = fmaxf(m, logits[c]);
        float se = 0.0f;
        for (int c = 0; c < 10; c++) se += expf(logits[c] - m);
        float lse = logf(se);
        for (int c = 0; c < 10; c++) out[c] = logits[c] - m - lse;
    }
}

// ---------------- launch ----------------
extern "C" void kernel_launch(void* const* d_in, const int* in_sizes, int n_in,
                              void* d_out, int out_size) {
    const float* x   = (const float*)d_in[0];
    const void*  ei  = d_in[1];
    const float* ew  = (const float*)d_in[2];
    const float* W1  = (const float*)d_in[3];
    const float* b1  = (const float*)d_in[4];
    const float* W2  = (const float*)d_in[5];
    const float* b2  = (const float*)d_in[6];
    const float* W3  = (const float*)d_in[7];
    const float* b3  = (const float*)d_in[8];
    const float* Wl1 = (const float*)d_in[9];
    const float* bl1 = (const float*)d_in[10];
    const float* Wl2 = (const float*)d_in[11];
    const float* bl2 = (const float*)d_in[12];
    float* out = (float*)d_out;

    int E = in_sizes[2];
    int N = in_sizes[0] / F0;

    float *deg, *dinv, *dinv2, *gmax;
    int *cnt, *part, *bsum, *rowptr, *cursor, *flag;
    int2* epack;
    __half *hh, *xh;
    cudaGetSymbolAddress((void**)&deg,    g_deg);
    cudaGetSymbolAddress((void**)&dinv,   g_dinv);
    cudaGetSymbolAddress((void**)&dinv2,  g_dinv2);
    cudaGetSymbolAddress((void**)&cnt,    g_cnt);
    cudaGetSymbolAddress((void**)&part,   g_part);
    cudaGetSymbolAddress((void**)&bsum,   g_bsum);
    cudaGetSymbolAddress((void**)&rowptr, g_rowptr);
    cudaGetSymbolAddress((void**)&cursor, g_cursor);
    cudaGetSymbolAddress((void**)&epack,  g_epack);
    cudaGetSymbolAddress((void**)&flag,   g_is32);
    cudaGetSymbolAddress((void**)&hh,     g_hh);
    cudaGetSymbolAddress((void**)&xh,     g_xh);
    cudaGetSymbolAddress((void**)&gmax,   g_gmax);

    int agg64Grid = (N + 31) / 32;
    int agg128Grid = (N + 15) / 16;
    int gy = (N + 127) / 128;
    int nb = (N + SCAN_BLK - 1) / SCAN_BLK;
    int det = E < 65536 ? E : 65536;

    // Fork/join events (created+destroyed per call; net device-mem delta 0)
    cudaEvent_t evFork, evJoin;
    cudaEventCreateWithFlags(&evFork, cudaEventDisableTiming);
    cudaEventCreateWithFlags(&evJoin, cudaEventDisableTiming);

    // ---- fork: layer-1 GEMM (x W1) has no preprocessing dependencies ----
    cudaEventRecord(evFork, 0);
    cudaStreamWaitEvent(cudaStreamPerThread, evFork, 0);
    k_tfgemm<0, float><<<dim3(F1 / 64, gy), 256, 0, cudaStreamPerThread>>>(
        x, W1, nullptr, hh, nullptr, N, F0, F1);
    cudaEventRecord(evJoin, cudaStreamPerThread);

    // ---- preprocessing chain (default stream, concurrent with GEMM1) ----
    k_init_detect<<<(N + 255) / 256, 256>>>(deg, cnt, N, flag, gmax,
                                            (const long long*)ei, det);
    k_hist<<<(E + 255) / 256, 256>>>(ei, E, flag, ew, cnt, deg);
    k_scan1<<<nb, 256>>>(cnt, part, bsum, N);
    k_scan3f<<<(N + 255) / 256, 256>>>(rowptr, cursor, part, bsum, nb,
                                       deg, dinv, dinv2, N, E);
    k_sort<<<(E + 255) / 256, 256>>>(ei, E, flag, ew, dinv, cursor, epack);

    // ---- join: agg needs both CSR and GEMM1 output ----
    cudaStreamWaitEvent(0, evJoin, 0);

    // ---- layer 1 agg: xh = relu(A_hat hh + b1) ----
    k_agg64<true><<<agg64Grid, 256>>>(rowptr, epack, hh, dinv2, b1, xh, N);

    // ---- layer 2: hh = A_hat xh (64-wide); xh = relu(hh W2 + b2) ----
    k_agg64<false><<<agg64Grid, 256>>>(rowptr, epack, xh, dinv2, nullptr, hh, N);
    k_tfgemm<1, __half><<<dim3(F2 / 64, gy), 256>>>(hh, W2, b2, xh, nullptr, N, F1, F2);

    // ---- layer 3: hh = A_hat xh (128-wide); gmax = colmax(relu(hh W3 + b3)) ----
    k_agg128<<<agg128Grid, 256>>>(rowptr, epack, xh, dinv2, hh, N);
    k_tfgemm<2, __half><<<dim3(F3 / 64, gy), 256>>>(hh, W3, b3, nullptr, gmax, N, F2, F3);

    k_head<<<1, 256>>>(gmax, Wl1, bl1, Wl2, bl2, out);

    cudaEventDestroy(evFork);
    cudaEventDestroy(evJoin);
}

// round 13
// speedup vs baseline: 6.0443x; 1.0413x over previous
#include <cuda_runtime.h>
#include <cuda_fp16.h>
#include <stdint.h>
#include <math.h>

#define NN 100000
#define F0 128
#define F1 64
#define F2 128
#define F3 256
#define MAXF 256
#define MAXE 1600000
#define SCAN_BLK 1024
#define NBLK ((NN + SCAN_BLK - 1) / SCAN_BLK)

// deg fixed-point: bits [0:44) = deg * 2^20 ; bits [44:64) = edge count
#define DEG_SHIFT 20
#define CNT_SHIFT 44
#define DEG_MASK ((1ULL << CNT_SHIFT) - 1ULL)

// ---------------- scratch (static device globals; no allocation) ----------------
__device__ unsigned long long g_pk[NN];     // packed {count, deg_fixed}
__device__ float  g_dinv[NN];
__device__ float  g_dinv2[NN];
__device__ int    g_part[NN];
__device__ int    g_bsum[NBLK];
__device__ int    g_rowptr[NN + 1];
__device__ int    g_cursor[NN];
__device__ int2   g_epack[MAXE];            // {src, float_bits(norm)} dst-sorted
__device__ int    g_is32;
__device__ __half g_hh[(size_t)NN * MAXF];  // half feature buffer A
__device__ __half g_xh[(size_t)NN * MAXF];  // half feature buffer B
__device__ float  g_gmax[F3];

// ---------------- init + dtype detect (fused) ----------------
__global__ void k_init_detect(unsigned long long* pk, int n, int* flag, float* gmax,
                              const long long* __restrict__ ei64, int ndet) {
    int i = blockIdx.x * blockDim.x + threadIdx.x;
    if (i == 0) *flag = 0;
    if (i < n) pk[i] = (1ULL << DEG_SHIFT);  // deg starts at self-loop weight 1.0
    if (i < F3) gmax[i] = 0.0f;
    if (i < ndet) {
        long long v = ei64[i];
        if (v < 0 || v >= (long long)n) atomicOr(flag, 1);
    }
}

// one 64-bit atomic per edge: count++ and deg += ew (fixed point)
__global__ void k_hist(const void* __restrict__ ei, int e,
                       const int* __restrict__ flag, const float* __restrict__ ew,
                       unsigned long long* __restrict__ pk) {
    int i = blockIdx.x * blockDim.x + threadIdx.x;
    if (i >= e) return;
    int d;
    if (*flag) d = ((const int*)ei)[e + i];
    else       d = (int)((const long long*)ei)[e + i];
    unsigned long long degq =
        (unsigned long long)(ew[i] * (float)(1 << DEG_SHIFT) + 0.5f);
    atomicAdd(&pk[d], (1ULL << CNT_SHIFT) | degq);
}

// ---------------- scan stage 1: per-1024-block partial scan of counts ----------------
__global__ __launch_bounds__(256) void k_scan1(const unsigned long long* __restrict__ pk,
                                               int* __restrict__ out,
                                               int* __restrict__ bsum, int n) {
    __shared__ int ts[256];
    int t = threadIdx.x;
    int base = blockIdx.x * SCAN_BLK + t * 4;
    int v0 = 0, v1 = 0, v2 = 0, v3 = 0;
    if (base + 0 < n) v0 = (int)(pk[base + 0] >> CNT_SHIFT);
    if (base + 1 < n) v1 = (int)(pk[base + 1] >> CNT_SHIFT);
    if (base + 2 < n) v2 = (int)(pk[base + 2] >> CNT_SHIFT);
    if (base + 3 < n) v3 = (int)(pk[base + 3] >> CNT_SHIFT);
    int tsum = v0 + v1 + v2 + v3;
    ts[t] = tsum;
    __syncthreads();
    for (int off = 1; off < 256; off <<= 1) {
        int x = (t >= off) ? ts[t - off] : 0;
        __syncthreads();
        ts[t] += x;
        __syncthreads();
    }
    int excl = ts[t] - tsum;
    if (t == 255) bsum[blockIdx.x] = ts[255];
    if (base + 0 < n) out[base + 0] = excl;
    if (base + 1 < n) out[base + 1] = excl + v0;
    if (base + 2 < n) out[base + 2] = excl + v0 + v1;
    if (base + 3 < n) out[base + 3] = excl + v0 + v1 + v2;
}

// ---------------- scan stage 2+3 fused + dinv from packed deg ----------------
__global__ __launch_bounds__(256) void k_scan3f(
    int* __restrict__ rowptr, int* __restrict__ cursor,
    const int* __restrict__ part, const int* __restrict__ bsum, int nb,
    const unsigned long long* __restrict__ pk,
    float* __restrict__ dinv, float* __restrict__ dinv2,
    int n, int e) {
    __shared__ int s[128];
    __shared__ int ex[128];
    int t = threadIdx.x;
    int v = 0;
    if (t < 128) {
        v = (t < nb) ? bsum[t] : 0;
        s[t] = v;
    }
    __syncthreads();
    for (int off = 1; off < 128; off <<= 1) {
        int x = 0;
        if (t < 128 && t >= off) x = s[t - off];
        __syncthreads();
        if (t < 128) s[t] += x;
        __syncthreads();
    }
    if (t < 128) ex[t] = s[t] - v;
    __syncthreads();

    int i = blockIdx.x * blockDim.x + t;
    if (i < n) {
        int r = part[i] + ex[i / SCAN_BLK];
        rowptr[i] = r;
        cursor[i] = r;
        float d = (float)(pk[i] & DEG_MASK) * (1.0f / (float)(1 << DEG_SHIFT));
        dinv[i] = rsqrtf(d);
        dinv2[i] = 1.0f / d;
    }
    if (i == 0) rowptr[n] = e;
}

__global__ void k_sort(const void* __restrict__ ei, int e,
                       const int* __restrict__ flag,
                       const float* __restrict__ ew, const float* __restrict__ dinv,
                       int* __restrict__ cursor, int2* __restrict__ epack) {
    int i = blockIdx.x * blockDim.x + threadIdx.x;
    if (i >= e) return;
    int s, d;
    if (*flag) {
        const int* p = (const int*)ei;
        s = p[i]; d = p[e + i];
    } else {
        const long long* p = (const long long*)ei;
        s = (int)p[i]; d = (int)p[e + i];
    }
    int pos = atomicAdd(&cursor[d], 1);
    epack[pos] = make_int2(s, __float_as_int(dinv[s] * ew[i] * dinv[d]));
}

// ---------------- tf32 tensor-core GEMM: 128x64 tile, BK=16, 8 warps ----------------
__device__ __forceinline__ uint32_t f2tf(float f) {
    uint32_t u;
    asm("cvt.rna.tf32.f32 %0, %1;" : "=r"(u) : "f"(f));
    return u;
}

__device__ __forceinline__ void load_a8(const float* Ap, bool aok, uint32_t* t8) {
    float4 a0 = make_float4(0.f, 0.f, 0.f, 0.f), a1 = a0;
    if (aok) { a0 = *(const float4*)Ap; a1 = *(const float4*)(Ap + 4); }
    t8[0] = f2tf(a0.x); t8[1] = f2tf(a0.y); t8[2] = f2tf(a0.z); t8[3] = f2tf(a0.w);
    t8[4] = f2tf(a1.x); t8[5] = f2tf(a1.y); t8[6] = f2tf(a1.z); t8[7] = f2tf(a1.w);
}

__device__ __forceinline__ void load_a8(const __half* Ap, bool aok, uint32_t* t8) {
    uint4 raw = make_uint4(0u, 0u, 0u, 0u);
    if (aok) raw = *(const uint4*)Ap;
    const __half2* h = (const __half2*)&raw;
#pragma unroll
    for (int j = 0; j < 4; j++) {
        float2 f = __half22float2(h[j]);
        t8[2 * j + 0] = f2tf(f.x);
        t8[2 * j + 1] = f2tf(f.y);
    }
}

template <int EPI, typename TA>
__global__ __launch_bounds__(256) void k_tfgemm(
    const TA* __restrict__ A, const float* __restrict__ B,
    const float* __restrict__ bias, __half* __restrict__ Out,
    float* __restrict__ gmax, int M, int K, int N) {
    __shared__ uint32_t As[2][128][20];
    __shared__ uint32_t Bs[2][16][72];

    int tid = threadIdx.x;
    int lane = tid & 31, wid = tid >> 5;
    int warpM = wid & 3, warpN = wid >> 2;
    int bm = blockIdx.y * 128, bn = blockIdx.x * 64;

    int lr = tid >> 1;
    int lc = (tid & 1) << 3;
    int brr = tid >> 4;
    int bcc = (tid & 15) << 2;

    const TA* Ap = A + (size_t)(bm + lr) * K + lc;
    bool aok = (bm + lr) < M;
    const float* Bp = B + (size_t)brr * N + bn + bcc;

    float d[2][4][4];
#pragma unroll
    for (int mt = 0; mt < 2; mt++)
#pragma unroll
        for (int nt = 0; nt < 4; nt++)
#pragma unroll
            for (int j = 0; j < 4; j++) d[mt][nt][j] = 0.0f;

    int T = K >> 4;
    uint32_t a8[8];
    float4 bx;

    load_a8(Ap, aok, a8);
    bx = *(const float4*)Bp;
#pragma unroll
    for (int j = 0; j < 8; j++) As[0][lr][lc + j] = a8[j];
    Bs[0][brr][bcc + 0] = f2tf(bx.x); Bs[0][brr][bcc + 1] = f2tf(bx.y);
    Bs[0][brr][bcc + 2] = f2tf(bx.z); Bs[0][brr][bcc + 3] = f2tf(bx.w);
    __syncthreads();

    for (int t = 0; t < T; t++) {
        int buf = t & 1;
        if (t + 1 < T) {
            load_a8(Ap + (t + 1) * 16, aok, a8);
            bx = *(const float4*)(Bp + (size_t)(t + 1) * 16 * N);
        }
#pragma unroll
        for (int kk = 0; kk < 2; kk++) {
            int k0 = kk * 8 + (lane & 3);
            uint32_t a[2][4], b[4][2];
#pragma unroll
            for (int mt = 0; mt < 2; mt++) {
                int r = warpM * 32 + mt * 16 + (lane >> 2);
                a[mt][0] = As[buf][r][k0];
                a[mt][1] = As[buf][r + 8][k0];
                a[mt][2] = As[buf][r][k0 + 4];
                a[mt][3] = As[buf][r + 8][k0 + 4];
            }
#pragma unroll
            for (int nt = 0; nt < 4; nt++) {
                int c = warpN * 32 + nt * 8 + (lane >> 2);
                b[nt][0] = Bs[buf][k0][c];
                b[nt][1] = Bs[buf][k0 + 4][c];
            }
#pragma unroll
            for (int mt = 0; mt < 2; mt++)
#pragma unroll
                for (int nt = 0; nt < 4; nt++) {
                    asm volatile(
                        "mma.sync.aligned.m16n8k8.row.col.f32.tf32.tf32.f32 "
                        "{%0,%1,%2,%3}, {%4,%5,%6,%7}, {%8,%9}, {%0,%1,%2,%3};"
                        : "+f"(d[mt][nt][0]), "+f"(d[mt][nt][1]),
                          "+f"(d[mt][nt][2]), "+f"(d[mt][nt][3])
                        : "r"(a[mt][0]), "r"(a[mt][1]), "r"(a[mt][2]), "r"(a[mt][3]),
                          "r"(b[nt][0]), "r"(b[nt][1]));
                }
        }
        if (t + 1 < T) {
            int nb2 = buf ^ 1;
#pragma unroll
            for (int j = 0; j < 8; j++) As[nb2][lr][lc + j] = a8[j];
            Bs[nb2][brr][bcc + 0] = f2tf(bx.x); Bs[nb2][brr][bcc + 1] = f2tf(bx.y);
            Bs[nb2][brr][bcc + 2] = f2tf(bx.z); Bs[nb2][brr][bcc + 3] = f2tf(bx.w);
        }
        __syncthreads();
    }

    if (EPI == 2) {
        __shared__ float sgm[64];
        if (tid < 64) sgm[tid] = 0.0f;
        __syncthreads();
#pragma unroll
        for (int mt = 0; mt < 2; mt++)
#pragma unroll
            for (int nt = 0; nt < 4; nt++) {
                int c = warpN * 32 + nt * 8 + 2 * (lane & 3);
                int r = bm + warpM * 32 + mt * 16 + (lane >> 2);
                float bv0 = bias[bn + c], bv1 = bias[bn + c + 1];
                float m0 = 0.0f, m1 = 0.0f;
                if (r < M) {
                    m0 = fmaxf(d[mt][nt][0] + bv0, 0.0f);
                    m1 = fmaxf(d[mt][nt][1] + bv1, 0.0f);
                }
                if (r + 8 < M) {
                    m0 = fmaxf(m0, fmaxf(d[mt][nt][2] + bv0, 0.0f));
                    m1 = fmaxf(m1, fmaxf(d[mt][nt][3] + bv1, 0.0f));
                }
                atomicMax((int*)&sgm[c], __float_as_int(m0));
                atomicMax((int*)&sgm[c + 1], __float_as_int(m1));
            }
        __syncthreads();
        if (tid < 64) atomicMax((int*)&gmax[bn + tid], __float_as_int(sgm[tid]));
    } else {
#pragma unroll
        for (int mt = 0; mt < 2; mt++)
#pragma unroll
            for (int nt = 0; nt < 4; nt++) {
                int c = warpN * 32 + nt * 8 + 2 * (lane & 3);
                int r = bm + warpM * 32 + mt * 16 + (lane >> 2);
                float bv0 = 0.0f, bv1 = 0.0f;
                if (EPI == 1) { bv0 = bias[bn + c]; bv1 = bias[bn + c + 1]; }
                if (r < M) {
                    float v0 = d[mt][nt][0], v1 = d[mt][nt][1];
                    if (EPI == 1) { v0 = fmaxf(v0 + bv0, 0.0f); v1 = fmaxf(v1 + bv1, 0.0f); }
                    *(__half2*)(Out + (size_t)r * N + bn + c) = __floats2half2_rn(v0, v1);
                }
                if (r + 8 < M) {
                    float v2 = d[mt][nt][2], v3 = d[mt][nt][3];
                    if (EPI == 1) { v2 = fmaxf(v2 + bv0, 0.0f); v3 = fmaxf(v3 + bv1, 0.0f); }
                    *(__half2*)(Out + (size_t)(r + 8) * N + bn + c) = __floats2half2_rn(v2, v3);
                }
            }
    }
}

// ---------------- CSR aggregation, F=64: QUARTER-WARP per node, L2-only gathers ----------------
template <bool REL>
__global__ __launch_bounds__(256) void k_agg64(
    const int* __restrict__ rowptr, const int2* __restrict__ ep,
    const __half* __restrict__ H, const float* __restrict__ dinv2,
    const float* __restrict__ bias, __half* __restrict__ out, int n) {
    int qw = (int)((blockIdx.x * blockDim.x + threadIdx.x) >> 3);
    int li = threadIdx.x & 7;
    if (qw >= n) return;

    const uint4* Hv = (const uint4*)H;
    float a0, a1, a2, a3, a4, a5, a6, a7;
    {
        uint4 r = __ldcg(&Hv[(size_t)qw * 8 + li]);
        float2 f0 = __half22float2(*(__half2*)&r.x);
        float2 f1 = __half22float2(*(__half2*)&r.y);
        float2 f2 = __half22float2(*(__half2*)&r.z);
        float2 f3 = __half22float2(*(__half2*)&r.w);
        float d2 = dinv2[qw];
        a0 = f0.x * d2; a1 = f0.y * d2; a2 = f1.x * d2; a3 = f1.y * d2;
        a4 = f2.x * d2; a5 = f2.y * d2; a6 = f3.x * d2; a7 = f3.y * d2;
    }
    int e = rowptr[qw], r1 = rowptr[qw + 1];
    for (; e + 3 < r1; e += 4) {
        int2 e0 = __ldcs(&ep[e]), e1 = __ldcs(&ep[e + 1]);
        int2 e2 = __ldcs(&ep[e + 2]), e3 = __ldcs(&ep[e + 3]);
        float n0 = __int_as_float(e0.y), n1 = __int_as_float(e1.y);
        float n2 = __int_as_float(e2.y), n3 = __int_as_float(e3.y);
        uint4 r0 = __ldcg(&Hv[(size_t)e0.x * 8 + li]);
        uint4 r1v = __ldcg(&Hv[(size_t)e1.x * 8 + li]);
        uint4 r2 = __ldcg(&Hv[(size_t)e2.x * 8 + li]);
        uint4 r3 = __ldcg(&Hv[(size_t)e3.x * 8 + li]);
        float2 p0 = __half22float2(*(__half2*)&r0.x), p1 = __half22float2(*(__half2*)&r0.y);
        float2 p2 = __half22float2(*(__half2*)&r0.z), p3 = __half22float2(*(__half2*)&r0.w);
        float2 q0 = __half22float2(*(__half2*)&r1v.x), q1 = __half22float2(*(__half2*)&r1v.y);
        float2 q2 = __half22float2(*(__half2*)&r1v.z), q3 = __half22float2(*(__half2*)&r1v.w);
        float2 s0 = __half22float2(*(__half2*)&r2.x), s1 = __half22float2(*(__half2*)&r2.y);
        float2 s2 = __half22float2(*(__half2*)&r2.z), s3 = __half22float2(*(__half2*)&r2.w);
        float2 t0 = __half22float2(*(__half2*)&r3.x), t1 = __half22float2(*(__half2*)&r3.y);
        float2 t2 = __half22float2(*(__half2*)&r3.z), t3 = __half22float2(*(__half2*)&r3.w);
        a0 += p0.x * n0 + q0.x * n1 + s0.x * n2 + t0.x * n3;
        a1 += p0.y * n0 + q0.y * n1 + s0.y * n2 + t0.y * n3;
        a2 += p1.x * n0 + q1.x * n1 + s1.x * n2 + t1.x * n3;
        a3 += p1.y * n0 + q1.y * n1 + s1.y * n2 + t1.y * n3;
        a4 += p2.x * n0 + q2.x * n1 + s2.x * n2 + t2.x * n3;
        a5 += p2.y * n0 + q2.y * n1 + s2.y * n2 + t2.y * n3;
        a6 += p3.x * n0 + q3.x * n1 + s3.x * n2 + t3.x * n3;
        a7 += p3.y * n0 + q3.y * n1 + s3.y * n2 + t3.y * n3;
    }
    for (; e < r1; e++) {
        int2 e0 = __ldcs(&ep[e]);
        float n0 = __int_as_float(e0.y);
        uint4 r0 = __ldcg(&Hv[(size_t)e0.x * 8 + li]);
        float2 p0 = __half22float2(*(__half2*)&r0.x), p1 = __half22float2(*(__half2*)&r0.y);
        float2 p2 = __half22float2(*(__half2*)&r0.z), p3 = __half22float2(*(__half2*)&r0.w);
        a0 += p0.x * n0; a1 += p0.y * n0; a2 += p1.x * n0; a3 += p1.y * n0;
        a4 += p2.x * n0; a5 += p2.y * n0; a6 += p3.x * n0; a7 += p3.y * n0;
    }
    if (REL) {
        float4 bv0 = ((const float4*)bias)[2 * li];
        float4 bv1 = ((const float4*)bias)[2 * li + 1];
        a0 = fmaxf(a0 + bv0.x, 0.0f); a1 = fmaxf(a1 + bv0.y, 0.0f);
        a2 = fmaxf(a2 + bv0.z, 0.0f); a3 = fmaxf(a3 + bv0.w, 0.0f);
        a4 = fmaxf(a4 + bv1.x, 0.0f); a5 = fmaxf(a5 + bv1.y, 0.0f);
        a6 = fmaxf(a6 + bv1.z, 0.0f); a7 = fmaxf(a7 + bv1.w, 0.0f);
    }
    uint4 o;
    *(__half2*)&o.x = __floats2half2_rn(a0, a1);
    *(__half2*)&o.y = __floats2half2_rn(a2, a3);
    *(__half2*)&o.z = __floats2half2_rn(a4, a5);
    *(__half2*)&o.w = __floats2half2_rn(a6, a7);
    ((uint4*)out)[(size_t)qw * 8 + li] = o;
}

// ---------------- CSR aggregation, F=128: HALF-WARP per node, L2-only gathers ----------------
__global__ __launch_bounds__(256) void k_agg128(
    const int* __restrict__ rowptr, const int2* __restrict__ ep,
    const __half* __restrict__ H, const float* __restrict__ dinv2,
    __half* __restrict__ out, int n) {
    int hw = (int)((blockIdx.x * blockDim.x + threadIdx.x) >> 4);
    int li = threadIdx.x & 15;
    if (hw >= n) return;

    const uint4* Hv = (const uint4*)H;
    float a0, a1, a2, a3, a4, a5, a6, a7;
    {
        uint4 r = __ldcg(&Hv[(size_t)hw * 16 + li]);
        float2 f0 = __half22float2(*(__half2*)&r.x);
        float2 f1 = __half22float2(*(__half2*)&r.y);
        float2 f2 = __half22float2(*(__half2*)&r.z);
        float2 f3 = __half22float2(*(__half2*)&r.w);
        float d2 = dinv2[hw];
        a0 = f0.x * d2; a1 = f0.y * d2; a2 = f1.x * d2; a3 = f1.y * d2;
        a4 = f2.x * d2; a5 = f2.y * d2; a6 = f3.x * d2; a7 = f3.y * d2;
    }
    int e = rowptr[hw], r1 = rowptr[hw + 1];
    for (; e + 3 < r1; e += 4) {
        int2 e0 = __ldcs(&ep[e]), e1 = __ldcs(&ep[e + 1]);
        int2 e2 = __ldcs(&ep[e + 2]), e3 = __ldcs(&ep[e + 3]);
        float n0 = __int_as_float(e0.y), n1 = __int_as_float(e1.y);
        float n2 = __int_as_float(e2.y), n3 = __int_as_float(e3.y);
        uint4 r0 = __ldcg(&Hv[(size_t)e0.x * 16 + li]);
        uint4 r1v = __ldcg(&Hv[(size_t)e1.x * 16 + li]);
        uint4 r2 = __ldcg(&Hv[(size_t)e2.x * 16 + li]);
        uint4 r3 = __ldcg(&Hv[(size_t)e3.x * 16 + li]);
        float2 p0 = __half22float2(*(__half2*)&r0.x), p1 = __half22float2(*(__half2*)&r0.y);
        float2 p2 = __half22float2(*(__half2*)&r0.z), p3 = __half22float2(*(__half2*)&r0.w);
        float2 q0 = __half22float2(*(__half2*)&r1v.x), q1 = __half22float2(*(__half2*)&r1v.y);
        float2 q2 = __half22float2(*(__half2*)&r1v.z), q3 = __half22float2(*(__half2*)&r1v.w);
        float2 s0 = __half22float2(*(__half2*)&r2.x), s1 = __half22float2(*(__half2*)&r2.y);
        float2 s2 = __half22float2(*(__half2*)&r2.z), s3 = __half22float2(*(__half2*)&r2.w);
        float2 t0 = __half22float2(*(__half2*)&r3.x), t1 = __half22float2(*(__half2*)&r3.y);
        float2 t2 = __half22float2(*(__half2*)&r3.z), t3 = __half22float2(*(__half2*)&r3.w);
        a0 += p0.x * n0 + q0.x * n1 + s0.x * n2 + t0.x * n3;
        a1 += p0.y * n0 + q0.y * n1 + s0.y * n2 + t0.y * n3;
        a2 += p1.x * n0 + q1.x * n1 + s1.x * n2 + t1.x * n3;
        a3 += p1.y * n0 + q1.y * n1 + s1.y * n2 + t1.y * n3;
        a4 += p2.x * n0 + q2.x * n1 + s2.x * n2 + t2.x * n3;
        a5 += p2.y * n0 + q2.y * n1 + s2.y * n2 + t2.y * n3;
        a6 += p3.x * n0 + q3.x * n1 + s3.x * n2 + t3.x * n3;
        a7 += p3.y * n0 + q3.y * n1 + s3.y * n2 + t3.y * n3;
    }
    for (; e < r1; e++) {
        int2 e0 = __ldcs(&ep[e]);
        float n0 = __int_as_float(e0.y);
        uint4 r0 = __ldcg(&Hv[(size_t)e0.x * 16 + li]);
        float2 p0 = __half22float2(*(__half2*)&r0.x), p1 = __half22float2(*(__half2*)&r0.y);
        float2 p2 = __half22float2(*(__half2*)&r0.z), p3 = __half22float2(*(__half2*)&r0.w);
        a0 += p0.x * n0; a1 += p0.y * n0; a2 += p1.x * n0; a3 += p1.y * n0;
        a4 += p2.x * n0; a5 += p2.y * n0; a6 += p3.x * n0; a7 += p3.y * n0;
    }
    uint4 o;
    *(__half2*)&o.x = __floats2half2_rn(a0, a1);
    *(__half2*)&o.y = __floats2half2_rn(a2, a3);
    *(__half2*)&o.z = __floats2half2_rn(a4, a5);
    *(__half2*)&o.w = __floats2half2_rn(a6, a7);
    ((uint4*)out)[(size_t)hw * 16 + li] = o;
}

// ---------------- MLP head + log_softmax ----------------
__global__ void k_head(const float* __restrict__ gmax,
                       const float* __restrict__ Wl1, const float* __restrict__ bl1,
                       const float* __restrict__ Wl2, const float* __restrict__ bl2,
                       float* __restrict__ out) {
    __shared__ float g[256];
    __shared__ float h1[128];
    __shared__ float logits[10];
    int t = threadIdx.x;
    g[t] = gmax[t];
    __syncthreads();
    if (t < 128) {
        float s = bl1[t];
        for (int k = 0; k < 256; k++) s += g[k] * Wl1[k * 128 + t];
        h1[t] = fmaxf(s, 0.0f);
    }
    __syncthreads();
    if (t < 10) {
        float s = bl2[t];
        for (int k = 0; k < 128; k++) s += h1[k] * Wl2[k * 10 + t];
        logits[t] = s;
    }
    __syncthreads();
    if (t == 0) {
        float m = -1e30f;
        for (int c = 0; c < 10; c++) m = fmaxf(m, logits[c]);
        float se = 0.0f;
        for (int c = 0; c < 10; c++) se += expf(logits[c] - m);
        float lse = logf(se);
        for (int c = 0; c < 10; c++) out[c] = logits[c] - m - lse;
    }
}

// ---------------- launch ----------------
extern "C" void kernel_launch(void* const* d_in, const int* in_sizes, int n_in,
                              void* d_out, int out_size) {
    const float* x   = (const float*)d_in[0];
    const void*  ei  = d_in[1];
    const float* ew  = (const float*)d_in[2];
    const float* W1  = (const float*)d_in[3];
    const float* b1  = (const float*)d_in[4];
    const float* W2  = (const float*)d_in[5];
    const float* b2  = (const float*)d_in[6];
    const float* W3  = (const float*)d_in[7];
    const float* b3  = (const float*)d_in[8];
    const float* Wl1 = (const float*)d_in[9];
    const float* bl1 = (const float*)d_in[10];
    const float* Wl2 = (const float*)d_in[11];
    const float* bl2 = (const float*)d_in[12];
    float* out = (float*)d_out;

    int E = in_sizes[2];
    int N = in_sizes[0] / F0;

    unsigned long long* pk;
    float *dinv, *dinv2, *gmax;
    int *part, *bsum, *rowptr, *cursor, *flag;
    int2* epack;
    __half *hh, *xh;
    cudaGetSymbolAddress((void**)&pk,     g_pk);
    cudaGetSymbolAddress((void**)&dinv,   g_dinv);
    cudaGetSymbolAddress((void**)&dinv2,  g_dinv2);
    cudaGetSymbolAddress((void**)&part,   g_part);
    cudaGetSymbolAddress((void**)&bsum,   g_bsum);
    cudaGetSymbolAddress((void**)&rowptr, g_rowptr);
    cudaGetSymbolAddress((void**)&cursor, g_cursor);
    cudaGetSymbolAddress((void**)&epack,  g_epack);
    cudaGetSymbolAddress((void**)&flag,   g_is32);
    cudaGetSymbolAddress((void**)&hh,     g_hh);
    cudaGetSymbolAddress((void**)&xh,     g_xh);
    cudaGetSymbolAddress((void**)&gmax,   g_gmax);

    int agg64Grid = (N + 31) / 32;
    int agg128Grid = (N + 15) / 16;
    int gy = (N + 127) / 128;
    int nb = (N + SCAN_BLK - 1) / SCAN_BLK;
    int det = E < 65536 ? E : 65536;

    cudaEvent_t evFork, evJoin;
    cudaEventCreateWithFlags(&evFork, cudaEventDisableTiming);
    cudaEventCreateWithFlags(&evJoin, cudaEventDisableTiming);

    // ---- fork: layer-1 GEMM (x W1) has no preprocessing dependencies ----
    cudaEventRecord(evFork, 0);
    cudaStreamWaitEvent(cudaStreamPerThread, evFork, 0);
    k_tfgemm<0, float><<<dim3(F1 / 64, gy), 256, 0, cudaStreamPerThread>>>(
        x, W1, nullptr, hh, nullptr, N, F0, F1);
    cudaEventRecord(evJoin, cudaStreamPerThread);

    // ---- preprocessing chain (default stream, concurrent with GEMM1) ----
    k_init_detect<<<(N + 255) / 256, 256>>>(pk, N, flag, gmax,
                                            (const long long*)ei, det);
    k_hist<<<(E + 255) / 256, 256>>>(ei, E, flag, ew, pk);
    k_scan1<<<nb, 256>>>(pk, part, bsum, N);
    k_scan3f<<<(N + 255) / 256, 256>>>(rowptr, cursor, part, bsum, nb,
                                       pk, dinv, dinv2, N, E);
    k_sort<<<(E + 255) / 256, 256>>>(ei, E, flag, ew, dinv, cursor, epack);

    // ---- join ----
    cudaStreamWaitEvent(0, evJoin, 0);

    // ---- layer 1 agg: xh = relu(A_hat hh + b1) ----
    k_agg64<true><<<agg64Grid, 256>>>(rowptr, epack, hh, dinv2, b1, xh, N);

    // ---- layer 2 ----
    k_agg64<false><<<agg64Grid, 256>>>(rowptr, epack, xh, dinv2, nullptr, hh, N);
    k_tfgemm<1, __half><<<dim3(F2 / 64, gy), 256>>>(hh, W2, b2, xh, nullptr, N, F1, F2);

    // ---- layer 3 ----
    k_agg128<<<agg128Grid, 256>>>(rowptr, epack, xh, dinv2, hh, N);
    k_tfgemm<2, __half><<<dim3(F3 / 64, gy), 256>>>(hh, W3, b3, nullptr, gmax, N, F2, F3);

    k_head<<<1, 256>>>(gmax, Wl1, bl1, Wl2, bl2, out);

    cudaEventDestroy(evFork);
    cudaEventDestroy(evJoin);
}